// round 1
// baseline (speedup 1.0000x reference)
#include <cuda_runtime.h>
#include <math.h>

#define NDA 100000
#define NQ  20000
#define EDA 1000000
#define EQ  200000
#define BB  64
#define HH  8
#define HD  128
#define HD2 256
#define NEG_SLOPE 2.0f

// ---------------- scratch (device globals; no allocations allowed) ----------------
__device__ float g_feat[(size_t)NDA * HD];
__device__ float g_ft[(size_t)NDA * HD];
__device__ float g_agg[(size_t)NDA * HD];
__device__ float g_y1[(size_t)NDA * HD2];
__device__ float g_y2[(size_t)NDA * HD];
__device__ float g_el[NDA * HH];
__device__ float g_er[NDA * HH];
__device__ float g_m[NDA * HH];
__device__ float g_s[NDA * HH];
__device__ float g_gb[NDA];
__device__ float g_qb[NDA];
__device__ float g_glq[BB * HD];
__device__ float g_t1[BB * HD2];
__device__ float g_t2[BB * HD2];
__device__ float g_Q[BB * HD2];
__device__ float g_gmax[BB];
__device__ float g_gsum[BB];
__device__ float g_gt[BB];
__device__ float g_dot1[BB];
__device__ float g_dot2[BB];
__device__ float g_aab[BB * 2];
__device__ double g_dsum[HD2];
__device__ double g_dsq[HD2];
__device__ float g_mu[HD2];
__device__ float g_rstd[HD2];
__device__ float g_pe[HH];
__device__ float g_de[HH];

// ---------------- device helpers ----------------
__device__ __forceinline__ float eluf(float x) { return x > 0.f ? x : expm1f(x); }

__device__ __forceinline__ void atomicMaxF(float* a, float v) {
    if (v >= 0.f) atomicMax((int*)a, __float_as_int(v));
    else          atomicMin((unsigned int*)a, __float_as_uint(v));
}

// ---------------- fills ----------------
__global__ void k_fillf(float* p, float v, long long n) {
    long long i = (long long)blockIdx.x * blockDim.x + threadIdx.x;
    if (i < n) p[i] = v;
}
__global__ void k_filld(double* p, int n) {
    int i = blockIdx.x * blockDim.x + threadIdx.x;
    if (i < n) p[i] = 0.0;
}

// ---------------- _gap kernels ----------------
// pass A: per-node gate dot (warp per node), atomicMax per group. Optionally Q_comb dot.
__global__ void k_gap_a(const float* __restrict__ M, const float* __restrict__ gw,
                        const float* __restrict__ gb, const float* __restrict__ qc,
                        const int* __restrict__ gid, float* g, float* q, float* gmax,
                        int n, int withq) {
    int w = (blockIdx.x * blockDim.x + threadIdx.x) >> 5;
    int lane = threadIdx.x & 31;
    if (w >= n) return;
    const float* row = M + (long long)w * HD;
    float sg = 0.f, sq = 0.f;
#pragma unroll
    for (int j = lane; j < HD; j += 32) {
        float v = row[j];
        sg = fmaf(v, gw[j], sg);
        if (withq) sq = fmaf(v, qc[j], sq);
    }
#pragma unroll
    for (int o = 16; o; o >>= 1) {
        sg += __shfl_down_sync(0xffffffffu, sg, o);
        sq += __shfl_down_sync(0xffffffffu, sq, o);
    }
    if (lane == 0) {
        sg += gb[0];
        g[w] = sg;
        if (withq) q[w] = sq;
        atomicMaxF(&gmax[gid[w]], sg);
    }
}

// pass B: e = exp(g - max); accumulate group sum (and e * qdot). g overwritten with e.
__global__ void k_gap_b(const int* __restrict__ gid, float* g, const float* __restrict__ q,
                        const float* __restrict__ gmax, float* gsum, float* gt, int n, int withq) {
    int i = blockIdx.x * blockDim.x + threadIdx.x;
    if (i >= n) return;
    int b = gid[i];
    float e = expf(g[i] - gmax[b]);
    g[i] = e;
    atomicAdd(&gsum[b], e);
    if (withq) atomicAdd(&gt[b], e * q[i]);
}

// pass C (gateq only): pooled = sum_i w_i * M_i  (warp per node)
__global__ void k_gap_pool(const float* __restrict__ M, const int* __restrict__ gid,
                           const float* __restrict__ e, const float* __restrict__ gsum,
                           float* pool, int n) {
    int w = (blockIdx.x * blockDim.x + threadIdx.x) >> 5;
    int lane = threadIdx.x & 31;
    if (w >= n) return;
    int b = gid[w];
    float wt = e[w] / gsum[b];
    const float* row = M + (long long)w * HD;
#pragma unroll
    for (int j = lane; j < HD; j += 32) atomicAdd(&pool[b * HD + j], wt * row[j]);
}

__global__ void k_dotfin(const float* gt, const float* gsum, float* dot) {
    int b = threadIdx.x;
    if (b < BB) dot[b] = gsum[b] > 0.f ? gt[b] / gsum[b] : 0.f;
}

__global__ void k_comb(const float* d1, const float* d2, float* a) {
    int b = threadIdx.x;
    if (b < BB) {
        float x1 = d1[b], x2 = d2[b];
        float mm = fmaxf(x1, x2);
        float e1 = expf(x1 - mm), e2 = expf(x2 - mm);
        float ss = e1 + e2;
        a[2 * b] = e1 / ss;
        a[2 * b + 1] = e2 / ss;
    }
}

// ---------------- tiled SGEMM: C[n x NC] = f(A)[n x K] @ W[K x NC] + bias ----------------
// AMODE 0: A = A1
// AMODE 1: A = a0[gid]*A1 + a1[gid]*A2
// AMODE 2: A = elu((A1 - mu[k]) * rstd[k])
template <int AMODE>
__global__ void __launch_bounds__(256) k_gemm(
    const float* __restrict__ A1, const float* __restrict__ A2,
    const float* __restrict__ acoef, const int* __restrict__ gid,
    const float* __restrict__ W, const float* __restrict__ bias,
    const float* __restrict__ mu, const float* __restrict__ rstd,
    float* __restrict__ C, int n, int K, int NC) {
    __shared__ float As[8][128];
    __shared__ float Ws[8][128];
    const int tid = threadIdx.x;
    const int tx = tid & 15, ty = tid >> 4;
    const int rowBase = blockIdx.y * 128;
    const int colBase = blockIdx.x * 128;
    const int lm = tid >> 1;
    const int lk = (tid & 1) * 4;
    const int wk = tid >> 5;
    const int wc = (tid & 31) * 4;
    const int row = rowBase + lm;

    float c0 = 0.f, c1 = 0.f;
    if (AMODE == 1) {
        if (row < n) {
            int gg = gid[row];
            c0 = acoef[2 * gg];
            c1 = acoef[2 * gg + 1];
        }
    }

    float acc[8][8];
#pragma unroll
    for (int i = 0; i < 8; i++)
#pragma unroll
        for (int j = 0; j < 8; j++) acc[i][j] = 0.f;

    for (int k0 = 0; k0 < K; k0 += 8) {
        float4 av = make_float4(0.f, 0.f, 0.f, 0.f);
        if (row < n) {
            av = *(const float4*)(A1 + (long long)row * K + k0 + lk);
            if (AMODE == 1) {
                float4 bv = *(const float4*)(A2 + (long long)row * K + k0 + lk);
                av.x = c0 * av.x + c1 * bv.x;
                av.y = c0 * av.y + c1 * bv.y;
                av.z = c0 * av.z + c1 * bv.z;
                av.w = c0 * av.w + c1 * bv.w;
            } else if (AMODE == 2) {
                int kk = k0 + lk;
                av.x = eluf((av.x - mu[kk + 0]) * rstd[kk + 0]);
                av.y = eluf((av.y - mu[kk + 1]) * rstd[kk + 1]);
                av.z = eluf((av.z - mu[kk + 2]) * rstd[kk + 2]);
                av.w = eluf((av.w - mu[kk + 3]) * rstd[kk + 3]);
            }
        }
        As[lk + 0][lm] = av.x;
        As[lk + 1][lm] = av.y;
        As[lk + 2][lm] = av.z;
        As[lk + 3][lm] = av.w;
        float4 wv = *(const float4*)(W + (long long)(k0 + wk) * NC + colBase + wc);
        Ws[wk][wc + 0] = wv.x;
        Ws[wk][wc + 1] = wv.y;
        Ws[wk][wc + 2] = wv.z;
        Ws[wk][wc + 3] = wv.w;
        __syncthreads();
#pragma unroll
        for (int k = 0; k < 8; k++) {
            float ra[8], rb[8];
#pragma unroll
            for (int i = 0; i < 8; i++) ra[i] = As[k][ty * 8 + i];
#pragma unroll
            for (int j = 0; j < 8; j++) rb[j] = Ws[k][tx * 8 + j];
#pragma unroll
            for (int i = 0; i < 8; i++)
#pragma unroll
                for (int j = 0; j < 8; j++) acc[i][j] = fmaf(ra[i], rb[j], acc[i][j]);
        }
        __syncthreads();
    }
#pragma unroll
    for (int i = 0; i < 8; i++) {
        int r = rowBase + ty * 8 + i;
        if (r < n) {
#pragma unroll
            for (int j = 0; j < 8; j++) {
                int c = colBase + tx * 8 + j;
                C[(long long)r * NC + c] = acc[i][j] + bias[c];
            }
        }
    }
}

// ---------------- el / er per (node, head) ----------------
__global__ void k_eler(const float* __restrict__ feat, const float* __restrict__ Q,
                       const int* __restrict__ gid, float* el, float* er, int n) {
    int idx = blockIdx.x * blockDim.x + threadIdx.x;
    if (idx >= n * HH) return;
    int i = idx >> 3, h = idx & 7;
    const float* f = feat + (long long)i * HD + h * 16;
    const float* q = Q + (long long)gid[i] * HD2 + h * 32;
    float sl = 0.f, sr = 0.f;
#pragma unroll
    for (int c = 0; c < 16; c++) {
        float fv = f[c];
        sl = fmaf(fv, q[c], sl);
        sr = fmaf(fv, q[16 + c], sr);
    }
    el[idx] = sl;
    er[idx] = sr;
}

// ---------------- edge softmax passes ----------------
__global__ void k_edge_max(const int* __restrict__ src, const int* __restrict__ dst,
                           const float* __restrict__ el, const float* __restrict__ er,
                           float* m, int E) {
    int e = blockIdx.x * blockDim.x + threadIdx.x;
    if (e >= E) return;
    int se = src[e] * HH, de = dst[e] * HH;
#pragma unroll
    for (int h = 0; h < HH; h++) {
        float v = el[se + h] + er[de + h];
        v = v > 0.f ? v : NEG_SLOPE * v;
        atomicMaxF(&m[de + h], v);
    }
}

__global__ void k_edge_sum(const int* __restrict__ src, const int* __restrict__ dst,
                           const float* __restrict__ el, const float* __restrict__ er,
                           const float* __restrict__ m, float* s, int E) {
    int e = blockIdx.x * blockDim.x + threadIdx.x;
    if (e >= E) return;
    int se = src[e] * HH, de = dst[e] * HH;
#pragma unroll
    for (int h = 0; h < HH; h++) {
        float v = el[se + h] + er[de + h];
        v = v > 0.f ? v : NEG_SLOPE * v;
        atomicAdd(&s[de + h], expf(v - m[de + h]));
    }
}

// warp per edge: agg[dst] += w_h * ft[src]  (float4 lanes; h = lane/4)
__global__ void k_edge_agg(const int* __restrict__ src, const int* __restrict__ dst,
                           const float* __restrict__ el, const float* __restrict__ er,
                           const float* __restrict__ m, const float* __restrict__ s,
                           const float* __restrict__ ft, float* agg, int E) {
    int gw = (blockIdx.x * blockDim.x + threadIdx.x) >> 5;
    int lane = threadIdx.x & 31;
    if (gw >= E) return;
    int se = src[gw], de = dst[gw];
    int h = lane >> 2;
    float v = el[se * HH + h] + er[de * HH + h];
    v = v > 0.f ? v : NEG_SLOPE * v;
    float w = expf(v - m[de * HH + h]) / s[de * HH + h];
    float4 fv = *(const float4*)(ft + (long long)se * HD + lane * 4);
    float* ap = agg + (long long)de * HD + lane * 4;
    atomicAdd(ap + 0, w * fv.x);
    atomicAdd(ap + 1, w * fv.y);
    atomicAdd(ap + 2, w * fv.z);
    atomicAdd(ap + 3, w * fv.w);
}

// ---------------- batchnorm column stats ----------------
__global__ void k_bnred(const float* __restrict__ Y, int n, int C, double* sum, double* sq) {
    int c = threadIdx.x;  // blockDim.x == C
    double s = 0.0, s2 = 0.0;
    for (int r = blockIdx.x; r < n; r += gridDim.x) {
        float v = Y[(long long)r * C + c];
        s += v;
        s2 += (double)v * v;
    }
    atomicAdd(&sum[c], s);
    atomicAdd(&sq[c], s2);
}
__global__ void k_bnfin(const double* sum, const double* sq, int n, float* mu, float* rstd) {
    int c = threadIdx.x;
    double m = sum[c] / n;
    double v = sq[c] / n - m * m;
    if (v < 0.0) v = 0.0;
    mu[c] = (float)m;
    rstd[c] = (float)(1.0 / sqrt(v + 1e-5));
}

__global__ void k_bnelu(const float* __restrict__ Y, const float* __restrict__ mu,
                        const float* __restrict__ rstd, float* out, long long total, int C) {
    long long i = (long long)blockIdx.x * blockDim.x + threadIdx.x;
    if (i < total) {
        int c = (int)(i % C);
        out[i] = eluf((Y[i] - mu[c]) * rstd[c]);
    }
}

__global__ void k_final(const float* __restrict__ hlast, const float* __restrict__ Y,
                        const float* __restrict__ mu, const float* __restrict__ rstd,
                        float* out, long long total) {
    long long i = (long long)blockIdx.x * blockDim.x + threadIdx.x;
    if (i < total) {
        int c = (int)(i & (HD - 1));
        float v = eluf((Y[i] - mu[c]) * rstd[c]);
        out[i] = hlast[i] + v;
    }
}

// ---------------- PE/DE sampled attention sums + loss ----------------
__global__ void k_pesum(const int* __restrict__ ids, int nids, const int* __restrict__ src,
                        const int* __restrict__ dst, const float* __restrict__ el,
                        const float* __restrict__ er, const float* __restrict__ m,
                        const float* __restrict__ s, float* out8) {
    float acc[HH];
#pragma unroll
    for (int h = 0; h < HH; h++) acc[h] = 0.f;
    for (int i = blockIdx.x * blockDim.x + threadIdx.x; i < nids; i += gridDim.x * blockDim.x) {
        int e = ids[i];
        int se = src[e] * HH, de = dst[e] * HH;
#pragma unroll
        for (int h = 0; h < HH; h++) {
            float v = el[se + h] + er[de + h];
            v = v > 0.f ? v : NEG_SLOPE * v;
            acc[h] += expf(v - m[de + h]) / s[de + h];
        }
    }
#pragma unroll
    for (int h = 0; h < HH; h++) {
#pragma unroll
        for (int o = 16; o; o >>= 1) acc[h] += __shfl_down_sync(0xffffffffu, acc[h], o);
    }
    if ((threadIdx.x & 31) == 0) {
#pragma unroll
        for (int h = 0; h < HH; h++) atomicAdd(&out8[h], acc[h]);
    }
}

__global__ void k_loss(const float* pe, const float* de, const int* lenp, float* out) {
    float sum = 0.f;
#pragma unroll
    for (int h = 0; h < HH; h++) sum += pe[h] - de[h];
    out[0] = -sum / (8.0f * (float)lenp[0]);
}

// ---------------- host side ----------------
static inline int cdiv(long long a, long long b) { return (int)((a + b - 1) / b); }
static inline void fillf(float* p, float v, long long n) { k_fillf<<<cdiv(n, 256), 256>>>(p, v, n); }

struct Scratch {
    float *feat, *ft, *agg, *y1, *y2, *el, *er, *mm, *ss, *gbuf, *qbuf;
    float *glq, *t1, *t2, *Qb, *gmax, *gsum, *gt, *dot1, *dot2, *aab, *mu, *rstd, *pe, *de;
    double *dsum, *dsq;
};

static void run_branch(int n, int E, const float* h_last, const float* h0,
                       const int* src, const int* dst, const int* gid,
                       const float* W_L, const float* b_L,
                       const float* gate1_W, const float* gate1_b,
                       const float* gate2_W, const float* gate2_b,
                       const float* Q_comb,
                       const float* end_W1, const float* end_b1,
                       const float* end_W2, const float* end_b2,
                       float* out_branch, const Scratch& S) {
    dim3 g128(1, cdiv(n, 128)), g256(2, cdiv(n, 128));
    // feat = h_last @ W_L + b_L
    k_gemm<0><<<g128, 256>>>(h_last, nullptr, nullptr, nullptr, W_L, b_L, nullptr, nullptr,
                             S.feat, n, 128, 128);
    // gate1 on h0 (with Q_comb dot)
    fillf(S.gmax, -INFINITY, BB);
    fillf(S.gsum, 0.f, BB);
    fillf(S.gt, 0.f, BB);
    k_gap_a<<<cdiv((long long)n * 32, 256), 256>>>(h0, gate1_W, gate1_b, Q_comb, gid, S.gbuf,
                                                   S.qbuf, S.gmax, n, 1);
    k_gap_b<<<cdiv(n, 256), 256>>>(gid, S.gbuf, S.qbuf, S.gmax, S.gsum, S.gt, n, 1);
    k_dotfin<<<1, BB>>>(S.gt, S.gsum, S.dot1);
    // gate2 on h_last (M2 == h_last in both branches)
    fillf(S.gmax, -INFINITY, BB);
    fillf(S.gsum, 0.f, BB);
    fillf(S.gt, 0.f, BB);
    k_gap_a<<<cdiv((long long)n * 32, 256), 256>>>(h_last, gate2_W, gate2_b, Q_comb, gid, S.gbuf,
                                                   S.qbuf, S.gmax, n, 1);
    k_gap_b<<<cdiv(n, 256), 256>>>(gid, S.gbuf, S.qbuf, S.gmax, S.gsum, S.gt, n, 1);
    k_dotfin<<<1, BB>>>(S.gt, S.gsum, S.dot2);
    k_comb<<<1, BB>>>(S.dot1, S.dot2, S.aab);
    // ft = (a0*h0 + a1*h_last) @ W_L + b_L
    k_gemm<1><<<g128, 256>>>(h0, h_last, S.aab, gid, W_L, b_L, nullptr, nullptr, S.ft, n, 128, 128);
    // el/er
    k_eler<<<cdiv((long long)n * HH, 256), 256>>>(S.feat, S.Qb, gid, S.el, S.er, n);
    // edge softmax + aggregation
    fillf(S.mm, -INFINITY, (long long)n * HH);
    fillf(S.ss, 0.f, (long long)n * HH);
    fillf(S.agg, 0.f, (long long)n * HD);
    k_edge_max<<<cdiv(E, 256), 256>>>(src, dst, S.el, S.er, S.mm, E);
    k_edge_sum<<<cdiv(E, 256), 256>>>(src, dst, S.el, S.er, S.mm, S.ss, E);
    k_edge_agg<<<cdiv((long long)E * 32, 256), 256>>>(src, dst, S.el, S.er, S.mm, S.ss, S.ft,
                                                      S.agg, E);
    // end FNN: y1 = agg @ end_W1 + b1 ; bn ; y2 = elu(bn(y1)) @ end_W2 + b2 ; bn ; out = h_last + elu(bn(y2))
    k_gemm<0><<<g256, 256>>>(S.agg, nullptr, nullptr, nullptr, end_W1, end_b1, nullptr, nullptr,
                             S.y1, n, 128, 256);
    k_filld<<<1, 256>>>(S.dsum, 256);
    k_filld<<<1, 256>>>(S.dsq, 256);
    k_bnred<<<512, 256>>>(S.y1, n, 256, S.dsum, S.dsq);
    k_bnfin<<<1, 256>>>(S.dsum, S.dsq, n, S.mu, S.rstd);
    k_gemm<2><<<g128, 256>>>(S.y1, nullptr, nullptr, nullptr, end_W2, end_b2, S.mu, S.rstd, S.y2,
                             n, 256, 128);
    k_filld<<<1, 128>>>(S.dsum, 128);
    k_filld<<<1, 128>>>(S.dsq, 128);
    k_bnred<<<512, 128>>>(S.y2, n, 128, S.dsum, S.dsq);
    k_bnfin<<<1, 128>>>(S.dsum, S.dsq, n, S.mu, S.rstd);
    k_final<<<cdiv((long long)n * HD, 256), 256>>>(h_last, S.y2, S.mu, S.rstd, out_branch,
                                                   (long long)n * HD);
}

extern "C" void kernel_launch(void* const* d_in, const int* in_sizes, int n_in,
                              void* d_out, int out_size) {
    const float* h_da_last = (const float*)d_in[0];
    const float* h_q_last  = (const float*)d_in[1];
    const float* h_da_0    = (const float*)d_in[2];
    const float* h_q_0     = (const float*)d_in[3];
    const float* W_L       = (const float*)d_in[4];
    const float* b_L       = (const float*)d_in[5];
    const float* gateq_W   = (const float*)d_in[6];
    const float* gateq_b   = (const float*)d_in[7];
    const float* gate1_W   = (const float*)d_in[8];
    const float* gate1_b   = (const float*)d_in[9];
    const float* gate2_W   = (const float*)d_in[10];
    const float* gate2_b   = (const float*)d_in[11];
    const float* Q_comb    = (const float*)d_in[12];
    const float* Qf_W1     = (const float*)d_in[13];
    const float* Qf_b1     = (const float*)d_in[14];
    const float* Qf_W2     = (const float*)d_in[15];
    const float* Qf_b2     = (const float*)d_in[16];
    const float* end_W1    = (const float*)d_in[17];
    const float* end_b1    = (const float*)d_in[18];
    const float* end_W2    = (const float*)d_in[19];
    const float* end_b2    = (const float*)d_in[20];
    const int* src_da = (const int*)d_in[21];
    const int* dst_da = (const int*)d_in[22];
    const int* src_q  = (const int*)d_in[23];
    const int* dst_q  = (const int*)d_in[24];
    const int* gid_da = (const int*)d_in[25];
    const int* gid_q  = (const int*)d_in[26];
    const int* PEid   = (const int*)d_in[27];
    const int* DEid   = (const int*)d_in[28];
    const int* lenp   = (const int*)d_in[29];
    int nPE = in_sizes[27], nDE = in_sizes[28];

    float* out = (float*)d_out;
    float* out_da = out;
    float* out_q = out + (long long)NDA * HD;
    float* out_loss = out + (long long)NDA * HD + (long long)NQ * HD;

    Scratch S;
    cudaGetSymbolAddress((void**)&S.feat, g_feat);
    cudaGetSymbolAddress((void**)&S.ft, g_ft);
    cudaGetSymbolAddress((void**)&S.agg, g_agg);
    cudaGetSymbolAddress((void**)&S.y1, g_y1);
    cudaGetSymbolAddress((void**)&S.y2, g_y2);
    cudaGetSymbolAddress((void**)&S.el, g_el);
    cudaGetSymbolAddress((void**)&S.er, g_er);
    cudaGetSymbolAddress((void**)&S.mm, g_m);
    cudaGetSymbolAddress((void**)&S.ss, g_s);
    cudaGetSymbolAddress((void**)&S.gbuf, g_gb);
    cudaGetSymbolAddress((void**)&S.qbuf, g_qb);
    cudaGetSymbolAddress((void**)&S.glq, g_glq);
    cudaGetSymbolAddress((void**)&S.t1, g_t1);
    cudaGetSymbolAddress((void**)&S.t2, g_t2);
    cudaGetSymbolAddress((void**)&S.Qb, g_Q);
    cudaGetSymbolAddress((void**)&S.gmax, g_gmax);
    cudaGetSymbolAddress((void**)&S.gsum, g_gsum);
    cudaGetSymbolAddress((void**)&S.gt, g_gt);
    cudaGetSymbolAddress((void**)&S.dot1, g_dot1);
    cudaGetSymbolAddress((void**)&S.dot2, g_dot2);
    cudaGetSymbolAddress((void**)&S.aab, g_aab);
    cudaGetSymbolAddress((void**)&S.mu, g_mu);
    cudaGetSymbolAddress((void**)&S.rstd, g_rstd);
    cudaGetSymbolAddress((void**)&S.pe, g_pe);
    cudaGetSymbolAddress((void**)&S.de, g_de);
    cudaGetSymbolAddress((void**)&S.dsum, g_dsum);
    cudaGetSymbolAddress((void**)&S.dsq, g_dsq);

    // ---- Phase 0: glq = _gap(gateq, h_q_last, gid_q); Q = fnn(glq) ----
    fillf(S.gmax, -INFINITY, BB);
    fillf(S.gsum, 0.f, BB);
    k_gap_a<<<cdiv((long long)NQ * 32, 256), 256>>>(h_q_last, gateq_W, gateq_b, nullptr, gid_q,
                                                    S.gbuf, S.qbuf, S.gmax, NQ, 0);
    k_gap_b<<<cdiv(NQ, 256), 256>>>(gid_q, S.gbuf, S.qbuf, S.gmax, S.gsum, S.gt, NQ, 0);
    fillf(S.glq, 0.f, (long long)BB * HD);
    k_gap_pool<<<cdiv((long long)NQ * 32, 256), 256>>>(h_q_last, gid_q, S.gbuf, S.gsum, S.glq, NQ);

    k_gemm<0><<<dim3(2, 1), 256>>>(S.glq, nullptr, nullptr, nullptr, Qf_W1, Qf_b1, nullptr,
                                   nullptr, S.t1, BB, 128, 256);
    k_filld<<<1, 256>>>(S.dsum, 256);
    k_filld<<<1, 256>>>(S.dsq, 256);
    k_bnred<<<8, 256>>>(S.t1, BB, 256, S.dsum, S.dsq);
    k_bnfin<<<1, 256>>>(S.dsum, S.dsq, BB, S.mu, S.rstd);
    k_gemm<2><<<dim3(2, 1), 256>>>(S.t1, nullptr, nullptr, nullptr, Qf_W2, Qf_b2, S.mu, S.rstd,
                                   S.t2, BB, 256, 256);
    k_filld<<<1, 256>>>(S.dsum, 256);
    k_filld<<<1, 256>>>(S.dsq, 256);
    k_bnred<<<8, 256>>>(S.t2, BB, 256, S.dsum, S.dsq);
    k_bnfin<<<1, 256>>>(S.dsum, S.dsq, BB, S.mu, S.rstd);
    k_bnelu<<<cdiv((long long)BB * 256, 256), 256>>>(S.t2, S.mu, S.rstd, S.Qb,
                                                     (long long)BB * 256, 256);

    // ---- q branch first (scratch reused), then da branch (its edge stats feed the loss) ----
    run_branch(NQ, EQ, h_q_last, h_q_0, src_q, dst_q, gid_q, W_L, b_L, gate1_W, gate1_b, gate2_W,
               gate2_b, Q_comb, end_W1, end_b1, end_W2, end_b2, out_q, S);
    run_branch(NDA, EDA, h_da_last, h_da_0, src_da, dst_da, gid_da, W_L, b_L, gate1_W, gate1_b,
               gate2_W, gate2_b, Q_comb, end_W1, end_b1, end_W2, end_b2, out_da, S);

    // ---- loss from da edge-attention at sampled edge ids ----
    fillf(S.pe, 0.f, HH);
    fillf(S.de, 0.f, HH);
    k_pesum<<<256, 256>>>(PEid, nPE, src_da, dst_da, S.el, S.er, S.mm, S.ss, S.pe);
    k_pesum<<<256, 256>>>(DEid, nDE, src_da, dst_da, S.el, S.er, S.mm, S.ss, S.de);
    k_loss<<<1, 1>>>(S.pe, S.de, lenp, out_loss);
}

// round 2
// speedup vs baseline: 1.5699x; 1.5699x over previous
#include <cuda_runtime.h>
#include <math.h>
#include <stdint.h>

#define NDA 100000
#define NQ  20000
#define EDA 1000000
#define EQ  200000
#define BB  64
#define HH  8
#define HD  128
#define HD2 256
#define NEG_SLOPE 2.0f

// ---------------- scratch (device globals; no allocations allowed) ----------------
__device__ float g_feat[(size_t)NDA * HD];
__device__ float g_ft[(size_t)NDA * HD];
__device__ float g_agg[(size_t)NDA * HD];
__device__ float g_y1[(size_t)NDA * HD2];
__device__ float g_y2[(size_t)NDA * HD];
__device__ float g_el[NDA * HH];
__device__ float g_er[NDA * HH];
__device__ float g_m[NDA * HH];
__device__ float g_s[NDA * HH];
__device__ float g_gb[NDA];
__device__ float g_qb[NDA];
__device__ int   g_deg[NDA];
__device__ int   g_coff[NDA];
__device__ int   g_cursor[NDA];
__device__ int   g_eid[EDA];
__device__ int   g_bsum[256];
__device__ float g_glq[BB * HD];
__device__ float g_t1[BB * HD2];
__device__ float g_t2[BB * HD2];
__device__ float g_Q[BB * HD2];
__device__ float g_gmax[BB];
__device__ float g_gsum[BB];
__device__ float g_gt[BB];
__device__ float g_dot1[BB];
__device__ float g_dot2[BB];
__device__ float g_aab[BB * 2];
__device__ double g_dsum[HD2];
__device__ double g_dsq[HD2];
__device__ float g_mu[HD2];
__device__ float g_rstd[HD2];
__device__ float g_pe[HH];
__device__ float g_de[HH];

// ---------------- device helpers ----------------
__device__ __forceinline__ float eluf(float x) { return x > 0.f ? x : expm1f(x); }

__device__ __forceinline__ void atomicMaxF(float* a, float v) {
    if (v >= 0.f) atomicMax((int*)a, __float_as_int(v));
    else          atomicMin((unsigned int*)a, __float_as_uint(v));
}

__device__ __forceinline__ uint32_t f2tf(float x) {
    uint32_t r;
    asm("cvt.rna.tf32.f32 %0, %1;" : "=r"(r) : "f"(x));
    return r;
}

__device__ __forceinline__ void mma8(float* d, const uint32_t* a, const uint32_t* b) {
    asm volatile(
        "mma.sync.aligned.m16n8k8.row.col.f32.tf32.tf32.f32 "
        "{%0,%1,%2,%3}, {%4,%5,%6,%7}, {%8,%9}, {%0,%1,%2,%3};\n"
        : "+f"(d[0]), "+f"(d[1]), "+f"(d[2]), "+f"(d[3])
        : "r"(a[0]), "r"(a[1]), "r"(a[2]), "r"(a[3]), "r"(b[0]), "r"(b[1]));
}

// ---------------- fills ----------------
__global__ void k_fillf(float* p, float v, long long n) {
    long long i = (long long)blockIdx.x * blockDim.x + threadIdx.x;
    if (i < n) p[i] = v;
}
__global__ void k_filli(int* p, int v, int n) {
    int i = blockIdx.x * blockDim.x + threadIdx.x;
    if (i < n) p[i] = v;
}
__global__ void k_filld(double* p, int n) {
    int i = blockIdx.x * blockDim.x + threadIdx.x;
    if (i < n) p[i] = 0.0;
}

// ---------------- _gap kernels ----------------
__global__ void k_gap_a(const float* __restrict__ M, const float* __restrict__ gw,
                        const float* __restrict__ gb, const float* __restrict__ qc,
                        const int* __restrict__ gid, float* g, float* q, float* gmax,
                        int n, int withq) {
    int w = (blockIdx.x * blockDim.x + threadIdx.x) >> 5;
    int lane = threadIdx.x & 31;
    if (w >= n) return;
    const float* row = M + (long long)w * HD;
    float sg = 0.f, sq = 0.f;
#pragma unroll
    for (int j = lane; j < HD; j += 32) {
        float v = row[j];
        sg = fmaf(v, gw[j], sg);
        if (withq) sq = fmaf(v, qc[j], sq);
    }
#pragma unroll
    for (int o = 16; o; o >>= 1) {
        sg += __shfl_down_sync(0xffffffffu, sg, o);
        sq += __shfl_down_sync(0xffffffffu, sq, o);
    }
    if (lane == 0) {
        sg += gb[0];
        g[w] = sg;
        if (withq) q[w] = sq;
        atomicMaxF(&gmax[gid[w]], sg);
    }
}

__global__ void k_gap_b(const int* __restrict__ gid, float* g, const float* __restrict__ q,
                        const float* __restrict__ gmax, float* gsum, float* gt, int n, int withq) {
    int i = blockIdx.x * blockDim.x + threadIdx.x;
    if (i >= n) return;
    int b = gid[i];
    float e = expf(g[i] - gmax[b]);
    g[i] = e;
    atomicAdd(&gsum[b], e);
    if (withq) atomicAdd(&gt[b], e * q[i]);
}

__global__ void k_gap_pool(const float* __restrict__ M, const int* __restrict__ gid,
                           const float* __restrict__ e, const float* __restrict__ gsum,
                           float* pool, int n) {
    int w = (blockIdx.x * blockDim.x + threadIdx.x) >> 5;
    int lane = threadIdx.x & 31;
    if (w >= n) return;
    int b = gid[w];
    float wt = e[w] / gsum[b];
    const float* row = M + (long long)w * HD;
#pragma unroll
    for (int j = lane; j < HD; j += 32) atomicAdd(&pool[b * HD + j], wt * row[j]);
}

__global__ void k_dotfin(const float* gt, const float* gsum, float* dot) {
    int b = threadIdx.x;
    if (b < BB) dot[b] = gsum[b] > 0.f ? gt[b] / gsum[b] : 0.f;
}

__global__ void k_comb(const float* d1, const float* d2, float* a) {
    int b = threadIdx.x;
    if (b < BB) {
        float x1 = d1[b], x2 = d2[b];
        float mm = fmaxf(x1, x2);
        float e1 = expf(x1 - mm), e2 = expf(x2 - mm);
        float ss = e1 + e2;
        a[2 * b] = e1 / ss;
        a[2 * b + 1] = e2 / ss;
    }
}

// ---------------- TF32 tensor-core GEMM ----------------
// C[n x NC] = f(A)[n x K] @ W[K x NC] + bias
// AMODE 0: A = A1 ; AMODE 1: A = a0[gid]*A1 + a1[gid]*A2 ; AMODE 2: A = elu(bn(A1))
// Block tile 128x128, BK=32, 8 warps (2 M x 4 N), warp tile 64x32 of m16n8k8.
template <int AMODE>
__global__ void __launch_bounds__(256) k_gemm_tf32(
    const float* __restrict__ A1, const float* __restrict__ A2,
    const float* __restrict__ acoef, const int* __restrict__ gid,
    const float* __restrict__ W, const float* __restrict__ bias,
    const float* __restrict__ mu, const float* __restrict__ rstd,
    float* __restrict__ C, int n, int K, int NC) {
    __shared__ uint32_t As[128 * 36];   // [row][k], stride 36 -> conflict-free frag loads
    __shared__ uint32_t Ws[32 * 132];   // [k][col], stride 132 -> conflict-free frag loads

    const int tid = threadIdx.x;
    const int lane = tid & 31;
    const int wid = tid >> 5;
    const int warp_m = wid >> 2;   // 0..1
    const int warp_n = wid & 3;    // 0..3
    const int rowBase = blockIdx.y * 128;
    const int colBase = blockIdx.x * 128;
    const int g4 = lane >> 2;      // 0..7
    const int t4 = lane & 3;       // 0..3

    float acc[4][4][4];
#pragma unroll
    for (int mi = 0; mi < 4; mi++)
#pragma unroll
        for (int ni = 0; ni < 4; ni++)
#pragma unroll
            for (int r = 0; r < 4; r++) acc[mi][ni][r] = 0.f;

    for (int k0 = 0; k0 < K; k0 += 32) {
        // ---- stage A tile (128 x 32) with fused transform ----
#pragma unroll
        for (int q = 0; q < 4; q++) {
            int idx = tid + q * 256;
            int r = idx >> 3, kq = idx & 7;
            int grow = rowBase + r;
            float4 av = make_float4(0.f, 0.f, 0.f, 0.f);
            if (grow < n) {
                av = *(const float4*)(A1 + (size_t)grow * K + k0 + kq * 4);
                if (AMODE == 1) {
                    int gg = gid[grow];
                    float c0 = acoef[2 * gg], c1 = acoef[2 * gg + 1];
                    float4 bv = *(const float4*)(A2 + (size_t)grow * K + k0 + kq * 4);
                    av.x = c0 * av.x + c1 * bv.x;
                    av.y = c0 * av.y + c1 * bv.y;
                    av.z = c0 * av.z + c1 * bv.z;
                    av.w = c0 * av.w + c1 * bv.w;
                } else if (AMODE == 2) {
                    int kk = k0 + kq * 4;
                    av.x = eluf((av.x - mu[kk + 0]) * rstd[kk + 0]);
                    av.y = eluf((av.y - mu[kk + 1]) * rstd[kk + 1]);
                    av.z = eluf((av.z - mu[kk + 2]) * rstd[kk + 2]);
                    av.w = eluf((av.w - mu[kk + 3]) * rstd[kk + 3]);
                }
            }
            uint32_t* dp = &As[r * 36 + kq * 4];
            dp[0] = f2tf(av.x);
            dp[1] = f2tf(av.y);
            dp[2] = f2tf(av.z);
            dp[3] = f2tf(av.w);
        }
        // ---- stage W tile (32 x 128) ----
#pragma unroll
        for (int q = 0; q < 4; q++) {
            int idx = tid + q * 256;
            int kk = idx >> 5, nq = idx & 31;
            float4 wv = *(const float4*)(W + (size_t)(k0 + kk) * NC + colBase + nq * 4);
            uint32_t* dp = &Ws[kk * 132 + nq * 4];
            dp[0] = f2tf(wv.x);
            dp[1] = f2tf(wv.y);
            dp[2] = f2tf(wv.z);
            dp[3] = f2tf(wv.w);
        }
        __syncthreads();
        // ---- compute ----
#pragma unroll
        for (int ks = 0; ks < 4; ks++) {
            int kk = ks * 8;
            uint32_t a[4][4];
#pragma unroll
            for (int mi = 0; mi < 4; mi++) {
                int r = warp_m * 64 + mi * 16 + g4;
                a[mi][0] = As[r * 36 + kk + t4];
                a[mi][1] = As[(r + 8) * 36 + kk + t4];
                a[mi][2] = As[r * 36 + kk + t4 + 4];
                a[mi][3] = As[(r + 8) * 36 + kk + t4 + 4];
            }
            uint32_t b[4][2];
#pragma unroll
            for (int ni = 0; ni < 4; ni++) {
                int c = warp_n * 32 + ni * 8 + g4;
                b[ni][0] = Ws[(kk + t4) * 132 + c];
                b[ni][1] = Ws[(kk + t4 + 4) * 132 + c];
            }
#pragma unroll
            for (int mi = 0; mi < 4; mi++)
#pragma unroll
                for (int ni = 0; ni < 4; ni++) mma8(acc[mi][ni], a[mi], b[ni]);
        }
        __syncthreads();
    }

    // ---- epilogue ----
#pragma unroll
    for (int mi = 0; mi < 4; mi++) {
        int r0 = rowBase + warp_m * 64 + mi * 16 + g4;
        int r1 = r0 + 8;
#pragma unroll
        for (int ni = 0; ni < 4; ni++) {
            int c = colBase + warp_n * 32 + ni * 8 + t4 * 2;
            float b0 = bias[c], b1 = bias[c + 1];
            if (r0 < n) {
                C[(size_t)r0 * NC + c]     = acc[mi][ni][0] + b0;
                C[(size_t)r0 * NC + c + 1] = acc[mi][ni][1] + b1;
            }
            if (r1 < n) {
                C[(size_t)r1 * NC + c]     = acc[mi][ni][2] + b0;
                C[(size_t)r1 * NC + c + 1] = acc[mi][ni][3] + b1;
            }
        }
    }
}

// ---------------- el / er per (node, head) ----------------
__global__ void k_eler(const float* __restrict__ feat, const float* __restrict__ Q,
                       const int* __restrict__ gid, float* el, float* er, int n) {
    int idx = blockIdx.x * blockDim.x + threadIdx.x;
    if (idx >= n * HH) return;
    int i = idx >> 3, h = idx & 7;
    const float* f = feat + (long long)i * HD + h * 16;
    const float* q = Q + (long long)gid[i] * HD2 + h * 32;
    float sl = 0.f, sr = 0.f;
#pragma unroll
    for (int c = 0; c < 16; c++) {
        float fv = f[c];
        sl = fmaf(fv, q[c], sl);
        sr = fmaf(fv, q[16 + c], sr);
    }
    el[idx] = sl;
    er[idx] = sr;
}

// ---------------- CSR construction ----------------
__global__ void k_hist(const int* __restrict__ dst, int* deg, int E) {
    int e = blockIdx.x * blockDim.x + threadIdx.x;
    if (e < E) atomicAdd(&deg[dst[e]], 1);
}

// per-512-block exclusive scan + block totals
__global__ void k_scan1(const int* __restrict__ deg, int* out, int* bsum, int n) {
    __shared__ int sh[512];
    int base = blockIdx.x * 512;
    int t = threadIdx.x;
    int v0 = (base + t < n) ? deg[base + t] : 0;
    int v1 = (base + 256 + t < n) ? deg[base + 256 + t] : 0;
    sh[t] = v0;
    sh[t + 256] = v1;
    __syncthreads();
    for (int off = 1; off < 512; off <<= 1) {
        int i0 = t, i1 = t + 256;
        int n0 = sh[i0] + ((i0 >= off) ? sh[i0 - off] : 0);
        int n1 = sh[i1] + ((i1 >= off) ? sh[i1 - off] : 0);
        __syncthreads();
        sh[i0] = n0;
        sh[i1] = n1;
        __syncthreads();
    }
    if (base + t < n) out[base + t] = sh[t] - v0;
    if (base + 256 + t < n) out[base + 256 + t] = sh[t + 256] - v1;
    if (t == 0) bsum[blockIdx.x] = sh[511];
}

__global__ void k_scan2(int* bsum, int nb) {
    __shared__ int sh[256];
    int t = threadIdx.x;
    int v = (t < nb) ? bsum[t] : 0;
    sh[t] = v;
    __syncthreads();
    for (int off = 1; off < 256; off <<= 1) {
        int x = sh[t] + ((t >= off) ? sh[t - off] : 0);
        __syncthreads();
        sh[t] = x;
        __syncthreads();
    }
    if (t < nb) bsum[t] = sh[t] - v;  // exclusive
}

__global__ void k_scan3(int* coff, int* cursor, const int* __restrict__ bsum, int n) {
    int i = blockIdx.x * blockDim.x + threadIdx.x;
    if (i < n) {
        int v = coff[i] + bsum[i >> 9];
        coff[i] = v;
        cursor[i] = v;
    }
}

__global__ void k_scatter(const int* __restrict__ dst, int* cursor, int* eid, int E) {
    int e = blockIdx.x * blockDim.x + threadIdx.x;
    if (e < E) {
        int p = atomicAdd(&cursor[dst[e]], 1);
        eid[p] = e;
    }
}

// ---------------- node-centric edge softmax (max + sum) ----------------
__global__ void k_node_ms(const int* __restrict__ src, const int* __restrict__ eid,
                          const int* __restrict__ coff, const int* __restrict__ deg,
                          const float* __restrict__ el, const float* __restrict__ er,
                          float* m, float* s, int n) {
    int idx = blockIdx.x * blockDim.x + threadIdx.x;
    if (idx >= n * HH) return;
    int i = idx >> 3, h = idx & 7;
    int off = coff[i], d = deg[i];
    float erv = er[idx];
    float mx = -INFINITY;
    for (int j = 0; j < d; j++) {
        int e = eid[off + j];
        float v = el[src[e] * HH + h] + erv;
        v = v > 0.f ? v : NEG_SLOPE * v;
        if (v > mx) mx = v;
    }
    float ss = 0.f;
    for (int j = 0; j < d; j++) {
        int e = eid[off + j];
        float v = el[src[e] * HH + h] + erv;
        v = v > 0.f ? v : NEG_SLOPE * v;
        ss += expf(v - mx);
    }
    m[idx] = mx;
    s[idx] = ss;
}

// ---------------- node-centric aggregation (warp per node) ----------------
__global__ void k_node_agg(const int* __restrict__ src, const int* __restrict__ eid,
                           const int* __restrict__ coff, const int* __restrict__ deg,
                           const float* __restrict__ el, const float* __restrict__ er,
                           const float* __restrict__ m, const float* __restrict__ s,
                           const float* __restrict__ ft, float* agg, int n) {
    int w = (blockIdx.x * blockDim.x + threadIdx.x) >> 5;
    int lane = threadIdx.x & 31;
    if (w >= n) return;
    int h = lane >> 2;
    int off = coff[w], d = deg[w];
    float erv = er[w * HH + h];
    float mv = m[w * HH + h];
    float sv = s[w * HH + h];
    float inv_s = d > 0 ? 1.f / sv : 0.f;
    float4 acc = make_float4(0.f, 0.f, 0.f, 0.f);
    for (int j = 0; j < d; j++) {
        int e = eid[off + j];
        int sn = src[e];
        float v = el[sn * HH + h] + erv;
        v = v > 0.f ? v : NEG_SLOPE * v;
        float wt = expf(v - mv) * inv_s;
        float4 fv = *(const float4*)(ft + (size_t)sn * HD + lane * 4);
        acc.x = fmaf(wt, fv.x, acc.x);
        acc.y = fmaf(wt, fv.y, acc.y);
        acc.z = fmaf(wt, fv.z, acc.z);
        acc.w = fmaf(wt, fv.w, acc.w);
    }
    *(float4*)(agg + (size_t)w * HD + lane * 4) = acc;
}

// ---------------- batchnorm column stats ----------------
__global__ void k_bnred(const float* __restrict__ Y, int n, int C, double* sum, double* sq) {
    int c = threadIdx.x;  // blockDim.x == C
    double s = 0.0, s2 = 0.0;
    for (int r = blockIdx.x; r < n; r += gridDim.x) {
        float v = Y[(long long)r * C + c];
        s += v;
        s2 += (double)v * v;
    }
    atomicAdd(&sum[c], s);
    atomicAdd(&sq[c], s2);
}
__global__ void k_bnfin(const double* sum, const double* sq, int n, float* mu, float* rstd) {
    int c = threadIdx.x;
    double m = sum[c] / n;
    double v = sq[c] / n - m * m;
    if (v < 0.0) v = 0.0;
    mu[c] = (float)m;
    rstd[c] = (float)(1.0 / sqrt(v + 1e-5));
}

__global__ void k_bnelu(const float* __restrict__ Y, const float* __restrict__ mu,
                        const float* __restrict__ rstd, float* out, long long total, int C) {
    long long i = (long long)blockIdx.x * blockDim.x + threadIdx.x;
    if (i < total) {
        int c = (int)(i % C);
        out[i] = eluf((Y[i] - mu[c]) * rstd[c]);
    }
}

__global__ void k_final(const float* __restrict__ hlast, const float* __restrict__ Y,
                        const float* __restrict__ mu, const float* __restrict__ rstd,
                        float* out, long long total) {
    long long i = (long long)blockIdx.x * blockDim.x + threadIdx.x;
    if (i < total) {
        int c = (int)(i & (HD - 1));
        float v = eluf((Y[i] - mu[c]) * rstd[c]);
        out[i] = hlast[i] + v;
    }
}

// ---------------- PE/DE sampled attention sums + loss ----------------
__global__ void k_pesum(const int* __restrict__ ids, int nids, const int* __restrict__ src,
                        const int* __restrict__ dst, const float* __restrict__ el,
                        const float* __restrict__ er, const float* __restrict__ m,
                        const float* __restrict__ s, float* out8) {
    float acc[HH];
#pragma unroll
    for (int h = 0; h < HH; h++) acc[h] = 0.f;
    for (int i = blockIdx.x * blockDim.x + threadIdx.x; i < nids; i += gridDim.x * blockDim.x) {
        int e = ids[i];
        int se = src[e] * HH, de = dst[e] * HH;
#pragma unroll
        for (int h = 0; h < HH; h++) {
            float v = el[se + h] + er[de + h];
            v = v > 0.f ? v : NEG_SLOPE * v;
            acc[h] += expf(v - m[de + h]) / s[de + h];
        }
    }
#pragma unroll
    for (int h = 0; h < HH; h++) {
#pragma unroll
        for (int o = 16; o; o >>= 1) acc[h] += __shfl_down_sync(0xffffffffu, acc[h], o);
    }
    if ((threadIdx.x & 31) == 0) {
#pragma unroll
        for (int h = 0; h < HH; h++) atomicAdd(&out8[h], acc[h]);
    }
}

__global__ void k_loss(const float* pe, const float* de, const int* lenp, float* out) {
    float sum = 0.f;
#pragma unroll
    for (int h = 0; h < HH; h++) sum += pe[h] - de[h];
    out[0] = -sum / (8.0f * (float)lenp[0]);
}

// ---------------- host side ----------------
static inline int cdiv(long long a, long long b) { return (int)((a + b - 1) / b); }
static inline void fillf(float* p, float v, long long n) { k_fillf<<<cdiv(n, 256), 256>>>(p, v, n); }

struct Scratch {
    float *feat, *ft, *agg, *y1, *y2, *el, *er, *mm, *ss, *gbuf, *qbuf;
    float *glq, *t1, *t2, *Qb, *gmax, *gsum, *gt, *dot1, *dot2, *aab, *mu, *rstd, *pe, *de;
    double *dsum, *dsq;
    int *deg, *coff, *cursor, *eid, *bsum;
};

static void run_branch(int n, int E, const float* h_last, const float* h0,
                       const int* src, const int* dst, const int* gid,
                       const float* W_L, const float* b_L,
                       const float* gate1_W, const float* gate1_b,
                       const float* gate2_W, const float* gate2_b,
                       const float* Q_comb,
                       const float* end_W1, const float* end_b1,
                       const float* end_W2, const float* end_b2,
                       float* out_branch, const Scratch& S) {
    dim3 g128(1, cdiv(n, 128)), g256(2, cdiv(n, 128));

    // --- CSR build (independent of GEMMs) ---
    int nb = cdiv(n, 512);
    k_filli<<<cdiv(n, 256), 256>>>(S.deg, 0, n);
    k_hist<<<cdiv(E, 256), 256>>>(dst, S.deg, E);
    k_scan1<<<nb, 256>>>(S.deg, S.coff, S.bsum, n);
    k_scan2<<<1, 256>>>(S.bsum, nb);
    k_scan3<<<cdiv(n, 256), 256>>>(S.coff, S.cursor, S.bsum, n);
    k_scatter<<<cdiv(E, 256), 256>>>(dst, S.cursor, S.eid, E);

    // feat = h_last @ W_L + b_L
    k_gemm_tf32<0><<<g128, 256>>>(h_last, nullptr, nullptr, nullptr, W_L, b_L, nullptr, nullptr,
                                  S.feat, n, 128, 128);
    // gate1 on h0 (with Q_comb dot)
    fillf(S.gmax, -INFINITY, BB);
    fillf(S.gsum, 0.f, BB);
    fillf(S.gt, 0.f, BB);
    k_gap_a<<<cdiv((long long)n * 32, 256), 256>>>(h0, gate1_W, gate1_b, Q_comb, gid, S.gbuf,
                                                   S.qbuf, S.gmax, n, 1);
    k_gap_b<<<cdiv(n, 256), 256>>>(gid, S.gbuf, S.qbuf, S.gmax, S.gsum, S.gt, n, 1);
    k_dotfin<<<1, BB>>>(S.gt, S.gsum, S.dot1);
    // gate2 on h_last
    fillf(S.gmax, -INFINITY, BB);
    fillf(S.gsum, 0.f, BB);
    fillf(S.gt, 0.f, BB);
    k_gap_a<<<cdiv((long long)n * 32, 256), 256>>>(h_last, gate2_W, gate2_b, Q_comb, gid, S.gbuf,
                                                   S.qbuf, S.gmax, n, 1);
    k_gap_b<<<cdiv(n, 256), 256>>>(gid, S.gbuf, S.qbuf, S.gmax, S.gsum, S.gt, n, 1);
    k_dotfin<<<1, BB>>>(S.gt, S.gsum, S.dot2);
    k_comb<<<1, BB>>>(S.dot1, S.dot2, S.aab);
    // ft = (a0*h0 + a1*h_last) @ W_L + b_L
    k_gemm_tf32<1><<<g128, 256>>>(h0, h_last, S.aab, gid, W_L, b_L, nullptr, nullptr, S.ft, n,
                                  128, 128);
    // el/er
    k_eler<<<cdiv((long long)n * HH, 256), 256>>>(S.feat, S.Qb, gid, S.el, S.er, n);
    // node-centric softmax + aggregation (no atomics)
    k_node_ms<<<cdiv((long long)n * HH, 256), 256>>>(src, S.eid, S.coff, S.deg, S.el, S.er, S.mm,
                                                     S.ss, n);
    k_node_agg<<<cdiv((long long)n * 32, 256), 256>>>(src, S.eid, S.coff, S.deg, S.el, S.er, S.mm,
                                                      S.ss, S.ft, S.agg, n);
    // end FNN
    k_gemm_tf32<0><<<g256, 256>>>(S.agg, nullptr, nullptr, nullptr, end_W1, end_b1, nullptr,
                                  nullptr, S.y1, n, 128, 256);
    k_filld<<<1, 256>>>(S.dsum, 256);
    k_filld<<<1, 256>>>(S.dsq, 256);
    k_bnred<<<512, 256>>>(S.y1, n, 256, S.dsum, S.dsq);
    k_bnfin<<<1, 256>>>(S.dsum, S.dsq, n, S.mu, S.rstd);
    k_gemm_tf32<2><<<g128, 256>>>(S.y1, nullptr, nullptr, nullptr, end_W2, end_b2, S.mu, S.rstd,
                                  S.y2, n, 256, 128);
    k_filld<<<1, 128>>>(S.dsum, 128);
    k_filld<<<1, 128>>>(S.dsq, 128);
    k_bnred<<<512, 128>>>(S.y2, n, 128, S.dsum, S.dsq);
    k_bnfin<<<1, 128>>>(S.dsum, S.dsq, n, S.mu, S.rstd);
    k_final<<<cdiv((long long)n * HD, 256), 256>>>(h_last, S.y2, S.mu, S.rstd, out_branch,
                                                   (long long)n * HD);
}

extern "C" void kernel_launch(void* const* d_in, const int* in_sizes, int n_in,
                              void* d_out, int out_size) {
    const float* h_da_last = (const float*)d_in[0];
    const float* h_q_last  = (const float*)d_in[1];
    const float* h_da_0    = (const float*)d_in[2];
    const float* h_q_0     = (const float*)d_in[3];
    const float* W_L       = (const float*)d_in[4];
    const float* b_L       = (const float*)d_in[5];
    const float* gateq_W   = (const float*)d_in[6];
    const float* gateq_b   = (const float*)d_in[7];
    const float* gate1_W   = (const float*)d_in[8];
    const float* gate1_b   = (const float*)d_in[9];
    const float* gate2_W   = (const float*)d_in[10];
    const float* gate2_b   = (const float*)d_in[11];
    const float* Q_comb    = (const float*)d_in[12];
    const float* Qf_W1     = (const float*)d_in[13];
    const float* Qf_b1     = (const float*)d_in[14];
    const float* Qf_W2     = (const float*)d_in[15];
    const float* Qf_b2     = (const float*)d_in[16];
    const float* end_W1    = (const float*)d_in[17];
    const float* end_b1    = (const float*)d_in[18];
    const float* end_W2    = (const float*)d_in[19];
    const float* end_b2    = (const float*)d_in[20];
    const int* src_da = (const int*)d_in[21];
    const int* dst_da = (const int*)d_in[22];
    const int* src_q  = (const int*)d_in[23];
    const int* dst_q  = (const int*)d_in[24];
    const int* gid_da = (const int*)d_in[25];
    const int* gid_q  = (const int*)d_in[26];
    const int* PEid   = (const int*)d_in[27];
    const int* DEid   = (const int*)d_in[28];
    const int* lenp   = (const int*)d_in[29];
    int nPE = in_sizes[27], nDE = in_sizes[28];

    float* out = (float*)d_out;
    float* out_da = out;
    float* out_q = out + (long long)NDA * HD;
    float* out_loss = out + (long long)NDA * HD + (long long)NQ * HD;

    Scratch S;
    cudaGetSymbolAddress((void**)&S.feat, g_feat);
    cudaGetSymbolAddress((void**)&S.ft, g_ft);
    cudaGetSymbolAddress((void**)&S.agg, g_agg);
    cudaGetSymbolAddress((void**)&S.y1, g_y1);
    cudaGetSymbolAddress((void**)&S.y2, g_y2);
    cudaGetSymbolAddress((void**)&S.el, g_el);
    cudaGetSymbolAddress((void**)&S.er, g_er);
    cudaGetSymbolAddress((void**)&S.mm, g_m);
    cudaGetSymbolAddress((void**)&S.ss, g_s);
    cudaGetSymbolAddress((void**)&S.gbuf, g_gb);
    cudaGetSymbolAddress((void**)&S.qbuf, g_qb);
    cudaGetSymbolAddress((void**)&S.glq, g_glq);
    cudaGetSymbolAddress((void**)&S.t1, g_t1);
    cudaGetSymbolAddress((void**)&S.t2, g_t2);
    cudaGetSymbolAddress((void**)&S.Qb, g_Q);
    cudaGetSymbolAddress((void**)&S.gmax, g_gmax);
    cudaGetSymbolAddress((void**)&S.gsum, g_gsum);
    cudaGetSymbolAddress((void**)&S.gt, g_gt);
    cudaGetSymbolAddress((void**)&S.dot1, g_dot1);
    cudaGetSymbolAddress((void**)&S.dot2, g_dot2);
    cudaGetSymbolAddress((void**)&S.aab, g_aab);
    cudaGetSymbolAddress((void**)&S.mu, g_mu);
    cudaGetSymbolAddress((void**)&S.rstd, g_rstd);
    cudaGetSymbolAddress((void**)&S.pe, g_pe);
    cudaGetSymbolAddress((void**)&S.de, g_de);
    cudaGetSymbolAddress((void**)&S.dsum, g_dsum);
    cudaGetSymbolAddress((void**)&S.dsq, g_dsq);
    cudaGetSymbolAddress((void**)&S.deg, g_deg);
    cudaGetSymbolAddress((void**)&S.coff, g_coff);
    cudaGetSymbolAddress((void**)&S.cursor, g_cursor);
    cudaGetSymbolAddress((void**)&S.eid, g_eid);
    cudaGetSymbolAddress((void**)&S.bsum, g_bsum);

    // ---- Phase 0: glq = _gap(gateq, h_q_last, gid_q); Q = fnn(glq) ----
    fillf(S.gmax, -INFINITY, BB);
    fillf(S.gsum, 0.f, BB);
    k_gap_a<<<cdiv((long long)NQ * 32, 256), 256>>>(h_q_last, gateq_W, gateq_b, nullptr, gid_q,
                                                    S.gbuf, S.qbuf, S.gmax, NQ, 0);
    k_gap_b<<<cdiv(NQ, 256), 256>>>(gid_q, S.gbuf, S.qbuf, S.gmax, S.gsum, S.gt, NQ, 0);
    fillf(S.glq, 0.f, (long long)BB * HD);
    k_gap_pool<<<cdiv((long long)NQ * 32, 256), 256>>>(h_q_last, gid_q, S.gbuf, S.gsum, S.glq, NQ);

    k_gemm_tf32<0><<<dim3(2, 1), 256>>>(S.glq, nullptr, nullptr, nullptr, Qf_W1, Qf_b1, nullptr,
                                        nullptr, S.t1, BB, 128, 256);
    k_filld<<<1, 256>>>(S.dsum, 256);
    k_filld<<<1, 256>>>(S.dsq, 256);
    k_bnred<<<8, 256>>>(S.t1, BB, 256, S.dsum, S.dsq);
    k_bnfin<<<1, 256>>>(S.dsum, S.dsq, BB, S.mu, S.rstd);
    k_gemm_tf32<2><<<dim3(2, 1), 256>>>(S.t1, nullptr, nullptr, nullptr, Qf_W2, Qf_b2, S.mu,
                                        S.rstd, S.t2, BB, 256, 256);
    k_filld<<<1, 256>>>(S.dsum, 256);
    k_filld<<<1, 256>>>(S.dsq, 256);
    k_bnred<<<8, 256>>>(S.t2, BB, 256, S.dsum, S.dsq);
    k_bnfin<<<1, 256>>>(S.dsum, S.dsq, BB, S.mu, S.rstd);
    k_bnelu<<<cdiv((long long)BB * 256, 256), 256>>>(S.t2, S.mu, S.rstd, S.Qb,
                                                     (long long)BB * 256, 256);

    // ---- q branch first (scratch reused), then da branch (its edge stats feed the loss) ----
    run_branch(NQ, EQ, h_q_last, h_q_0, src_q, dst_q, gid_q, W_L, b_L, gate1_W, gate1_b, gate2_W,
               gate2_b, Q_comb, end_W1, end_b1, end_W2, end_b2, out_q, S);
    run_branch(NDA, EDA, h_da_last, h_da_0, src_da, dst_da, gid_da, W_L, b_L, gate1_W, gate1_b,
               gate2_W, gate2_b, Q_comb, end_W1, end_b1, end_W2, end_b2, out_da, S);

    // ---- loss from da edge-attention at sampled edge ids ----
    fillf(S.pe, 0.f, HH);
    fillf(S.de, 0.f, HH);
    k_pesum<<<256, 256>>>(PEid, nPE, src_da, dst_da, S.el, S.er, S.mm, S.ss, S.pe);
    k_pesum<<<256, 256>>>(DEid, nDE, src_da, dst_da, S.el, S.er, S.mm, S.ss, S.de);
    k_loss<<<1, 1>>>(S.pe, S.de, lenp, out_loss);
}

// round 3
// speedup vs baseline: 1.5709x; 1.0006x over previous
#include <cuda_runtime.h>
#include <math.h>
#include <stdint.h>

#define NDA 100000
#define NQ  20000
#define EDA 1000000
#define EQ  200000
#define BB  64
#define HH  8
#define HD  128
#define HD2 256
#define NEG_SLOPE 2.0f

// ---------------- scratch (device globals; no allocations allowed) ----------------
__device__ float g_feat[(size_t)NDA * HD];
__device__ float g_ft[(size_t)NDA * HD];
__device__ float g_agg[(size_t)NDA * HD];
__device__ float g_y1[(size_t)NDA * HD2];
__device__ float g_y2[(size_t)NDA * HD];
__device__ float g_el[NDA * HH];
__device__ float g_er[NDA * HH];
__device__ float g_m[NDA * HH];
__device__ float g_s[NDA * HH];
__device__ float g_gb[NDA];
__device__ float g_qb[NDA];
__device__ int   g_deg[NDA];
__device__ int   g_coff[NDA];
__device__ int   g_cursor[NDA];
__device__ int   g_eid[EDA];
__device__ int   g_bsum[256];
__device__ float g_glq[BB * HD];
__device__ float g_t1[BB * HD2];
__device__ float g_t2[BB * HD2];
__device__ float g_Q[BB * HD2];
__device__ float g_gmax[BB];
__device__ float g_gsum[BB];
__device__ float g_gt[BB];
__device__ float g_dot1[BB];
__device__ float g_dot2[BB];
__device__ float g_aab[BB * 2];
__device__ double g_dsum[HD2];
__device__ double g_dsq[HD2];
__device__ float g_mu[HD2];
__device__ float g_rstd[HD2];
__device__ float g_pe[HH];
__device__ float g_de[HH];

// ---------------- device helpers ----------------
__device__ __forceinline__ float eluf(float x) { return x > 0.f ? x : expm1f(x); }

__device__ __forceinline__ void atomicMaxF(float* a, float v) {
    if (v >= 0.f) atomicMax((int*)a, __float_as_int(v));
    else          atomicMin((unsigned int*)a, __float_as_uint(v));
}

__device__ __forceinline__ uint32_t f2tf(float x) {
    uint32_t r;
    asm("cvt.rna.tf32.f32 %0, %1;" : "=r"(r) : "f"(x));
    return r;
}

__device__ __forceinline__ void mma8(float* d, const uint32_t* a, const uint32_t* b) {
    asm volatile(
        "mma.sync.aligned.m16n8k8.row.col.f32.tf32.tf32.f32 "
        "{%0,%1,%2,%3}, {%4,%5,%6,%7}, {%8,%9}, {%0,%1,%2,%3};\n"
        : "+f"(d[0]), "+f"(d[1]), "+f"(d[2]), "+f"(d[3])
        : "r"(a[0]), "r"(a[1]), "r"(a[2]), "r"(a[3]), "r"(b[0]), "r"(b[1]));
}

// ---------------- fills ----------------
__global__ void k_fillf(float* p, float v, long long n) {
    long long i = (long long)blockIdx.x * blockDim.x + threadIdx.x;
    if (i < n) p[i] = v;
}
__global__ void k_filli(int* p, int v, int n) {
    int i = blockIdx.x * blockDim.x + threadIdx.x;
    if (i < n) p[i] = v;
}
__global__ void k_filld(double* p, int n) {
    int i = blockIdx.x * blockDim.x + threadIdx.x;
    if (i < n) p[i] = 0.0;
}

// ---------------- _gap kernels ----------------
__global__ void k_gap_a(const float* __restrict__ M, const float* __restrict__ gw,
                        const float* __restrict__ gb, const float* __restrict__ qc,
                        const int* __restrict__ gid, float* g, float* q, float* gmax,
                        int n, int withq) {
    int w = (blockIdx.x * blockDim.x + threadIdx.x) >> 5;
    int lane = threadIdx.x & 31;
    if (w >= n) return;
    const float* row = M + (long long)w * HD;
    float sg = 0.f, sq = 0.f;
#pragma unroll
    for (int j = lane; j < HD; j += 32) {
        float v = row[j];
        sg = fmaf(v, gw[j], sg);
        if (withq) sq = fmaf(v, qc[j], sq);
    }
#pragma unroll
    for (int o = 16; o; o >>= 1) {
        sg += __shfl_down_sync(0xffffffffu, sg, o);
        sq += __shfl_down_sync(0xffffffffu, sq, o);
    }
    if (lane == 0) {
        sg += gb[0];
        g[w] = sg;
        if (withq) q[w] = sq;
        atomicMaxF(&gmax[gid[w]], sg);
    }
}

__global__ void k_gap_b(const int* __restrict__ gid, float* g, const float* __restrict__ q,
                        const float* __restrict__ gmax, float* gsum, float* gt, int n, int withq) {
    int i = blockIdx.x * blockDim.x + threadIdx.x;
    if (i >= n) return;
    int b = gid[i];
    float e = expf(g[i] - gmax[b]);
    g[i] = e;
    atomicAdd(&gsum[b], e);
    if (withq) atomicAdd(&gt[b], e * q[i]);
}

__global__ void k_gap_pool(const float* __restrict__ M, const int* __restrict__ gid,
                           const float* __restrict__ e, const float* __restrict__ gsum,
                           float* pool, int n) {
    int w = (blockIdx.x * blockDim.x + threadIdx.x) >> 5;
    int lane = threadIdx.x & 31;
    if (w >= n) return;
    int b = gid[w];
    float wt = e[w] / gsum[b];
    const float* row = M + (long long)w * HD;
#pragma unroll
    for (int j = lane; j < HD; j += 32) atomicAdd(&pool[b * HD + j], wt * row[j]);
}

__global__ void k_dotfin(const float* gt, const float* gsum, float* dot) {
    int b = threadIdx.x;
    if (b < BB) dot[b] = gsum[b] > 0.f ? gt[b] / gsum[b] : 0.f;
}

__global__ void k_comb(const float* d1, const float* d2, float* a) {
    int b = threadIdx.x;
    if (b < BB) {
        float x1 = d1[b], x2 = d2[b];
        float mm = fmaxf(x1, x2);
        float e1 = expf(x1 - mm), e2 = expf(x2 - mm);
        float ss = e1 + e2;
        a[2 * b] = e1 / ss;
        a[2 * b + 1] = e2 / ss;
    }
}

// ---------------- TF32 tensor-core GEMM ----------------
// C[n x NC] = f(A)[n x K] @ W[K x NC] + bias
// AMODE 0: A = A1 ; AMODE 1: A = a0[gid]*A1 + a1[gid]*A2 ; AMODE 2: A = elu(bn(A1))
// Block tile 128x128, BK=32, 8 warps (2 M x 4 N), warp tile 64x32 of m16n8k8.
template <int AMODE>
__global__ void __launch_bounds__(256) k_gemm_tf32(
    const float* __restrict__ A1, const float* __restrict__ A2,
    const float* __restrict__ acoef, const int* __restrict__ gid,
    const float* __restrict__ W, const float* __restrict__ bias,
    const float* __restrict__ mu, const float* __restrict__ rstd,
    float* __restrict__ C, int n, int K, int NC) {
    __shared__ uint32_t As[128 * 36];   // [row][k], stride 36 -> conflict-free frag loads
    __shared__ uint32_t Ws[32 * 132];   // [k][col], stride 132 -> conflict-free frag loads

    const int tid = threadIdx.x;
    const int lane = tid & 31;
    const int wid = tid >> 5;
    const int warp_m = wid >> 2;   // 0..1
    const int warp_n = wid & 3;    // 0..3
    const int rowBase = blockIdx.y * 128;
    const int colBase = blockIdx.x * 128;
    const int g4 = lane >> 2;      // 0..7
    const int t4 = lane & 3;       // 0..3

    float acc[4][4][4];
#pragma unroll
    for (int mi = 0; mi < 4; mi++)
#pragma unroll
        for (int ni = 0; ni < 4; ni++)
#pragma unroll
            for (int r = 0; r < 4; r++) acc[mi][ni][r] = 0.f;

    for (int k0 = 0; k0 < K; k0 += 32) {
        // ---- stage A tile (128 x 32) with fused transform ----
#pragma unroll
        for (int q = 0; q < 4; q++) {
            int idx = tid + q * 256;
            int r = idx >> 3, kq = idx & 7;
            int grow = rowBase + r;
            float4 av = make_float4(0.f, 0.f, 0.f, 0.f);
            if (grow < n) {
                av = *(const float4*)(A1 + (size_t)grow * K + k0 + kq * 4);
                if (AMODE == 1) {
                    int gg = gid[grow];
                    float c0 = acoef[2 * gg], c1 = acoef[2 * gg + 1];
                    float4 bv = *(const float4*)(A2 + (size_t)grow * K + k0 + kq * 4);
                    av.x = c0 * av.x + c1 * bv.x;
                    av.y = c0 * av.y + c1 * bv.y;
                    av.z = c0 * av.z + c1 * bv.z;
                    av.w = c0 * av.w + c1 * bv.w;
                } else if (AMODE == 2) {
                    int kk = k0 + kq * 4;
                    av.x = eluf((av.x - mu[kk + 0]) * rstd[kk + 0]);
                    av.y = eluf((av.y - mu[kk + 1]) * rstd[kk + 1]);
                    av.z = eluf((av.z - mu[kk + 2]) * rstd[kk + 2]);
                    av.w = eluf((av.w - mu[kk + 3]) * rstd[kk + 3]);
                }
            }
            uint32_t* dp = &As[r * 36 + kq * 4];
            dp[0] = f2tf(av.x);
            dp[1] = f2tf(av.y);
            dp[2] = f2tf(av.z);
            dp[3] = f2tf(av.w);
        }
        // ---- stage W tile (32 x 128) ----
#pragma unroll
        for (int q = 0; q < 4; q++) {
            int idx = tid + q * 256;
            int kk = idx >> 5, nq = idx & 31;
            float4 wv = *(const float4*)(W + (size_t)(k0 + kk) * NC + colBase + nq * 4);
            uint32_t* dp = &Ws[kk * 132 + nq * 4];
            dp[0] = f2tf(wv.x);
            dp[1] = f2tf(wv.y);
            dp[2] = f2tf(wv.z);
            dp[3] = f2tf(wv.w);
        }
        __syncthreads();
        // ---- compute ----
#pragma unroll
        for (int ks = 0; ks < 4; ks++) {
            int kk = ks * 8;
            uint32_t a[4][4];
#pragma unroll
            for (int mi = 0; mi < 4; mi++) {
                int r = warp_m * 64 + mi * 16 + g4;
                a[mi][0] = As[r * 36 + kk + t4];
                a[mi][1] = As[(r + 8) * 36 + kk + t4];
                a[mi][2] = As[r * 36 + kk + t4 + 4];
                a[mi][3] = As[(r + 8) * 36 + kk + t4 + 4];
            }
            uint32_t b[4][2];
#pragma unroll
            for (int ni = 0; ni < 4; ni++) {
                int c = warp_n * 32 + ni * 8 + g4;
                b[ni][0] = Ws[(kk + t4) * 132 + c];
                b[ni][1] = Ws[(kk + t4 + 4) * 132 + c];
            }
#pragma unroll
            for (int mi = 0; mi < 4; mi++)
#pragma unroll
                for (int ni = 0; ni < 4; ni++) mma8(acc[mi][ni], a[mi], b[ni]);
        }
        __syncthreads();
    }

    // ---- epilogue ----
#pragma unroll
    for (int mi = 0; mi < 4; mi++) {
        int r0 = rowBase + warp_m * 64 + mi * 16 + g4;
        int r1 = r0 + 8;
#pragma unroll
        for (int ni = 0; ni < 4; ni++) {
            int c = colBase + warp_n * 32 + ni * 8 + t4 * 2;
            float b0 = bias[c], b1 = bias[c + 1];
            if (r0 < n) {
                C[(size_t)r0 * NC + c]     = acc[mi][ni][0] + b0;
                C[(size_t)r0 * NC + c + 1] = acc[mi][ni][1] + b1;
            }
            if (r1 < n) {
                C[(size_t)r1 * NC + c]     = acc[mi][ni][2] + b0;
                C[(size_t)r1 * NC + c + 1] = acc[mi][ni][3] + b1;
            }
        }
    }
}

// ---------------- el / er per (node, head) ----------------
__global__ void k_eler(const float* __restrict__ feat, const float* __restrict__ Q,
                       const int* __restrict__ gid, float* el, float* er, int n) {
    int idx = blockIdx.x * blockDim.x + threadIdx.x;
    if (idx >= n * HH) return;
    int i = idx >> 3, h = idx & 7;
    const float* f = feat + (long long)i * HD + h * 16;
    const float* q = Q + (long long)gid[i] * HD2 + h * 32;
    float sl = 0.f, sr = 0.f;
#pragma unroll
    for (int c = 0; c < 16; c++) {
        float fv = f[c];
        sl = fmaf(fv, q[c], sl);
        sr = fmaf(fv, q[16 + c], sr);
    }
    el[idx] = sl;
    er[idx] = sr;
}

// ---------------- CSR construction ----------------
__global__ void k_hist(const int* __restrict__ dst, int* deg, int E) {
    int e = blockIdx.x * blockDim.x + threadIdx.x;
    if (e < E) atomicAdd(&deg[dst[e]], 1);
}

// per-512-block exclusive scan + block totals
__global__ void k_scan1(const int* __restrict__ deg, int* out, int* bsum, int n) {
    __shared__ int sh[512];
    int base = blockIdx.x * 512;
    int t = threadIdx.x;
    int v0 = (base + t < n) ? deg[base + t] : 0;
    int v1 = (base + 256 + t < n) ? deg[base + 256 + t] : 0;
    sh[t] = v0;
    sh[t + 256] = v1;
    __syncthreads();
    for (int off = 1; off < 512; off <<= 1) {
        int i0 = t, i1 = t + 256;
        int n0 = sh[i0] + ((i0 >= off) ? sh[i0 - off] : 0);
        int n1 = sh[i1] + ((i1 >= off) ? sh[i1 - off] : 0);
        __syncthreads();
        sh[i0] = n0;
        sh[i1] = n1;
        __syncthreads();
    }
    if (base + t < n) out[base + t] = sh[t] - v0;
    if (base + 256 + t < n) out[base + 256 + t] = sh[t + 256] - v1;
    if (t == 0) bsum[blockIdx.x] = sh[511];
}

__global__ void k_scan2(int* bsum, int nb) {
    __shared__ int sh[256];
    int t = threadIdx.x;
    int v = (t < nb) ? bsum[t] : 0;
    sh[t] = v;
    __syncthreads();
    for (int off = 1; off < 256; off <<= 1) {
        int x = sh[t] + ((t >= off) ? sh[t - off] : 0);
        __syncthreads();
        sh[t] = x;
        __syncthreads();
    }
    if (t < nb) bsum[t] = sh[t] - v;  // exclusive
}

__global__ void k_scan3(int* coff, int* cursor, const int* __restrict__ bsum, int n) {
    int i = blockIdx.x * blockDim.x + threadIdx.x;
    if (i < n) {
        int v = coff[i] + bsum[i >> 9];
        coff[i] = v;
        cursor[i] = v;
    }
}

__global__ void k_scatter(const int* __restrict__ dst, int* cursor, int* eid, int E) {
    int e = blockIdx.x * blockDim.x + threadIdx.x;
    if (e < E) {
        int p = atomicAdd(&cursor[dst[e]], 1);
        eid[p] = e;
    }
}

// ---------------- node-centric edge softmax (max + sum) ----------------
__global__ void k_node_ms(const int* __restrict__ src, const int* __restrict__ eid,
                          const int* __restrict__ coff, const int* __restrict__ deg,
                          const float* __restrict__ el, const float* __restrict__ er,
                          float* m, float* s, int n) {
    int idx = blockIdx.x * blockDim.x + threadIdx.x;
    if (idx >= n * HH) return;
    int i = idx >> 3, h = idx & 7;
    int off = coff[i], d = deg[i];
    float erv = er[idx];
    float mx = -INFINITY;
    for (int j = 0; j < d; j++) {
        int e = eid[off + j];
        float v = el[src[e] * HH + h] + erv;
        v = v > 0.f ? v : NEG_SLOPE * v;
        if (v > mx) mx = v;
    }
    float ss = 0.f;
    for (int j = 0; j < d; j++) {
        int e = eid[off + j];
        float v = el[src[e] * HH + h] + erv;
        v = v > 0.f ? v : NEG_SLOPE * v;
        ss += expf(v - mx);
    }
    m[idx] = mx;
    s[idx] = ss;
}

// ---------------- node-centric aggregation (warp per node) ----------------
__global__ void k_node_agg(const int* __restrict__ src, const int* __restrict__ eid,
                           const int* __restrict__ coff, const int* __restrict__ deg,
                           const float* __restrict__ el, const float* __restrict__ er,
                           const float* __restrict__ m, const float* __restrict__ s,
                           const float* __restrict__ ft, float* agg, int n) {
    int w = (blockIdx.x * blockDim.x + threadIdx.x) >> 5;
    int lane = threadIdx.x & 31;
    if (w >= n) return;
    int h = lane >> 2;
    int off = coff[w], d = deg[w];
    float erv = er[w * HH + h];
    float mv = m[w * HH + h];
    float sv = s[w * HH + h];
    float inv_s = d > 0 ? 1.f / sv : 0.f;
    float4 acc = make_float4(0.f, 0.f, 0.f, 0.f);
    for (int j = 0; j < d; j++) {
        int e = eid[off + j];
        int sn = src[e];
        float v = el[sn * HH + h] + erv;
        v = v > 0.f ? v : NEG_SLOPE * v;
        float wt = expf(v - mv) * inv_s;
        float4 fv = *(const float4*)(ft + (size_t)sn * HD + lane * 4);
        acc.x = fmaf(wt, fv.x, acc.x);
        acc.y = fmaf(wt, fv.y, acc.y);
        acc.z = fmaf(wt, fv.z, acc.z);
        acc.w = fmaf(wt, fv.w, acc.w);
    }
    *(float4*)(agg + (size_t)w * HD + lane * 4) = acc;
}

// ---------------- batchnorm column stats ----------------
__global__ void k_bnred(const float* __restrict__ Y, int n, int C, double* sum, double* sq) {
    int c = threadIdx.x;  // blockDim.x == C
    double s = 0.0, s2 = 0.0;
    for (int r = blockIdx.x; r < n; r += gridDim.x) {
        float v = Y[(long long)r * C + c];
        s += v;
        s2 += (double)v * v;
    }
    atomicAdd(&sum[c], s);
    atomicAdd(&sq[c], s2);
}
__global__ void k_bnfin(const double* sum, const double* sq, int n, float* mu, float* rstd) {
    int c = threadIdx.x;
    double m = sum[c] / n;
    double v = sq[c] / n - m * m;
    if (v < 0.0) v = 0.0;
    mu[c] = (float)m;
    rstd[c] = (float)(1.0 / sqrt(v + 1e-5));
}

__global__ void k_bnelu(const float* __restrict__ Y, const float* __restrict__ mu,
                        const float* __restrict__ rstd, float* out, long long total, int C) {
    long long i = (long long)blockIdx.x * blockDim.x + threadIdx.x;
    if (i < total) {
        int c = (int)(i % C);
        out[i] = eluf((Y[i] - mu[c]) * rstd[c]);
    }
}

__global__ void k_final(const float* __restrict__ hlast, const float* __restrict__ Y,
                        const float* __restrict__ mu, const float* __restrict__ rstd,
                        float* out, long long total) {
    long long i = (long long)blockIdx.x * blockDim.x + threadIdx.x;
    if (i < total) {
        int c = (int)(i & (HD - 1));
        float v = eluf((Y[i] - mu[c]) * rstd[c]);
        out[i] = hlast[i] + v;
    }
}

// ---------------- PE/DE sampled attention sums + loss ----------------
__global__ void k_pesum(const int* __restrict__ ids, int nids, const int* __restrict__ src,
                        const int* __restrict__ dst, const float* __restrict__ el,
                        const float* __restrict__ er, const float* __restrict__ m,
                        const float* __restrict__ s, float* out8) {
    float acc[HH];
#pragma unroll
    for (int h = 0; h < HH; h++) acc[h] = 0.f;
    for (int i = blockIdx.x * blockDim.x + threadIdx.x; i < nids; i += gridDim.x * blockDim.x) {
        int e = ids[i];
        int se = src[e] * HH, de = dst[e] * HH;
#pragma unroll
        for (int h = 0; h < HH; h++) {
            float v = el[se + h] + er[de + h];
            v = v > 0.f ? v : NEG_SLOPE * v;
            acc[h] += expf(v - m[de + h]) / s[de + h];
        }
    }
#pragma unroll
    for (int h = 0; h < HH; h++) {
#pragma unroll
        for (int o = 16; o; o >>= 1) acc[h] += __shfl_down_sync(0xffffffffu, acc[h], o);
    }
    if ((threadIdx.x & 31) == 0) {
#pragma unroll
        for (int h = 0; h < HH; h++) atomicAdd(&out8[h], acc[h]);
    }
}

__global__ void k_loss(const float* pe, const float* de, const int* lenp, float* out) {
    float sum = 0.f;
#pragma unroll
    for (int h = 0; h < HH; h++) sum += pe[h] - de[h];
    out[0] = -sum / (8.0f * (float)lenp[0]);
}

// ---------------- host side ----------------
static inline int cdiv(long long a, long long b) { return (int)((a + b - 1) / b); }
static inline void fillf(float* p, float v, long long n) { k_fillf<<<cdiv(n, 256), 256>>>(p, v, n); }

struct Scratch {
    float *feat, *ft, *agg, *y1, *y2, *el, *er, *mm, *ss, *gbuf, *qbuf;
    float *glq, *t1, *t2, *Qb, *gmax, *gsum, *gt, *dot1, *dot2, *aab, *mu, *rstd, *pe, *de;
    double *dsum, *dsq;
    int *deg, *coff, *cursor, *eid, *bsum;
};

static void run_branch(int n, int E, const float* h_last, const float* h0,
                       const int* src, const int* dst, const int* gid,
                       const float* W_L, const float* b_L,
                       const float* gate1_W, const float* gate1_b,
                       const float* gate2_W, const float* gate2_b,
                       const float* Q_comb,
                       const float* end_W1, const float* end_b1,
                       const float* end_W2, const float* end_b2,
                       float* out_branch, const Scratch& S) {
    dim3 g128(1, cdiv(n, 128)), g256(2, cdiv(n, 128));

    // --- CSR build (independent of GEMMs) ---
    int nb = cdiv(n, 512);
    k_filli<<<cdiv(n, 256), 256>>>(S.deg, 0, n);
    k_hist<<<cdiv(E, 256), 256>>>(dst, S.deg, E);
    k_scan1<<<nb, 256>>>(S.deg, S.coff, S.bsum, n);
    k_scan2<<<1, 256>>>(S.bsum, nb);
    k_scan3<<<cdiv(n, 256), 256>>>(S.coff, S.cursor, S.bsum, n);
    k_scatter<<<cdiv(E, 256), 256>>>(dst, S.cursor, S.eid, E);

    // feat = h_last @ W_L + b_L
    k_gemm_tf32<0><<<g128, 256>>>(h_last, nullptr, nullptr, nullptr, W_L, b_L, nullptr, nullptr,
                                  S.feat, n, 128, 128);
    // gate1 on h0 (with Q_comb dot)
    fillf(S.gmax, -INFINITY, BB);
    fillf(S.gsum, 0.f, BB);
    fillf(S.gt, 0.f, BB);
    k_gap_a<<<cdiv((long long)n * 32, 256), 256>>>(h0, gate1_W, gate1_b, Q_comb, gid, S.gbuf,
                                                   S.qbuf, S.gmax, n, 1);
    k_gap_b<<<cdiv(n, 256), 256>>>(gid, S.gbuf, S.qbuf, S.gmax, S.gsum, S.gt, n, 1);
    k_dotfin<<<1, BB>>>(S.gt, S.gsum, S.dot1);
    // gate2 on h_last
    fillf(S.gmax, -INFINITY, BB);
    fillf(S.gsum, 0.f, BB);
    fillf(S.gt, 0.f, BB);
    k_gap_a<<<cdiv((long long)n * 32, 256), 256>>>(h_last, gate2_W, gate2_b, Q_comb, gid, S.gbuf,
                                                   S.qbuf, S.gmax, n, 1);
    k_gap_b<<<cdiv(n, 256), 256>>>(gid, S.gbuf, S.qbuf, S.gmax, S.gsum, S.gt, n, 1);
    k_dotfin<<<1, BB>>>(S.gt, S.gsum, S.dot2);
    k_comb<<<1, BB>>>(S.dot1, S.dot2, S.aab);
    // ft = (a0*h0 + a1*h_last) @ W_L + b_L
    k_gemm_tf32<1><<<g128, 256>>>(h0, h_last, S.aab, gid, W_L, b_L, nullptr, nullptr, S.ft, n,
                                  128, 128);
    // el/er
    k_eler<<<cdiv((long long)n * HH, 256), 256>>>(S.feat, S.Qb, gid, S.el, S.er, n);
    // node-centric softmax + aggregation (no atomics)
    k_node_ms<<<cdiv((long long)n * HH, 256), 256>>>(src, S.eid, S.coff, S.deg, S.el, S.er, S.mm,
                                                     S.ss, n);
    k_node_agg<<<cdiv((long long)n * 32, 256), 256>>>(src, S.eid, S.coff, S.deg, S.el, S.er, S.mm,
                                                      S.ss, S.ft, S.agg, n);
    // end FNN
    k_gemm_tf32<0><<<g256, 256>>>(S.agg, nullptr, nullptr, nullptr, end_W1, end_b1, nullptr,
                                  nullptr, S.y1, n, 128, 256);
    k_filld<<<1, 256>>>(S.dsum, 256);
    k_filld<<<1, 256>>>(S.dsq, 256);
    k_bnred<<<512, 256>>>(S.y1, n, 256, S.dsum, S.dsq);
    k_bnfin<<<1, 256>>>(S.dsum, S.dsq, n, S.mu, S.rstd);
    k_gemm_tf32<2><<<g128, 256>>>(S.y1, nullptr, nullptr, nullptr, end_W2, end_b2, S.mu, S.rstd,
                                  S.y2, n, 256, 128);
    k_filld<<<1, 128>>>(S.dsum, 128);
    k_filld<<<1, 128>>>(S.dsq, 128);
    k_bnred<<<512, 128>>>(S.y2, n, 128, S.dsum, S.dsq);
    k_bnfin<<<1, 128>>>(S.dsum, S.dsq, n, S.mu, S.rstd);
    k_final<<<cdiv((long long)n * HD, 256), 256>>>(h_last, S.y2, S.mu, S.rstd, out_branch,
                                                   (long long)n * HD);
}

extern "C" void kernel_launch(void* const* d_in, const int* in_sizes, int n_in,
                              void* d_out, int out_size) {
    const float* h_da_last = (const float*)d_in[0];
    const float* h_q_last  = (const float*)d_in[1];
    const float* h_da_0    = (const float*)d_in[2];
    const float* h_q_0     = (const float*)d_in[3];
    const float* W_L       = (const float*)d_in[4];
    const float* b_L       = (const float*)d_in[5];
    const float* gateq_W   = (const float*)d_in[6];
    const float* gateq_b   = (const float*)d_in[7];
    const float* gate1_W   = (const float*)d_in[8];
    const float* gate1_b   = (const float*)d_in[9];
    const float* gate2_W   = (const float*)d_in[10];
    const float* gate2_b   = (const float*)d_in[11];
    const float* Q_comb    = (const float*)d_in[12];
    const float* Qf_W1     = (const float*)d_in[13];
    const float* Qf_b1     = (const float*)d_in[14];
    const float* Qf_W2     = (const float*)d_in[15];
    const float* Qf_b2     = (const float*)d_in[16];
    const float* end_W1    = (const float*)d_in[17];
    const float* end_b1    = (const float*)d_in[18];
    const float* end_W2    = (const float*)d_in[19];
    const float* end_b2    = (const float*)d_in[20];
    const int* src_da = (const int*)d_in[21];
    const int* dst_da = (const int*)d_in[22];
    const int* src_q  = (const int*)d_in[23];
    const int* dst_q  = (const int*)d_in[24];
    const int* gid_da = (const int*)d_in[25];
    const int* gid_q  = (const int*)d_in[26];
    const int* PEid   = (const int*)d_in[27];
    const int* DEid   = (const int*)d_in[28];
    const int* lenp   = (const int*)d_in[29];
    int nPE = in_sizes[27], nDE = in_sizes[28];

    float* out = (float*)d_out;
    float* out_da = out;
    float* out_q = out + (long long)NDA * HD;
    float* out_loss = out + (long long)NDA * HD + (long long)NQ * HD;

    Scratch S;
    cudaGetSymbolAddress((void**)&S.feat, g_feat);
    cudaGetSymbolAddress((void**)&S.ft, g_ft);
    cudaGetSymbolAddress((void**)&S.agg, g_agg);
    cudaGetSymbolAddress((void**)&S.y1, g_y1);
    cudaGetSymbolAddress((void**)&S.y2, g_y2);
    cudaGetSymbolAddress((void**)&S.el, g_el);
    cudaGetSymbolAddress((void**)&S.er, g_er);
    cudaGetSymbolAddress((void**)&S.mm, g_m);
    cudaGetSymbolAddress((void**)&S.ss, g_s);
    cudaGetSymbolAddress((void**)&S.gbuf, g_gb);
    cudaGetSymbolAddress((void**)&S.qbuf, g_qb);
    cudaGetSymbolAddress((void**)&S.glq, g_glq);
    cudaGetSymbolAddress((void**)&S.t1, g_t1);
    cudaGetSymbolAddress((void**)&S.t2, g_t2);
    cudaGetSymbolAddress((void**)&S.Qb, g_Q);
    cudaGetSymbolAddress((void**)&S.gmax, g_gmax);
    cudaGetSymbolAddress((void**)&S.gsum, g_gsum);
    cudaGetSymbolAddress((void**)&S.gt, g_gt);
    cudaGetSymbolAddress((void**)&S.dot1, g_dot1);
    cudaGetSymbolAddress((void**)&S.dot2, g_dot2);
    cudaGetSymbolAddress((void**)&S.aab, g_aab);
    cudaGetSymbolAddress((void**)&S.mu, g_mu);
    cudaGetSymbolAddress((void**)&S.rstd, g_rstd);
    cudaGetSymbolAddress((void**)&S.pe, g_pe);
    cudaGetSymbolAddress((void**)&S.de, g_de);
    cudaGetSymbolAddress((void**)&S.dsum, g_dsum);
    cudaGetSymbolAddress((void**)&S.dsq, g_dsq);
    cudaGetSymbolAddress((void**)&S.deg, g_deg);
    cudaGetSymbolAddress((void**)&S.coff, g_coff);
    cudaGetSymbolAddress((void**)&S.cursor, g_cursor);
    cudaGetSymbolAddress((void**)&S.eid, g_eid);
    cudaGetSymbolAddress((void**)&S.bsum, g_bsum);

    // ---- Phase 0: glq = _gap(gateq, h_q_last, gid_q); Q = fnn(glq) ----
    fillf(S.gmax, -INFINITY, BB);
    fillf(S.gsum, 0.f, BB);
    k_gap_a<<<cdiv((long long)NQ * 32, 256), 256>>>(h_q_last, gateq_W, gateq_b, nullptr, gid_q,
                                                    S.gbuf, S.qbuf, S.gmax, NQ, 0);
    k_gap_b<<<cdiv(NQ, 256), 256>>>(gid_q, S.gbuf, S.qbuf, S.gmax, S.gsum, S.gt, NQ, 0);
    fillf(S.glq, 0.f, (long long)BB * HD);
    k_gap_pool<<<cdiv((long long)NQ * 32, 256), 256>>>(h_q_last, gid_q, S.gbuf, S.gsum, S.glq, NQ);

    k_gemm_tf32<0><<<dim3(2, 1), 256>>>(S.glq, nullptr, nullptr, nullptr, Qf_W1, Qf_b1, nullptr,
                                        nullptr, S.t1, BB, 128, 256);
    k_filld<<<1, 256>>>(S.dsum, 256);
    k_filld<<<1, 256>>>(S.dsq, 256);
    k_bnred<<<8, 256>>>(S.t1, BB, 256, S.dsum, S.dsq);
    k_bnfin<<<1, 256>>>(S.dsum, S.dsq, BB, S.mu, S.rstd);
    k_gemm_tf32<2><<<dim3(2, 1), 256>>>(S.t1, nullptr, nullptr, nullptr, Qf_W2, Qf_b2, S.mu,
                                        S.rstd, S.t2, BB, 256, 256);
    k_filld<<<1, 256>>>(S.dsum, 256);
    k_filld<<<1, 256>>>(S.dsq, 256);
    k_bnred<<<8, 256>>>(S.t2, BB, 256, S.dsum, S.dsq);
    k_bnfin<<<1, 256>>>(S.dsum, S.dsq, BB, S.mu, S.rstd);
    k_bnelu<<<cdiv((long long)BB * 256, 256), 256>>>(S.t2, S.mu, S.rstd, S.Qb,
                                                     (long long)BB * 256, 256);

    // ---- q branch first (scratch reused), then da branch (its edge stats feed the loss) ----
    run_branch(NQ, EQ, h_q_last, h_q_0, src_q, dst_q, gid_q, W_L, b_L, gate1_W, gate1_b, gate2_W,
               gate2_b, Q_comb, end_W1, end_b1, end_W2, end_b2, out_q, S);
    run_branch(NDA, EDA, h_da_last, h_da_0, src_da, dst_da, gid_da, W_L, b_L, gate1_W, gate1_b,
               gate2_W, gate2_b, Q_comb, end_W1, end_b1, end_W2, end_b2, out_da, S);

    // ---- loss from da edge-attention at sampled edge ids ----
    fillf(S.pe, 0.f, HH);
    fillf(S.de, 0.f, HH);
    k_pesum<<<256, 256>>>(PEid, nPE, src_da, dst_da, S.el, S.er, S.mm, S.ss, S.pe);
    k_pesum<<<256, 256>>>(DEid, nDE, src_da, dst_da, S.el, S.er, S.mm, S.ss, S.de);
    k_loss<<<1, 1>>>(S.pe, S.de, lenp, out_loss);
}

// round 5
// speedup vs baseline: 2.8636x; 1.8230x over previous
#include <cuda_runtime.h>
#include <math.h>
#include <stdint.h>

#define NDA 100000
#define NQ  20000
#define EDA 1000000
#define EQ  200000
#define BB  64
#define HH  8
#define HD  128
#define HD2 256
#define NEG_SLOPE 2.0f

// ---------------- scratch ----------------
__device__ float g_feat[(size_t)NDA * HD];
__device__ float g_featq[(size_t)NQ * HD];
__device__ float g_ft[(size_t)NDA * HD];
__device__ float g_agg[(size_t)NDA * HD];
__device__ float g_y1[(size_t)NDA * HD2];
__device__ float g_y2[(size_t)NDA * HD];
__device__ float g_el[NDA * HH];
__device__ float g_er[NDA * HH];
__device__ float g_s[NDA * HH];
__device__ float g_eb[NQ];
__device__ int   g_deg[NDA];
__device__ int   g_coff[NDA];
__device__ int   g_cursor[NDA];
__device__ int   g_eid[EDA];
__device__ int   g_bsum[256];
__device__ int   g_degq[NQ];
__device__ int   g_coffq[NQ];
__device__ int   g_cursorq[NQ];
__device__ int   g_eidq[EQ];
__device__ int   g_bsumq[256];
__device__ float g_glq[BB * HD];
__device__ float g_t1[BB * HD2];
__device__ float g_t2[BB * HD2];
__device__ float g_Q[BB * HD2];
__device__ float g_gsumq[BB];
__device__ float g_accq[BB * 4];
__device__ float g_accda[BB * 4];
__device__ float g_aabq[BB * 2];
__device__ float g_aabda[BB * 2];
__device__ double g_dstat[512];
__device__ float g_mu[HD2];
__device__ float g_rstd[HD2];
__device__ float g_pe[HH];
__device__ float g_de[HH];

__device__ __forceinline__ float eluf(float x) { return x > 0.f ? x : expm1f(x); }

__device__ __forceinline__ uint32_t f2tf(float x) {
    uint32_t r;
    asm("cvt.rna.tf32.f32 %0, %1;" : "=r"(r) : "f"(x));
    return r;
}
__device__ __forceinline__ void mma8(float* d, const uint32_t* a, const uint32_t* b) {
    asm volatile(
        "mma.sync.aligned.m16n8k8.row.col.f32.tf32.tf32.f32 "
        "{%0,%1,%2,%3}, {%4,%5,%6,%7}, {%8,%9}, {%0,%1,%2,%3};\n"
        : "+f"(d[0]), "+f"(d[1]), "+f"(d[2]), "+f"(d[3])
        : "r"(a[0]), "r"(a[1]), "r"(a[2]), "r"(a[3]), "r"(b[0]), "r"(b[1]));
}

// ---------------- fills ----------------
__global__ void k_zero0(float* glq, float* gsumq, float* accq, float* accda, float* pe, float* de,
                        int* degda, int* degq) {
    int i = blockIdx.x * blockDim.x + threadIdx.x;
    if (i < NDA) degda[i] = 0;
    if (i < NQ) degq[i] = 0;
    if (i < BB * HD) glq[i] = 0.f;
    if (i < BB) gsumq[i] = 0.f;
    if (i < BB * 4) { accq[i] = 0.f; accda[i] = 0.f; }
    if (i < HH) { pe[i] = 0.f; de[i] = 0.f; }
}
__global__ void k_filld(double* p, int n) {
    int i = blockIdx.x * blockDim.x + threadIdx.x;
    if (i < n) p[i] = 0.0;
}

// ---------------- TF32 tensor-core GEMM + optional fused BN stats ----------------
// AMODE 0: A=A1 ; 1: A=a0[gid]*A1+a1[gid]*A2 ; 2: A=elu(bn(A1))
template <int AMODE, int STAT>
__global__ void __launch_bounds__(256) k_gemm_tf32(
    const float* __restrict__ A1, const float* __restrict__ A2,
    const float* __restrict__ acoef, const int* __restrict__ gid,
    const float* __restrict__ W, const float* __restrict__ bias,
    const float* __restrict__ mu, const float* __restrict__ rstd,
    float* __restrict__ C, double* dstat, int n, int K, int NC) {
    __shared__ uint32_t As[128 * 36];
    __shared__ uint32_t Ws[32 * 132];
    __shared__ float sstat[256];

    const int tid = threadIdx.x;
    const int lane = tid & 31;
    const int wid = tid >> 5;
    const int warp_m = wid >> 2;
    const int warp_n = wid & 3;
    const int rowBase = blockIdx.y * 128;
    const int colBase = blockIdx.x * 128;
    const int g4 = lane >> 2;
    const int t4 = lane & 3;

    if (STAT && tid < 256) sstat[tid] = 0.f;

    float acc[4][4][4];
#pragma unroll
    for (int mi = 0; mi < 4; mi++)
#pragma unroll
        for (int ni = 0; ni < 4; ni++)
#pragma unroll
            for (int r = 0; r < 4; r++) acc[mi][ni][r] = 0.f;

    for (int k0 = 0; k0 < K; k0 += 32) {
#pragma unroll
        for (int q = 0; q < 4; q++) {
            int idx = tid + q * 256;
            int r = idx >> 3, kq = idx & 7;
            int grow = rowBase + r;
            float4 av = make_float4(0.f, 0.f, 0.f, 0.f);
            if (grow < n) {
                av = *(const float4*)(A1 + (size_t)grow * K + k0 + kq * 4);
                if (AMODE == 1) {
                    int gg = gid[grow];
                    float c0 = acoef[2 * gg], c1 = acoef[2 * gg + 1];
                    float4 bv = *(const float4*)(A2 + (size_t)grow * K + k0 + kq * 4);
                    av.x = c0 * av.x + c1 * bv.x;
                    av.y = c0 * av.y + c1 * bv.y;
                    av.z = c0 * av.z + c1 * bv.z;
                    av.w = c0 * av.w + c1 * bv.w;
                } else if (AMODE == 2) {
                    int kk = k0 + kq * 4;
                    av.x = eluf((av.x - mu[kk + 0]) * rstd[kk + 0]);
                    av.y = eluf((av.y - mu[kk + 1]) * rstd[kk + 1]);
                    av.z = eluf((av.z - mu[kk + 2]) * rstd[kk + 2]);
                    av.w = eluf((av.w - mu[kk + 3]) * rstd[kk + 3]);
                }
            }
            uint32_t* dp = &As[r * 36 + kq * 4];
            dp[0] = f2tf(av.x);
            dp[1] = f2tf(av.y);
            dp[2] = f2tf(av.z);
            dp[3] = f2tf(av.w);
        }
#pragma unroll
        for (int q = 0; q < 4; q++) {
            int idx = tid + q * 256;
            int kk = idx >> 5, nq = idx & 31;
            float4 wv = *(const float4*)(W + (size_t)(k0 + kk) * NC + colBase + nq * 4);
            uint32_t* dp = &Ws[kk * 132 + nq * 4];
            dp[0] = f2tf(wv.x);
            dp[1] = f2tf(wv.y);
            dp[2] = f2tf(wv.z);
            dp[3] = f2tf(wv.w);
        }
        __syncthreads();
#pragma unroll
        for (int ks = 0; ks < 4; ks++) {
            int kk = ks * 8;
            uint32_t a[4][4];
#pragma unroll
            for (int mi = 0; mi < 4; mi++) {
                int r = warp_m * 64 + mi * 16 + g4;
                a[mi][0] = As[r * 36 + kk + t4];
                a[mi][1] = As[(r + 8) * 36 + kk + t4];
                a[mi][2] = As[r * 36 + kk + t4 + 4];
                a[mi][3] = As[(r + 8) * 36 + kk + t4 + 4];
            }
            uint32_t b[4][2];
#pragma unroll
            for (int ni = 0; ni < 4; ni++) {
                int c = warp_n * 32 + ni * 8 + g4;
                b[ni][0] = Ws[(kk + t4) * 132 + c];
                b[ni][1] = Ws[(kk + t4 + 4) * 132 + c];
            }
#pragma unroll
            for (int mi = 0; mi < 4; mi++)
#pragma unroll
                for (int ni = 0; ni < 4; ni++) mma8(acc[mi][ni], a[mi], b[ni]);
        }
        __syncthreads();
    }

    float cs[8], cq[8];
#pragma unroll
    for (int i = 0; i < 8; i++) { cs[i] = 0.f; cq[i] = 0.f; }

#pragma unroll
    for (int mi = 0; mi < 4; mi++) {
        int r0 = rowBase + warp_m * 64 + mi * 16 + g4;
        int r1 = r0 + 8;
#pragma unroll
        for (int ni = 0; ni < 4; ni++) {
            int c = colBase + warp_n * 32 + ni * 8 + t4 * 2;
            float b0 = bias[c], b1 = bias[c + 1];
            if (r0 < n) {
                float v0 = acc[mi][ni][0] + b0, v1 = acc[mi][ni][1] + b1;
                C[(size_t)r0 * NC + c] = v0;
                C[(size_t)r0 * NC + c + 1] = v1;
                if (STAT) {
                    cs[ni * 2] += v0; cq[ni * 2] += v0 * v0;
                    cs[ni * 2 + 1] += v1; cq[ni * 2 + 1] += v1 * v1;
                }
            }
            if (r1 < n) {
                float v2 = acc[mi][ni][2] + b0, v3 = acc[mi][ni][3] + b1;
                C[(size_t)r1 * NC + c] = v2;
                C[(size_t)r1 * NC + c + 1] = v3;
                if (STAT) {
                    cs[ni * 2] += v2; cq[ni * 2] += v2 * v2;
                    cs[ni * 2 + 1] += v3; cq[ni * 2 + 1] += v3 * v3;
                }
            }
        }
    }
    if (STAT) {
#pragma unroll
        for (int i = 0; i < 8; i++) {
            float s = cs[i], q = cq[i];
            s += __shfl_down_sync(0xffffffffu, s, 16);
            q += __shfl_down_sync(0xffffffffu, q, 16);
            s += __shfl_down_sync(0xffffffffu, s, 8);
            q += __shfl_down_sync(0xffffffffu, q, 8);
            s += __shfl_down_sync(0xffffffffu, s, 4);
            q += __shfl_down_sync(0xffffffffu, q, 4);
            if (g4 == 0) {
                int c = warp_n * 32 + (i >> 1) * 8 + t4 * 2 + (i & 1);
                atomicAdd(&sstat[c], s);
                atomicAdd(&sstat[128 + c], q);
            }
        }
        __syncthreads();
        if (tid < 128) {
            atomicAdd(&dstat[colBase + tid], (double)sstat[tid]);
            atomicAdd(&dstat[256 + colBase + tid], (double)sstat[128 + tid]);
        }
    }
}

// ---------------- fused gate kernels (sorted gid -> block-reduced atomics) ----------------
__global__ void __launch_bounds__(1024) k_gapq(const float* __restrict__ M,
                                               const float* __restrict__ w,
                                               const float* __restrict__ b,
                                               const int* __restrict__ gid, float* ebuf,
                                               float* gsum, int n) {
    __shared__ int sgid[32];
    __shared__ float se[32];
    int wid = threadIdx.x >> 5, lane = threadIdx.x & 31;
    int node = blockIdx.x * 32 + wid;
    if (node < n) {
        const float* row = M + (size_t)node * HD;
        float s = 0.f;
#pragma unroll
        for (int j = lane; j < HD; j += 32) s = fmaf(row[j], w[j], s);
#pragma unroll
        for (int o = 16; o; o >>= 1) s += __shfl_down_sync(0xffffffffu, s, o);
        if (lane == 0) {
            float e = expf(s + b[0]);
            ebuf[node] = e;
            sgid[wid] = gid[node];
            se[wid] = e;
        }
    } else if (lane == 0) sgid[wid] = -1;
    __syncthreads();
    if (threadIdx.x == 0) {
        int cur = -2;
        float a = 0.f;
        for (int i = 0; i < 32; i++) {
            int g = sgid[i];
            if (g < 0) continue;
            if (g != cur) { if (cur >= 0) atomicAdd(&gsum[cur], a); cur = g; a = 0.f; }
            a += se[i];
        }
        if (cur >= 0) atomicAdd(&gsum[cur], a);
    }
}

__global__ void k_gap_pool(const float* __restrict__ M, const int* __restrict__ gid,
                           const float* __restrict__ e, const float* __restrict__ gsum,
                           float* pool, int n) {
    int w = (blockIdx.x * blockDim.x + threadIdx.x) >> 5;
    int lane = threadIdx.x & 31;
    if (w >= n) return;
    int b = gid[w];
    float wt = e[w] / gsum[b];
    const float* row = M + (size_t)w * HD;
#pragma unroll
    for (int j = lane; j < HD; j += 32) atomicAdd(&pool[b * HD + j], wt * row[j]);
}

__global__ void __launch_bounds__(1024) k_gapdots(
    const float* __restrict__ M1, const float* __restrict__ M2, const float* __restrict__ w1,
    const float* __restrict__ b1, const float* __restrict__ w2, const float* __restrict__ b2,
    const float* __restrict__ qc, const int* __restrict__ gid, float* acc, int n) {
    __shared__ int sgid[32];
    __shared__ float sv[32][4];
    int wid = threadIdx.x >> 5, lane = threadIdx.x & 31;
    int node = blockIdx.x * 32 + wid;
    if (node < n) {
        const float* r1 = M1 + (size_t)node * HD;
        const float* r2 = M2 + (size_t)node * HD;
        float s1 = 0.f, q1 = 0.f, s2 = 0.f, q2 = 0.f;
#pragma unroll
        for (int j = lane; j < HD; j += 32) {
            float a = r1[j], bb = r2[j], qv = qc[j];
            s1 = fmaf(a, w1[j], s1);
            q1 = fmaf(a, qv, q1);
            s2 = fmaf(bb, w2[j], s2);
            q2 = fmaf(bb, qv, q2);
        }
#pragma unroll
        for (int o = 16; o; o >>= 1) {
            s1 += __shfl_down_sync(0xffffffffu, s1, o);
            q1 += __shfl_down_sync(0xffffffffu, q1, o);
            s2 += __shfl_down_sync(0xffffffffu, s2, o);
            q2 += __shfl_down_sync(0xffffffffu, q2, o);
        }
        if (lane == 0) {
            float e1 = expf(s1 + b1[0]), e2 = expf(s2 + b2[0]);
            sgid[wid] = gid[node];
            sv[wid][0] = e1; sv[wid][1] = e1 * q1; sv[wid][2] = e2; sv[wid][3] = e2 * q2;
        }
    } else if (lane == 0) sgid[wid] = -1;
    __syncthreads();
    if (threadIdx.x < 4) {
        int comp = threadIdx.x;
        int cur = -2;
        float a = 0.f;
        for (int i = 0; i < 32; i++) {
            int g = sgid[i];
            if (g < 0) continue;
            if (g != cur) { if (cur >= 0) atomicAdd(&acc[cur * 4 + comp], a); cur = g; a = 0.f; }
            a += sv[i][comp];
        }
        if (cur >= 0) atomicAdd(&acc[cur * 4 + comp], a);
    }
}

__global__ void k_comb2(const float* __restrict__ acc, float* aab) {
    int b = threadIdx.x;
    if (b < BB) {
        float d1 = acc[b * 4 + 1] / acc[b * 4 + 0];
        float d2 = acc[b * 4 + 3] / acc[b * 4 + 2];
        float mm = fmaxf(d1, d2);
        float e1 = expf(d1 - mm), e2 = expf(d2 - mm);
        float ss = e1 + e2;
        aab[2 * b] = e1 / ss;
        aab[2 * b + 1] = e2 / ss;
    }
}

__global__ void k_eler(const float* __restrict__ feat, const float* __restrict__ Q,
                       const int* __restrict__ gid, float* el, float* er, int n) {
    int idx = blockIdx.x * blockDim.x + threadIdx.x;
    if (idx >= n * HH) return;
    int i = idx >> 3, h = idx & 7;
    const float* f = feat + (size_t)i * HD + h * 16;
    const float* q = Q + (size_t)gid[i] * HD2 + h * 32;
    float sl = 0.f, sr = 0.f;
#pragma unroll
    for (int c = 0; c < 16; c++) {
        float fv = f[c];
        sl = fmaf(fv, q[c], sl);
        sr = fmaf(fv, q[16 + c], sr);
    }
    el[idx] = sl;
    er[idx] = sr;
}

// ---------------- CSR build ----------------
__global__ void k_hist(const int* __restrict__ dst, int* deg, int E) {
    int e = blockIdx.x * blockDim.x + threadIdx.x;
    if (e < E) atomicAdd(&deg[dst[e]], 1);
}
__global__ void k_scan1(const int* __restrict__ deg, int* out, int* bsum, int n) {
    __shared__ int sh[512];
    int base = blockIdx.x * 512, t = threadIdx.x;
    int v0 = (base + t < n) ? deg[base + t] : 0;
    int v1 = (base + 256 + t < n) ? deg[base + 256 + t] : 0;
    sh[t] = v0; sh[t + 256] = v1;
    __syncthreads();
    for (int off = 1; off < 512; off <<= 1) {
        int i0 = t, i1 = t + 256;
        int n0 = sh[i0] + ((i0 >= off) ? sh[i0 - off] : 0);
        int n1 = sh[i1] + ((i1 >= off) ? sh[i1 - off] : 0);
        __syncthreads();
        sh[i0] = n0; sh[i1] = n1;
        __syncthreads();
    }
    if (base + t < n) out[base + t] = sh[t] - v0;
    if (base + 256 + t < n) out[base + 256 + t] = sh[t + 256] - v1;
    if (t == 0) bsum[blockIdx.x] = sh[511];
}
__global__ void k_scan2(int* bsum, int nb) {
    __shared__ int sh[256];
    int t = threadIdx.x;
    int v = (t < nb) ? bsum[t] : 0;
    sh[t] = v;
    __syncthreads();
    for (int off = 1; off < 256; off <<= 1) {
        int x = sh[t] + ((t >= off) ? sh[t - off] : 0);
        __syncthreads();
        sh[t] = x;
        __syncthreads();
    }
    if (t < nb) bsum[t] = sh[t] - v;
}
__global__ void k_scan3(int* coff, int* cursor, const int* __restrict__ bsum, int n) {
    int i = blockIdx.x * blockDim.x + threadIdx.x;
    if (i < n) {
        int v = coff[i] + bsum[i >> 9];
        coff[i] = v;
        cursor[i] = v;
    }
}
__global__ void k_scatter(const int* __restrict__ dst, int* cursor, int* eid, int E) {
    int e = blockIdx.x * blockDim.x + threadIdx.x;
    if (e < E) {
        int p = atomicAdd(&cursor[dst[e]], 1);
        eid[p] = e;
    }
}

// ---------------- single-pass edge softmax + aggregation (warp per node) ----------------
__global__ void k_node_agg(const int* __restrict__ src, const int* __restrict__ eid,
                           const int* __restrict__ coff, const int* __restrict__ deg,
                           const float* __restrict__ el, const float* __restrict__ er,
                           const float* __restrict__ ft, float* agg, float* s, int n) {
    int w = (blockIdx.x * blockDim.x + threadIdx.x) >> 5;
    int lane = threadIdx.x & 31;
    if (w >= n) return;
    int h = lane >> 2;
    int off = coff[w], d = deg[w];
    float erv = er[w * HH + h];
    float wsum = 0.f;
    float4 acc = make_float4(0.f, 0.f, 0.f, 0.f);
    for (int j = 0; j < d; j++) {
        int sn = src[eid[off + j]];
        float v = el[sn * HH + h] + erv;
        v = v > 0.f ? v : NEG_SLOPE * v;
        float wt = expf(v);
        wsum += wt;
        float4 fv = *(const float4*)(ft + (size_t)sn * HD + lane * 4);
        acc.x = fmaf(wt, fv.x, acc.x);
        acc.y = fmaf(wt, fv.y, acc.y);
        acc.z = fmaf(wt, fv.z, acc.z);
        acc.w = fmaf(wt, fv.w, acc.w);
    }
    float inv = wsum > 0.f ? 1.f / wsum : 0.f;
    acc.x *= inv; acc.y *= inv; acc.z *= inv; acc.w *= inv;
    *(float4*)(agg + (size_t)w * HD + lane * 4) = acc;
    if ((lane & 3) == 0) s[w * HH + h] = wsum;
}

// ---------------- batchnorm finalize + small stats ----------------
__global__ void k_bnred(const float* __restrict__ Y, int n, int C, double* st) {
    int c = threadIdx.x;
    double s = 0.0, s2 = 0.0;
    for (int r = blockIdx.x; r < n; r += gridDim.x) {
        float v = Y[(size_t)r * C + c];
        s += v;
        s2 += (double)v * v;
    }
    atomicAdd(&st[c], s);
    atomicAdd(&st[256 + c], s2);
}
__global__ void k_bnfin(const double* st, int n, float* mu, float* rstd) {
    int c = threadIdx.x;
    double m = st[c] / n;
    double v = st[256 + c] / n - m * m;
    if (v < 0.0) v = 0.0;
    mu[c] = (float)m;
    rstd[c] = (float)(1.0 / sqrt(v + 1e-5));
}
__global__ void k_bnelu(const float* __restrict__ Y, const float* __restrict__ mu,
                        const float* __restrict__ rstd, float* out, long long total, int C) {
    long long i = (long long)blockIdx.x * blockDim.x + threadIdx.x;
    if (i < total) {
        int c = (int)(i % C);
        out[i] = eluf((Y[i] - mu[c]) * rstd[c]);
    }
}
__global__ void k_final(const float* __restrict__ hlast, const float* __restrict__ Y,
                        const float* __restrict__ mu, const float* __restrict__ rstd, float* out,
                        long long total) {
    long long i = (long long)blockIdx.x * blockDim.x + threadIdx.x;
    if (i < total) {
        int c = (int)(i & (HD - 1));
        out[i] = hlast[i] + eluf((Y[i] - mu[c]) * rstd[c]);
    }
}

// ---------------- loss ----------------
__global__ void k_pesum(const int* __restrict__ ids, int nids, const int* __restrict__ src,
                        const int* __restrict__ dst, const float* __restrict__ el,
                        const float* __restrict__ er, const float* __restrict__ s, float* out8) {
    float acc[HH];
#pragma unroll
    for (int h = 0; h < HH; h++) acc[h] = 0.f;
    for (int i = blockIdx.x * blockDim.x + threadIdx.x; i < nids; i += gridDim.x * blockDim.x) {
        int e = ids[i];
        int se = src[e] * HH, de = dst[e] * HH;
#pragma unroll
        for (int h = 0; h < HH; h++) {
            float v = el[se + h] + er[de + h];
            v = v > 0.f ? v : NEG_SLOPE * v;
            acc[h] += expf(v) / s[de + h];
        }
    }
#pragma unroll
    for (int h = 0; h < HH; h++)
#pragma unroll
        for (int o = 16; o; o >>= 1) acc[h] += __shfl_down_sync(0xffffffffu, acc[h], o);
    if ((threadIdx.x & 31) == 0)
#pragma unroll
        for (int h = 0; h < HH; h++) atomicAdd(&out8[h], acc[h]);
}
__global__ void k_loss(const float* pe, const float* de, const int* lenp, float* out) {
    float sum = 0.f;
#pragma unroll
    for (int h = 0; h < HH; h++) sum += pe[h] - de[h];
    out[0] = -sum / (8.0f * (float)lenp[0]);
}

// ---------------- host ----------------
static inline int cdiv(long long a, long long b) { return (int)((a + b - 1) / b); }

extern "C" void kernel_launch(void* const* d_in, const int* in_sizes, int n_in, void* d_out,
                              int out_size) {
    const float* h_da_last = (const float*)d_in[0];
    const float* h_q_last  = (const float*)d_in[1];
    const float* h_da_0    = (const float*)d_in[2];
    const float* h_q_0     = (const float*)d_in[3];
    const float* W_L       = (const float*)d_in[4];
    const float* b_L       = (const float*)d_in[5];
    const float* gateq_W   = (const float*)d_in[6];
    const float* gateq_b   = (const float*)d_in[7];
    const float* gate1_W   = (const float*)d_in[8];
    const float* gate1_b   = (const float*)d_in[9];
    const float* gate2_W   = (const float*)d_in[10];
    const float* gate2_b   = (const float*)d_in[11];
    const float* Q_comb    = (const float*)d_in[12];
    const float* Qf_W1     = (const float*)d_in[13];
    const float* Qf_b1     = (const float*)d_in[14];
    const float* Qf_W2     = (const float*)d_in[15];
    const float* Qf_b2     = (const float*)d_in[16];
    const float* end_W1    = (const float*)d_in[17];
    const float* end_b1    = (const float*)d_in[18];
    const float* end_W2    = (const float*)d_in[19];
    const float* end_b2    = (const float*)d_in[20];
    const int* src_da = (const int*)d_in[21];
    const int* dst_da = (const int*)d_in[22];
    const int* src_q  = (const int*)d_in[23];
    const int* dst_q  = (const int*)d_in[24];
    const int* gid_da = (const int*)d_in[25];
    const int* gid_q  = (const int*)d_in[26];
    const int* PEid   = (const int*)d_in[27];
    const int* DEid   = (const int*)d_in[28];
    const int* lenp   = (const int*)d_in[29];
    int nPE = in_sizes[27], nDE = in_sizes[28];

    float* out = (float*)d_out;
    float* out_da = out;
    float* out_q = out + (long long)NDA * HD;
    float* out_loss = out + (long long)NDA * HD + (long long)NQ * HD;

    float *feat, *featq, *ft, *agg, *y1, *y2, *el, *er, *ss, *eb;
    float *glq, *t1, *t2, *Qb, *gsumq, *accq, *accda, *aabq, *aabda, *mu, *rstd, *pe, *de;
    double* dstat;
    int *deg, *coff, *cursor, *eid, *bsum, *degq, *coffq, *cursorq, *eidq, *bsumq;
    cudaGetSymbolAddress((void**)&feat, g_feat);
    cudaGetSymbolAddress((void**)&featq, g_featq);
    cudaGetSymbolAddress((void**)&ft, g_ft);
    cudaGetSymbolAddress((void**)&agg, g_agg);
    cudaGetSymbolAddress((void**)&y1, g_y1);
    cudaGetSymbolAddress((void**)&y2, g_y2);
    cudaGetSymbolAddress((void**)&el, g_el);
    cudaGetSymbolAddress((void**)&er, g_er);
    cudaGetSymbolAddress((void**)&ss, g_s);
    cudaGetSymbolAddress((void**)&eb, g_eb);
    cudaGetSymbolAddress((void**)&glq, g_glq);
    cudaGetSymbolAddress((void**)&t1, g_t1);
    cudaGetSymbolAddress((void**)&t2, g_t2);
    cudaGetSymbolAddress((void**)&Qb, g_Q);
    cudaGetSymbolAddress((void**)&gsumq, g_gsumq);
    cudaGetSymbolAddress((void**)&accq, g_accq);
    cudaGetSymbolAddress((void**)&accda, g_accda);
    cudaGetSymbolAddress((void**)&aabq, g_aabq);
    cudaGetSymbolAddress((void**)&aabda, g_aabda);
    cudaGetSymbolAddress((void**)&mu, g_mu);
    cudaGetSymbolAddress((void**)&rstd, g_rstd);
    cudaGetSymbolAddress((void**)&pe, g_pe);
    cudaGetSymbolAddress((void**)&de, g_de);
    cudaGetSymbolAddress((void**)&dstat, g_dstat);
    cudaGetSymbolAddress((void**)&deg, g_deg);
    cudaGetSymbolAddress((void**)&coff, g_coff);
    cudaGetSymbolAddress((void**)&cursor, g_cursor);
    cudaGetSymbolAddress((void**)&eid, g_eid);
    cudaGetSymbolAddress((void**)&bsum, g_bsum);
    cudaGetSymbolAddress((void**)&degq, g_degq);
    cudaGetSymbolAddress((void**)&coffq, g_coffq);
    cudaGetSymbolAddress((void**)&cursorq, g_cursorq);
    cudaGetSymbolAddress((void**)&eidq, g_eidq);
    cudaGetSymbolAddress((void**)&bsumq, g_bsumq);

    // 1: zero everything replay-sensitive
    k_zero0<<<cdiv(NDA, 256), 256>>>(glq, gsumq, accq, accda, pe, de, deg, degq);
    // 2-3: gateq pooling (q graph)
    k_gapq<<<cdiv(NQ, 32), 1024>>>(h_q_last, gateq_W, gateq_b, gid_q, eb, gsumq, NQ);
    k_gap_pool<<<cdiv((long long)NQ * 32, 256), 256>>>(h_q_last, gid_q, eb, gsumq, glq, NQ);
    // 4: da feat GEMM (input-only; also the ncu sample target)
    k_gemm_tf32<0, 0><<<dim3(1, cdiv(NDA, 128)), 256>>>(h_da_last, nullptr, nullptr, nullptr, W_L,
                                                        b_L, nullptr, nullptr, feat, nullptr, NDA,
                                                        128, 128);
    // 5: da gate dots
    k_gapdots<<<cdiv(NDA, 32), 1024>>>(h_da_0, h_da_last, gate1_W, gate1_b, gate2_W, gate2_b,
                                       Q_comb, gid_da, accda, NDA);
    // 6: da degree histogram
    k_hist<<<cdiv(EDA, 256), 256>>>(dst_da, deg, EDA);
    // 7: q feat GEMM
    k_gemm_tf32<0, 0><<<dim3(1, cdiv(NQ, 128)), 256>>>(h_q_last, nullptr, nullptr, nullptr, W_L,
                                                       b_L, nullptr, nullptr, featq, nullptr, NQ,
                                                       128, 128);
    // 8: q gate dots
    k_gapdots<<<cdiv(NQ, 32), 1024>>>(h_q_0, h_q_last, gate1_W, gate1_b, gate2_W, gate2_b, Q_comb,
                                      gid_q, accq, NQ);
    // CSR builds
    k_scan1<<<cdiv(NDA, 512), 256>>>(deg, coff, bsum, NDA);
    k_scan2<<<1, 256>>>(bsum, cdiv(NDA, 512));
    k_scan3<<<cdiv(NDA, 256), 256>>>(coff, cursor, bsum, NDA);
    k_scatter<<<cdiv(EDA, 256), 256>>>(dst_da, cursor, eid, EDA);
    k_hist<<<cdiv(EQ, 256), 256>>>(dst_q, degq, EQ);
    k_scan1<<<cdiv(NQ, 512), 256>>>(degq, coffq, bsumq, NQ);
    k_scan2<<<1, 256>>>(bsumq, cdiv(NQ, 512));
    k_scan3<<<cdiv(NQ, 256), 256>>>(coffq, cursorq, bsumq, NQ);
    k_scatter<<<cdiv(EQ, 256), 256>>>(dst_q, cursorq, eidq, EQ);
    k_comb2<<<1, BB>>>(accq, aabq);
    k_comb2<<<1, BB>>>(accda, aabda);

    // Qf FNN -> Qb
    k_filld<<<2, 256>>>(dstat, 512);
    k_gemm_tf32<0, 1><<<dim3(2, 1), 256>>>(glq, nullptr, nullptr, nullptr, Qf_W1, Qf_b1, nullptr,
                                           nullptr, t1, dstat, BB, 128, 256);
    k_bnfin<<<1, 256>>>(dstat, BB, mu, rstd);
    k_filld<<<2, 256>>>(dstat, 512);
    k_gemm_tf32<2, 1><<<dim3(2, 1), 256>>>(t1, nullptr, nullptr, nullptr, Qf_W2, Qf_b2, mu, rstd,
                                           t2, dstat, BB, 256, 256);
    k_bnfin<<<1, 256>>>(dstat, BB, mu, rstd);
    k_bnelu<<<cdiv((long long)BB * 256, 256), 256>>>(t2, mu, rstd, Qb, (long long)BB * 256, 256);

    // ---- q branch ----
    k_gemm_tf32<1, 0><<<dim3(1, cdiv(NQ, 128)), 256>>>(h_q_0, h_q_last, aabq, gid_q, W_L, b_L,
                                                       nullptr, nullptr, ft, nullptr, NQ, 128, 128);
    k_eler<<<cdiv((long long)NQ * HH, 256), 256>>>(featq, Qb, gid_q, el, er, NQ);
    k_node_agg<<<cdiv((long long)NQ * 32, 256), 256>>>(src_q, eidq, coffq, degq, el, er, ft, agg,
                                                       ss, NQ);
    k_filld<<<2, 256>>>(dstat, 512);
    k_gemm_tf32<0, 1><<<dim3(2, cdiv(NQ, 128)), 256>>>(agg, nullptr, nullptr, nullptr, end_W1,
                                                       end_b1, nullptr, nullptr, y1, dstat, NQ,
                                                       128, 256);
    k_bnfin<<<1, 256>>>(dstat, NQ, mu, rstd);
    k_filld<<<2, 256>>>(dstat, 512);
    k_gemm_tf32<2, 1><<<dim3(1, cdiv(NQ, 128)), 256>>>(y1, nullptr, nullptr, nullptr, end_W2,
                                                       end_b2, mu, rstd, y2, dstat, NQ, 256, 128);
    k_bnfin<<<1, 128>>>(dstat, NQ, mu, rstd);
    k_final<<<cdiv((long long)NQ * HD, 256), 256>>>(h_q_last, y2, mu, rstd, out_q,
                                                    (long long)NQ * HD);

    // ---- da branch ----
    k_gemm_tf32<1, 0><<<dim3(1, cdiv(NDA, 128)), 256>>>(h_da_0, h_da_last, aabda, gid_da, W_L, b_L,
                                                        nullptr, nullptr, ft, nullptr, NDA, 128,
                                                        128);
    k_eler<<<cdiv((long long)NDA * HH, 256), 256>>>(feat, Qb, gid_da, el, er, NDA);
    k_node_agg<<<cdiv((long long)NDA * 32, 256), 256>>>(src_da, eid, coff, deg, el, er, ft, agg,
                                                        ss, NDA);
    k_filld<<<2, 256>>>(dstat, 512);
    k_gemm_tf32<0, 1><<<dim3(2, cdiv(NDA, 128)), 256>>>(agg, nullptr, nullptr, nullptr, end_W1,
                                                        end_b1, nullptr, nullptr, y1, dstat, NDA,
                                                        128, 256);
    k_bnfin<<<1, 256>>>(dstat, NDA, mu, rstd);
    k_filld<<<2, 256>>>(dstat, 512);
    k_gemm_tf32<2, 1><<<dim3(1, cdiv(NDA, 128)), 256>>>(y1, nullptr, nullptr, nullptr, end_W2,
                                                        end_b2, mu, rstd, y2, dstat, NDA, 256,
                                                        128);
    k_bnfin<<<1, 128>>>(dstat, NDA, mu, rstd);
    k_final<<<cdiv((long long)NDA * HD, 256), 256>>>(h_da_last, y2, mu, rstd, out_da,
                                                     (long long)NDA * HD);

    // ---- loss ----
    k_pesum<<<256, 256>>>(PEid, nPE, src_da, dst_da, el, er, ss, pe);
    k_pesum<<<256, 256>>>(DEid, nDE, src_da, dst_da, el, er, ss, de);
    k_loss<<<1, 1>>>(pe, de, lenp, out_loss);
}

// round 6
// speedup vs baseline: 3.0126x; 1.0520x over previous
#include <cuda_runtime.h>
#include <math.h>
#include <stdint.h>

#define NDA 100000
#define NQ  20000
#define EDA 1000000
#define EQ  200000
#define BB  64
#define HH  8
#define HD  128
#define HD2 256
#define NEG_SLOPE 2.0f

// ---------------- scratch ----------------
__device__ float g_feat[(size_t)NDA * HD];
__device__ float g_featq[(size_t)NQ * HD];
__device__ float g_ft[(size_t)NDA * HD];
__device__ float g_fh[(size_t)NDA * HD];
__device__ float g_agg[(size_t)NDA * HD];
__device__ float g_y1[(size_t)NDA * HD2];
__device__ float g_y1b[(size_t)NDA * HD2];
__device__ float g_y2[(size_t)NDA * HD];
__device__ float g_el[NDA * HH];
__device__ float g_er[NDA * HH];
__device__ float g_s[NDA * HH];
__device__ float g_eb[NQ];
__device__ int   g_deg[NDA];
__device__ int   g_coff[NDA];
__device__ int   g_cursor[NDA];
__device__ int   g_eid[EDA];
__device__ int   g_bsum[256];
__device__ int   g_degq[NQ];
__device__ int   g_coffq[NQ];
__device__ int   g_cursorq[NQ];
__device__ int   g_eidq[EQ];
__device__ int   g_bsumq[256];
__device__ float g_glq[BB * HD];
__device__ float g_t1[BB * HD2];
__device__ float g_t1b[BB * HD2];
__device__ float g_t2[BB * HD2];
__device__ float g_Q[BB * HD2];
__device__ float g_gsumq[BB];
__device__ float g_accq[BB * 4];
__device__ float g_accda[BB * 4];
__device__ float g_aabq[BB * 2];
__device__ float g_aabda[BB * 2];
__device__ double g_dstat[512];
__device__ float g_mu[HD2];
__device__ float g_rstd[HD2];
__device__ float g_pe[HH];
__device__ float g_de[HH];

__device__ __forceinline__ float eluf(float x) { return x > 0.f ? x : expm1f(x); }

__device__ __forceinline__ uint32_t smem_u32(const void* p) {
    uint32_t a;
    asm("{ .reg .u64 t; cvta.to.shared.u64 t, %1; cvt.u32.u64 %0, t; }" : "=r"(a) : "l"(p));
    return a;
}
__device__ __forceinline__ uint32_t f2tf(float x) {
    uint32_t r;
    asm("cvt.rna.tf32.f32 %0, %1;" : "=r"(r) : "f"(x));
    return r;
}
__device__ __forceinline__ void mma8(float* d, const uint32_t* a, const uint32_t* b) {
    asm volatile(
        "mma.sync.aligned.m16n8k8.row.col.f32.tf32.tf32.f32 "
        "{%0,%1,%2,%3}, {%4,%5,%6,%7}, {%8,%9}, {%0,%1,%2,%3};\n"
        : "+f"(d[0]), "+f"(d[1]), "+f"(d[2]), "+f"(d[3])
        : "r"(a[0]), "r"(a[1]), "r"(a[2]), "r"(a[3]), "r"(b[0]), "r"(b[1]));
}

// ---------------- pipelined TF32 GEMM: C[n x NC] = A[n x K] @ W[K x NC] + bias ----------------
// dynamic smem: A stages 2 x 128x36 floats, W stages 2 x 32x132 floats
#define AOFF(buf) ((buf) * 4608)
#define WOFF(buf) (9216 + (buf) * 4224)
#define SMEM_GA ((9216 + 2 * 4224) * 4)

__device__ __forceinline__ void stage_issue(uint32_t sb, int buf, const float* __restrict__ A,
                                            const float* __restrict__ W, int rowBase, int colBase,
                                            int k0, int n, int K, int NC, int tid) {
    uint32_t abase = sb + AOFF(buf) * 4;
    uint32_t wbase = sb + WOFF(buf) * 4;
#pragma unroll
    for (int q = 0; q < 4; q++) {
        int id = tid + q * 256;
        int r = id >> 3, kq = id & 7;
        int grow = rowBase + r;
        const float* src = A + (size_t)grow * K + k0 + kq * 4;
        uint32_t dst = abase + (r * 36 + kq * 4) * 4;
        int sz = grow < n ? 16 : 0;
        asm volatile("cp.async.ca.shared.global [%0], [%1], 16, %2;" ::"r"(dst), "l"(src), "r"(sz)
                     : "memory");
    }
#pragma unroll
    for (int q = 0; q < 4; q++) {
        int id = tid + q * 256;
        int kk = id >> 5, nq = id & 31;
        const float* src = W + (size_t)(k0 + kk) * NC + colBase + nq * 4;
        uint32_t dst = wbase + (kk * 132 + nq * 4) * 4;
        asm volatile("cp.async.ca.shared.global [%0], [%1], 16;" ::"r"(dst), "l"(src) : "memory");
    }
    asm volatile("cp.async.commit_group;" ::: "memory");
}

template <int STAT>
__global__ void __launch_bounds__(256, 2) k_gemm_async(
    const float* __restrict__ A, const float* __restrict__ W, const float* __restrict__ bias,
    float* __restrict__ C, double* dstat, int n, int K, int NC) {
    extern __shared__ float smf[];
    __shared__ float sstat[256];
    const uint32_t sb = smem_u32(smf);
    const int tid = threadIdx.x;
    const int lane = tid & 31;
    const int wid = tid >> 5;
    const int warp_m = wid >> 2;
    const int warp_n = wid & 3;
    const int rowBase = blockIdx.y * 128;
    const int colBase = blockIdx.x * 128;
    const int g4 = lane >> 2;
    const int t4 = lane & 3;

    if (STAT && tid < 256) sstat[tid] = 0.f;

    stage_issue(sb, 0, A, W, rowBase, colBase, 0, n, K, NC, tid);
    stage_issue(sb, 1, A, W, rowBase, colBase, 32, n, K, NC, tid);

    float acc[4][4][4];
#pragma unroll
    for (int mi = 0; mi < 4; mi++)
#pragma unroll
        for (int ni = 0; ni < 4; ni++)
#pragma unroll
            for (int r = 0; r < 4; r++) acc[mi][ni][r] = 0.f;

    const int nk = K >> 5;
    for (int i = 0; i < nk; i++) {
        int p = i & 1;
        if (i + 1 < nk)
            asm volatile("cp.async.wait_group 1;" ::: "memory");
        else
            asm volatile("cp.async.wait_group 0;" ::: "memory");
        __syncthreads();
        const float* Af = smf + AOFF(p);
        const float* Wf = smf + WOFF(p);
#pragma unroll
        for (int ks = 0; ks < 4; ks++) {
            int kk = ks * 8;
            uint32_t a[4][4];
#pragma unroll
            for (int mi = 0; mi < 4; mi++) {
                int r = warp_m * 64 + mi * 16 + g4;
                a[mi][0] = f2tf(Af[r * 36 + kk + t4]);
                a[mi][1] = f2tf(Af[(r + 8) * 36 + kk + t4]);
                a[mi][2] = f2tf(Af[r * 36 + kk + t4 + 4]);
                a[mi][3] = f2tf(Af[(r + 8) * 36 + kk + t4 + 4]);
            }
            uint32_t b[4][2];
#pragma unroll
            for (int ni = 0; ni < 4; ni++) {
                int c = warp_n * 32 + ni * 8 + g4;
                b[ni][0] = f2tf(Wf[(kk + t4) * 132 + c]);
                b[ni][1] = f2tf(Wf[(kk + t4 + 4) * 132 + c]);
            }
#pragma unroll
            for (int mi = 0; mi < 4; mi++)
#pragma unroll
                for (int ni = 0; ni < 4; ni++) mma8(acc[mi][ni], a[mi], b[ni]);
        }
        __syncthreads();
        if (i + 2 < nk) stage_issue(sb, p, A, W, rowBase, colBase, (i + 2) * 32, n, K, NC, tid);
    }

    float cs[8], cq[8];
#pragma unroll
    for (int i = 0; i < 8; i++) { cs[i] = 0.f; cq[i] = 0.f; }

#pragma unroll
    for (int mi = 0; mi < 4; mi++) {
        int r0 = rowBase + warp_m * 64 + mi * 16 + g4;
        int r1 = r0 + 8;
#pragma unroll
        for (int ni = 0; ni < 4; ni++) {
            int c = colBase + warp_n * 32 + ni * 8 + t4 * 2;
            float b0 = bias[c], b1 = bias[c + 1];
            if (r0 < n) {
                float v0 = acc[mi][ni][0] + b0, v1 = acc[mi][ni][1] + b1;
                C[(size_t)r0 * NC + c] = v0;
                C[(size_t)r0 * NC + c + 1] = v1;
                if (STAT) {
                    cs[ni * 2] += v0; cq[ni * 2] += v0 * v0;
                    cs[ni * 2 + 1] += v1; cq[ni * 2 + 1] += v1 * v1;
                }
            }
            if (r1 < n) {
                float v2 = acc[mi][ni][2] + b0, v3 = acc[mi][ni][3] + b1;
                C[(size_t)r1 * NC + c] = v2;
                C[(size_t)r1 * NC + c + 1] = v3;
                if (STAT) {
                    cs[ni * 2] += v2; cq[ni * 2] += v2 * v2;
                    cs[ni * 2 + 1] += v3; cq[ni * 2 + 1] += v3 * v3;
                }
            }
        }
    }
    if (STAT) {
#pragma unroll
        for (int i = 0; i < 8; i++) {
            float s = cs[i], q = cq[i];
            s += __shfl_down_sync(0xffffffffu, s, 16);
            q += __shfl_down_sync(0xffffffffu, q, 16);
            s += __shfl_down_sync(0xffffffffu, s, 8);
            q += __shfl_down_sync(0xffffffffu, q, 8);
            s += __shfl_down_sync(0xffffffffu, s, 4);
            q += __shfl_down_sync(0xffffffffu, q, 4);
            if (g4 == 0) {
                int c = warp_n * 32 + (i >> 1) * 8 + t4 * 2 + (i & 1);
                atomicAdd(&sstat[c], s);
                atomicAdd(&sstat[128 + c], q);
            }
        }
        __syncthreads();
        if (tid < 128) {
            atomicAdd(&dstat[colBase + tid], (double)sstat[tid]);
            atomicAdd(&dstat[256 + colBase + tid], (double)sstat[128 + tid]);
        }
    }
}

// ---------------- elementwise blend: fh = a0[gid]*h0 + a1[gid]*h_last ----------------
__global__ void k_mix(const float* __restrict__ h0, const float* __restrict__ hlast,
                      const float* __restrict__ aab, const int* __restrict__ gid,
                      float* __restrict__ out, int n) {
    int i = blockIdx.x * blockDim.x + threadIdx.x;
    if (i >= n * 32) return;
    int row = i >> 5;
    int g = gid[row];
    float c0 = aab[2 * g], c1 = aab[2 * g + 1];
    float4 a = ((const float4*)h0)[i];
    float4 b = ((const float4*)hlast)[i];
    float4 o;
    o.x = c0 * a.x + c1 * b.x;
    o.y = c0 * a.y + c1 * b.y;
    o.z = c0 * a.z + c1 * b.z;
    o.w = c0 * a.w + c1 * b.w;
    ((float4*)out)[i] = o;
}

// ---------------- fills ----------------
__global__ void k_zero0(float* glq, float* gsumq, float* accq, float* accda, float* pe, float* de,
                        int* degda, int* degq) {
    int i = blockIdx.x * blockDim.x + threadIdx.x;
    if (i < NDA) degda[i] = 0;
    if (i < NQ) degq[i] = 0;
    if (i < BB * HD) glq[i] = 0.f;
    if (i < BB) gsumq[i] = 0.f;
    if (i < BB * 4) { accq[i] = 0.f; accda[i] = 0.f; }
    if (i < HH) { pe[i] = 0.f; de[i] = 0.f; }
}
__global__ void k_filld(double* p, int n) {
    int i = blockIdx.x * blockDim.x + threadIdx.x;
    if (i < n) p[i] = 0.0;
}

// ---------------- fused gate kernels ----------------
__global__ void __launch_bounds__(1024) k_gapq(const float* __restrict__ M,
                                               const float* __restrict__ w,
                                               const float* __restrict__ b,
                                               const int* __restrict__ gid, float* ebuf,
                                               float* gsum, int n) {
    __shared__ int sgid[32];
    __shared__ float se[32];
    int wid = threadIdx.x >> 5, lane = threadIdx.x & 31;
    int node = blockIdx.x * 32 + wid;
    if (node < n) {
        const float* row = M + (size_t)node * HD;
        float s = 0.f;
#pragma unroll
        for (int j = lane; j < HD; j += 32) s = fmaf(row[j], w[j], s);
#pragma unroll
        for (int o = 16; o; o >>= 1) s += __shfl_down_sync(0xffffffffu, s, o);
        if (lane == 0) {
            float e = expf(s + b[0]);
            ebuf[node] = e;
            sgid[wid] = gid[node];
            se[wid] = e;
        }
    } else if (lane == 0) sgid[wid] = -1;
    __syncthreads();
    if (threadIdx.x == 0) {
        int cur = -2;
        float a = 0.f;
        for (int i = 0; i < 32; i++) {
            int g = sgid[i];
            if (g < 0) continue;
            if (g != cur) { if (cur >= 0) atomicAdd(&gsum[cur], a); cur = g; a = 0.f; }
            a += se[i];
        }
        if (cur >= 0) atomicAdd(&gsum[cur], a);
    }
}

__global__ void k_gap_pool(const float* __restrict__ M, const int* __restrict__ gid,
                           const float* __restrict__ e, const float* __restrict__ gsum,
                           float* pool, int n) {
    int w = (blockIdx.x * blockDim.x + threadIdx.x) >> 5;
    int lane = threadIdx.x & 31;
    if (w >= n) return;
    int b = gid[w];
    float wt = e[w] / gsum[b];
    const float* row = M + (size_t)w * HD;
#pragma unroll
    for (int j = lane; j < HD; j += 32) atomicAdd(&pool[b * HD + j], wt * row[j]);
}

__global__ void __launch_bounds__(1024) k_gapdots(
    const float* __restrict__ M1, const float* __restrict__ M2, const float* __restrict__ w1,
    const float* __restrict__ b1, const float* __restrict__ w2, const float* __restrict__ b2,
    const float* __restrict__ qc, const int* __restrict__ gid, float* acc, int n) {
    __shared__ int sgid[32];
    __shared__ float sv[32][4];
    int wid = threadIdx.x >> 5, lane = threadIdx.x & 31;
    int node = blockIdx.x * 32 + wid;
    if (node < n) {
        const float* r1 = M1 + (size_t)node * HD;
        const float* r2 = M2 + (size_t)node * HD;
        float s1 = 0.f, q1 = 0.f, s2 = 0.f, q2 = 0.f;
#pragma unroll
        for (int j = lane; j < HD; j += 32) {
            float a = r1[j], bb = r2[j], qv = qc[j];
            s1 = fmaf(a, w1[j], s1);
            q1 = fmaf(a, qv, q1);
            s2 = fmaf(bb, w2[j], s2);
            q2 = fmaf(bb, qv, q2);
        }
#pragma unroll
        for (int o = 16; o; o >>= 1) {
            s1 += __shfl_down_sync(0xffffffffu, s1, o);
            q1 += __shfl_down_sync(0xffffffffu, q1, o);
            s2 += __shfl_down_sync(0xffffffffu, s2, o);
            q2 += __shfl_down_sync(0xffffffffu, q2, o);
        }
        if (lane == 0) {
            float e1 = expf(s1 + b1[0]), e2 = expf(s2 + b2[0]);
            sgid[wid] = gid[node];
            sv[wid][0] = e1; sv[wid][1] = e1 * q1; sv[wid][2] = e2; sv[wid][3] = e2 * q2;
        }
    } else if (lane == 0) sgid[wid] = -1;
    __syncthreads();
    if (threadIdx.x < 4) {
        int comp = threadIdx.x;
        int cur = -2;
        float a = 0.f;
        for (int i = 0; i < 32; i++) {
            int g = sgid[i];
            if (g < 0) continue;
            if (g != cur) { if (cur >= 0) atomicAdd(&acc[cur * 4 + comp], a); cur = g; a = 0.f; }
            a += sv[i][comp];
        }
        if (cur >= 0) atomicAdd(&acc[cur * 4 + comp], a);
    }
}

__global__ void k_comb2(const float* __restrict__ acc, float* aab) {
    int b = threadIdx.x;
    if (b < BB) {
        float d1 = acc[b * 4 + 1] / acc[b * 4 + 0];
        float d2 = acc[b * 4 + 3] / acc[b * 4 + 2];
        float mm = fmaxf(d1, d2);
        float e1 = expf(d1 - mm), e2 = expf(d2 - mm);
        float ss = e1 + e2;
        aab[2 * b] = e1 / ss;
        aab[2 * b + 1] = e2 / ss;
    }
}

__global__ void k_eler(const float* __restrict__ feat, const float* __restrict__ Q,
                       const int* __restrict__ gid, float* el, float* er, int n) {
    int idx = blockIdx.x * blockDim.x + threadIdx.x;
    if (idx >= n * HH) return;
    int i = idx >> 3, h = idx & 7;
    const float* f = feat + (size_t)i * HD + h * 16;
    const float* q = Q + (size_t)gid[i] * HD2 + h * 32;
    float sl = 0.f, sr = 0.f;
#pragma unroll
    for (int c = 0; c < 16; c++) {
        float fv = f[c];
        sl = fmaf(fv, q[c], sl);
        sr = fmaf(fv, q[16 + c], sr);
    }
    el[idx] = sl;
    er[idx] = sr;
}

// ---------------- CSR build ----------------
__global__ void k_hist(const int* __restrict__ dst, int* deg, int E) {
    int e = blockIdx.x * blockDim.x + threadIdx.x;
    if (e < E) atomicAdd(&deg[dst[e]], 1);
}
__global__ void k_scan1(const int* __restrict__ deg, int* out, int* bsum, int n) {
    __shared__ int sh[512];
    int base = blockIdx.x * 512, t = threadIdx.x;
    int v0 = (base + t < n) ? deg[base + t] : 0;
    int v1 = (base + 256 + t < n) ? deg[base + 256 + t] : 0;
    sh[t] = v0; sh[t + 256] = v1;
    __syncthreads();
    for (int off = 1; off < 512; off <<= 1) {
        int i0 = t, i1 = t + 256;
        int n0 = sh[i0] + ((i0 >= off) ? sh[i0 - off] : 0);
        int n1 = sh[i1] + ((i1 >= off) ? sh[i1 - off] : 0);
        __syncthreads();
        sh[i0] = n0; sh[i1] = n1;
        __syncthreads();
    }
    if (base + t < n) out[base + t] = sh[t] - v0;
    if (base + 256 + t < n) out[base + 256 + t] = sh[t + 256] - v1;
    if (t == 0) bsum[blockIdx.x] = sh[511];
}
__global__ void k_scan2(int* bsum, int nb) {
    __shared__ int sh[256];
    int t = threadIdx.x;
    int v = (t < nb) ? bsum[t] : 0;
    sh[t] = v;
    __syncthreads();
    for (int off = 1; off < 256; off <<= 1) {
        int x = sh[t] + ((t >= off) ? sh[t - off] : 0);
        __syncthreads();
        sh[t] = x;
        __syncthreads();
    }
    if (t < nb) bsum[t] = sh[t] - v;
}
__global__ void k_scan3(int* coff, int* cursor, const int* __restrict__ bsum, int n) {
    int i = blockIdx.x * blockDim.x + threadIdx.x;
    if (i < n) {
        int v = coff[i] + bsum[i >> 9];
        coff[i] = v;
        cursor[i] = v;
    }
}
__global__ void k_scatter(const int* __restrict__ dst, int* cursor, int* eid, int E) {
    int e = blockIdx.x * blockDim.x + threadIdx.x;
    if (e < E) {
        int p = atomicAdd(&cursor[dst[e]], 1);
        eid[p] = e;
    }
}

// ---------------- single-pass edge softmax + aggregation ----------------
__global__ void k_node_agg(const int* __restrict__ src, const int* __restrict__ eid,
                           const int* __restrict__ coff, const int* __restrict__ deg,
                           const float* __restrict__ el, const float* __restrict__ er,
                           const float* __restrict__ ft, float* agg, float* s, int n) {
    int w = (blockIdx.x * blockDim.x + threadIdx.x) >> 5;
    int lane = threadIdx.x & 31;
    if (w >= n) return;
    int h = lane >> 2;
    int off = coff[w], d = deg[w];
    float erv = er[w * HH + h];
    float wsum = 0.f;
    float4 acc = make_float4(0.f, 0.f, 0.f, 0.f);
#pragma unroll 2
    for (int j = 0; j < d; j++) {
        int sn = src[eid[off + j]];
        float v = el[sn * HH + h] + erv;
        v = v > 0.f ? v : NEG_SLOPE * v;
        float wt = expf(v);
        wsum += wt;
        float4 fv = *(const float4*)(ft + (size_t)sn * HD + lane * 4);
        acc.x = fmaf(wt, fv.x, acc.x);
        acc.y = fmaf(wt, fv.y, acc.y);
        acc.z = fmaf(wt, fv.z, acc.z);
        acc.w = fmaf(wt, fv.w, acc.w);
    }
    float inv = wsum > 0.f ? 1.f / wsum : 0.f;
    acc.x *= inv; acc.y *= inv; acc.z *= inv; acc.w *= inv;
    *(float4*)(agg + (size_t)w * HD + lane * 4) = acc;
    if ((lane & 3) == 0) s[w * HH + h] = wsum;
}

// ---------------- batchnorm finalize / apply ----------------
__global__ void k_bnfin(const double* st, int n, float* mu, float* rstd) {
    int c = threadIdx.x;
    double m = st[c] / n;
    double v = st[256 + c] / n - m * m;
    if (v < 0.0) v = 0.0;
    mu[c] = (float)m;
    rstd[c] = (float)(1.0 / sqrt(v + 1e-5));
}
__global__ void k_bnelu(const float* __restrict__ Y, const float* __restrict__ mu,
                        const float* __restrict__ rstd, float* out, long long total, int C) {
    long long i = (long long)blockIdx.x * blockDim.x + threadIdx.x;
    if (i < total) {
        int c = (int)(i % C);
        out[i] = eluf((Y[i] - mu[c]) * rstd[c]);
    }
}
__global__ void k_final(const float* __restrict__ hlast, const float* __restrict__ Y,
                        const float* __restrict__ mu, const float* __restrict__ rstd, float* out,
                        long long total) {
    long long i = (long long)blockIdx.x * blockDim.x + threadIdx.x;
    if (i < total) {
        int c = (int)(i & (HD - 1));
        out[i] = hlast[i] + eluf((Y[i] - mu[c]) * rstd[c]);
    }
}

// ---------------- loss ----------------
__global__ void k_pesum(const int* __restrict__ ids, int nids, const int* __restrict__ src,
                        const int* __restrict__ dst, const float* __restrict__ el,
                        const float* __restrict__ er, const float* __restrict__ s, float* out8) {
    float acc[HH];
#pragma unroll
    for (int h = 0; h < HH; h++) acc[h] = 0.f;
    for (int i = blockIdx.x * blockDim.x + threadIdx.x; i < nids; i += gridDim.x * blockDim.x) {
        int e = ids[i];
        int se = src[e] * HH, de = dst[e] * HH;
#pragma unroll
        for (int h = 0; h < HH; h++) {
            float v = el[se + h] + er[de + h];
            v = v > 0.f ? v : NEG_SLOPE * v;
            acc[h] += expf(v) / s[de + h];
        }
    }
#pragma unroll
    for (int h = 0; h < HH; h++)
#pragma unroll
        for (int o = 16; o; o >>= 1) acc[h] += __shfl_down_sync(0xffffffffu, acc[h], o);
    if ((threadIdx.x & 31) == 0)
#pragma unroll
        for (int h = 0; h < HH; h++) atomicAdd(&out8[h], acc[h]);
}
__global__ void k_loss(const float* pe, const float* de, const int* lenp, float* out) {
    float sum = 0.f;
#pragma unroll
    for (int h = 0; h < HH; h++) sum += pe[h] - de[h];
    out[0] = -sum / (8.0f * (float)lenp[0]);
}

// ---------------- host ----------------
static inline int cdiv(long long a, long long b) { return (int)((a + b - 1) / b); }

extern "C" void kernel_launch(void* const* d_in, const int* in_sizes, int n_in, void* d_out,
                              int out_size) {
    const float* h_da_last = (const float*)d_in[0];
    const float* h_q_last  = (const float*)d_in[1];
    const float* h_da_0    = (const float*)d_in[2];
    const float* h_q_0     = (const float*)d_in[3];
    const float* W_L       = (const float*)d_in[4];
    const float* b_L       = (const float*)d_in[5];
    const float* gateq_W   = (const float*)d_in[6];
    const float* gateq_b   = (const float*)d_in[7];
    const float* gate1_W   = (const float*)d_in[8];
    const float* gate1_b   = (const float*)d_in[9];
    const float* gate2_W   = (const float*)d_in[10];
    const float* gate2_b   = (const float*)d_in[11];
    const float* Q_comb    = (const float*)d_in[12];
    const float* Qf_W1     = (const float*)d_in[13];
    const float* Qf_b1     = (const float*)d_in[14];
    const float* Qf_W2     = (const float*)d_in[15];
    const float* Qf_b2     = (const float*)d_in[16];
    const float* end_W1    = (const float*)d_in[17];
    const float* end_b1    = (const float*)d_in[18];
    const float* end_W2    = (const float*)d_in[19];
    const float* end_b2    = (const float*)d_in[20];
    const int* src_da = (const int*)d_in[21];
    const int* dst_da = (const int*)d_in[22];
    const int* src_q  = (const int*)d_in[23];
    const int* dst_q  = (const int*)d_in[24];
    const int* gid_da = (const int*)d_in[25];
    const int* gid_q  = (const int*)d_in[26];
    const int* PEid   = (const int*)d_in[27];
    const int* DEid   = (const int*)d_in[28];
    const int* lenp   = (const int*)d_in[29];
    int nPE = in_sizes[27], nDE = in_sizes[28];

    float* out = (float*)d_out;
    float* out_da = out;
    float* out_q = out + (long long)NDA * HD;
    float* out_loss = out + (long long)NDA * HD + (long long)NQ * HD;

    float *feat, *featq, *ft, *fh, *agg, *y1, *y1b, *y2, *el, *er, *ss, *eb;
    float *glq, *t1, *t1b, *t2, *Qb, *gsumq, *accq, *accda, *aabq, *aabda, *mu, *rstd, *pe, *de;
    double* dstat;
    int *deg, *coff, *cursor, *eid, *bsum, *degq, *coffq, *cursorq, *eidq, *bsumq;
    cudaGetSymbolAddress((void**)&feat, g_feat);
    cudaGetSymbolAddress((void**)&featq, g_featq);
    cudaGetSymbolAddress((void**)&ft, g_ft);
    cudaGetSymbolAddress((void**)&fh, g_fh);
    cudaGetSymbolAddress((void**)&agg, g_agg);
    cudaGetSymbolAddress((void**)&y1, g_y1);
    cudaGetSymbolAddress((void**)&y1b, g_y1b);
    cudaGetSymbolAddress((void**)&y2, g_y2);
    cudaGetSymbolAddress((void**)&el, g_el);
    cudaGetSymbolAddress((void**)&er, g_er);
    cudaGetSymbolAddress((void**)&ss, g_s);
    cudaGetSymbolAddress((void**)&eb, g_eb);
    cudaGetSymbolAddress((void**)&glq, g_glq);
    cudaGetSymbolAddress((void**)&t1, g_t1);
    cudaGetSymbolAddress((void**)&t1b, g_t1b);
    cudaGetSymbolAddress((void**)&t2, g_t2);
    cudaGetSymbolAddress((void**)&Qb, g_Q);
    cudaGetSymbolAddress((void**)&gsumq, g_gsumq);
    cudaGetSymbolAddress((void**)&accq, g_accq);
    cudaGetSymbolAddress((void**)&accda, g_accda);
    cudaGetSymbolAddress((void**)&aabq, g_aabq);
    cudaGetSymbolAddress((void**)&aabda, g_aabda);
    cudaGetSymbolAddress((void**)&mu, g_mu);
    cudaGetSymbolAddress((void**)&rstd, g_rstd);
    cudaGetSymbolAddress((void**)&pe, g_pe);
    cudaGetSymbolAddress((void**)&de, g_de);
    cudaGetSymbolAddress((void**)&dstat, g_dstat);
    cudaGetSymbolAddress((void**)&deg, g_deg);
    cudaGetSymbolAddress((void**)&coff, g_coff);
    cudaGetSymbolAddress((void**)&cursor, g_cursor);
    cudaGetSymbolAddress((void**)&eid, g_eid);
    cudaGetSymbolAddress((void**)&bsum, g_bsum);
    cudaGetSymbolAddress((void**)&degq, g_degq);
    cudaGetSymbolAddress((void**)&coffq, g_coffq);
    cudaGetSymbolAddress((void**)&cursorq, g_cursorq);
    cudaGetSymbolAddress((void**)&eidq, g_eidq);
    cudaGetSymbolAddress((void**)&bsumq, g_bsumq);

    cudaFuncSetAttribute(k_gemm_async<0>, cudaFuncAttributeMaxDynamicSharedMemorySize, SMEM_GA);
    cudaFuncSetAttribute(k_gemm_async<1>, cudaFuncAttributeMaxDynamicSharedMemorySize, SMEM_GA);

    // 1-5: independent prep
    k_zero0<<<cdiv(NDA, 256), 256>>>(glq, gsumq, accq, accda, pe, de, deg, degq);
    k_gapq<<<cdiv(NQ, 32), 1024>>>(h_q_last, gateq_W, gateq_b, gid_q, eb, gsumq, NQ);
    k_gap_pool<<<cdiv((long long)NQ * 32, 256), 256>>>(h_q_last, gid_q, eb, gsumq, glq, NQ);
    k_gapdots<<<cdiv(NDA, 32), 1024>>>(h_da_0, h_da_last, gate1_W, gate1_b, gate2_W, gate2_b,
                                       Q_comb, gid_da, accda, NDA);
    k_hist<<<cdiv(EDA, 256), 256>>>(dst_da, deg, EDA);
    // 6: da feat GEMM (ncu sample target)
    k_gemm_async<0><<<dim3(1, cdiv(NDA, 128)), 256, SMEM_GA>>>(h_da_last, W_L, b_L, feat, nullptr,
                                                               NDA, 128, 128);
    k_gemm_async<0><<<dim3(1, cdiv(NQ, 128)), 256, SMEM_GA>>>(h_q_last, W_L, b_L, featq, nullptr,
                                                              NQ, 128, 128);
    k_gapdots<<<cdiv(NQ, 32), 1024>>>(h_q_0, h_q_last, gate1_W, gate1_b, gate2_W, gate2_b, Q_comb,
                                      gid_q, accq, NQ);
    k_scan1<<<cdiv(NDA, 512), 256>>>(deg, coff, bsum, NDA);
    k_scan2<<<1, 256>>>(bsum, cdiv(NDA, 512));
    k_scan3<<<cdiv(NDA, 256), 256>>>(coff, cursor, bsum, NDA);
    k_scatter<<<cdiv(EDA, 256), 256>>>(dst_da, cursor, eid, EDA);
    k_hist<<<cdiv(EQ, 256), 256>>>(dst_q, degq, EQ);
    k_scan1<<<cdiv(NQ, 512), 256>>>(degq, coffq, bsumq, NQ);
    k_scan2<<<1, 256>>>(bsumq, cdiv(NQ, 512));
    k_scan3<<<cdiv(NQ, 256), 256>>>(coffq, cursorq, bsumq, NQ);
    k_scatter<<<cdiv(EQ, 256), 256>>>(dst_q, cursorq, eidq, EQ);
    k_comb2<<<1, BB>>>(accq, aabq);
    k_comb2<<<1, BB>>>(accda, aabda);

    // Qf FNN -> Qb
    k_filld<<<2, 256>>>(dstat, 512);
    k_gemm_async<1><<<dim3(2, 1), 256, SMEM_GA>>>(glq, Qf_W1, Qf_b1, t1, dstat, BB, 128, 256);
    k_bnfin<<<1, 256>>>(dstat, BB, mu, rstd);
    k_bnelu<<<cdiv(BB * 256, 256), 256>>>(t1, mu, rstd, t1b, (long long)BB * 256, 256);
    k_filld<<<2, 256>>>(dstat, 512);
    k_gemm_async<1><<<dim3(2, 1), 256, SMEM_GA>>>(t1b, Qf_W2, Qf_b2, t2, dstat, BB, 256, 256);
    k_bnfin<<<1, 256>>>(dstat, BB, mu, rstd);
    k_bnelu<<<cdiv(BB * 256, 256), 256>>>(t2, mu, rstd, Qb, (long long)BB * 256, 256);

    // ---- q branch ----
    k_mix<<<cdiv((long long)NQ * 32, 256), 256>>>(h_q_0, h_q_last, aabq, gid_q, fh, NQ);
    k_gemm_async<0><<<dim3(1, cdiv(NQ, 128)), 256, SMEM_GA>>>(fh, W_L, b_L, ft, nullptr, NQ, 128,
                                                              128);
    k_eler<<<cdiv((long long)NQ * HH, 256), 256>>>(featq, Qb, gid_q, el, er, NQ);
    k_node_agg<<<cdiv((long long)NQ * 32, 256), 256>>>(src_q, eidq, coffq, degq, el, er, ft, agg,
                                                       ss, NQ);
    k_filld<<<2, 256>>>(dstat, 512);
    k_gemm_async<1><<<dim3(2, cdiv(NQ, 128)), 256, SMEM_GA>>>(agg, end_W1, end_b1, y1, dstat, NQ,
                                                              128, 256);
    k_bnfin<<<1, 256>>>(dstat, NQ, mu, rstd);
    k_bnelu<<<cdiv((long long)NQ * 256, 256), 256>>>(y1, mu, rstd, y1b, (long long)NQ * 256, 256);
    k_filld<<<2, 256>>>(dstat, 512);
    k_gemm_async<1><<<dim3(1, cdiv(NQ, 128)), 256, SMEM_GA>>>(y1b, end_W2, end_b2, y2, dstat, NQ,
                                                              256, 128);
    k_bnfin<<<1, 128>>>(dstat, NQ, mu, rstd);
    k_final<<<cdiv((long long)NQ * HD, 256), 256>>>(h_q_last, y2, mu, rstd, out_q,
                                                    (long long)NQ * HD);

    // ---- da branch ----
    k_mix<<<cdiv((long long)NDA * 32, 256), 256>>>(h_da_0, h_da_last, aabda, gid_da, fh, NDA);
    k_gemm_async<0><<<dim3(1, cdiv(NDA, 128)), 256, SMEM_GA>>>(fh, W_L, b_L, ft, nullptr, NDA,
                                                               128, 128);
    k_eler<<<cdiv((long long)NDA * HH, 256), 256>>>(feat, Qb, gid_da, el, er, NDA);
    k_node_agg<<<cdiv((long long)NDA * 32, 256), 256>>>(src_da, eid, coff, deg, el, er, ft, agg,
                                                        ss, NDA);
    k_filld<<<2, 256>>>(dstat, 512);
    k_gemm_async<1><<<dim3(2, cdiv(NDA, 128)), 256, SMEM_GA>>>(agg, end_W1, end_b1, y1, dstat,
                                                               NDA, 128, 256);
    k_bnfin<<<1, 256>>>(dstat, NDA, mu, rstd);
    k_bnelu<<<cdiv((long long)NDA * 256, 256), 256>>>(y1, mu, rstd, y1b, (long long)NDA * 256,
                                                      256);
    k_filld<<<2, 256>>>(dstat, 512);
    k_gemm_async<1><<<dim3(1, cdiv(NDA, 128)), 256, SMEM_GA>>>(y1b, end_W2, end_b2, y2, dstat,
                                                               NDA, 256, 128);
    k_bnfin<<<1, 128>>>(dstat, NDA, mu, rstd);
    k_final<<<cdiv((long long)NDA * HD, 256), 256>>>(h_da_last, y2, mu, rstd, out_da,
                                                     (long long)NDA * HD);

    // ---- loss ----
    k_pesum<<<256, 256>>>(PEid, nPE, src_da, dst_da, el, er, ss, pe);
    k_pesum<<<256, 256>>>(DEid, nDE, src_da, dst_da, el, er, ss, de);
    k_loss<<<1, 1>>>(pe, de, lenp, out_loss);
}

// round 7
// speedup vs baseline: 3.0411x; 1.0095x over previous
#include <cuda_runtime.h>
#include <math.h>
#include <stdint.h>

#define NDA 100000
#define NQ  20000
#define EDA 1000000
#define EQ  200000
#define BB  64
#define HH  8
#define HD  128
#define HD2 256
#define NEG_SLOPE 2.0f

// ---------------- scratch ----------------
__device__ float g_feat[(size_t)NDA * HD];
__device__ float g_featq[(size_t)NQ * HD];
__device__ float g_ft[(size_t)NDA * HD];
__device__ float g_agg[(size_t)NDA * HD];
__device__ float g_y1[(size_t)NDA * HD2];
__device__ float g_y2[(size_t)NDA * HD];
__device__ float g_el[NDA * HH];
__device__ float g_er[NDA * HH];
__device__ float g_s[NDA * HH];
__device__ float g_eb[NQ];
__device__ int   g_deg[NDA];
__device__ int   g_coff[NDA];
__device__ int   g_cursor[NDA];
__device__ int   g_eid[EDA];
__device__ int   g_bsum[256];
__device__ int   g_degq[NQ];
__device__ int   g_coffq[NQ];
__device__ int   g_cursorq[NQ];
__device__ int   g_eidq[EQ];
__device__ int   g_bsumq[256];
__device__ float g_glq[BB * HD];
__device__ float g_t1[BB * HD2];
__device__ float g_t2[BB * HD2];
__device__ float g_Q[BB * HD2];
__device__ float g_gsumq[BB];
__device__ float g_accq[BB * 4];
__device__ float g_accda[BB * 4];
__device__ float g_aabq[BB * 2];
__device__ float g_aabda[BB * 2];
__device__ double g_dstat[512];
__device__ float g_mu[HD2];
__device__ float g_rstd[HD2];
__device__ float g_pe[HH];
__device__ float g_de[HH];

__device__ __forceinline__ float eluf(float x) { return x > 0.f ? x : expm1f(x); }

__device__ __forceinline__ uint32_t smem_u32(const void* p) {
    uint32_t a;
    asm("{ .reg .u64 t; cvta.to.shared.u64 t, %1; cvt.u32.u64 %0, t; }" : "=r"(a) : "l"(p));
    return a;
}
__device__ __forceinline__ uint32_t f2tf(float x) {
    uint32_t r;
    asm("cvt.rna.tf32.f32 %0, %1;" : "=r"(r) : "f"(x));
    return r;
}
__device__ __forceinline__ void mma8(float* d, const uint32_t* a, const uint32_t* b) {
    asm volatile(
        "mma.sync.aligned.m16n8k8.row.col.f32.tf32.tf32.f32 "
        "{%0,%1,%2,%3}, {%4,%5,%6,%7}, {%8,%9}, {%0,%1,%2,%3};\n"
        : "+f"(d[0]), "+f"(d[1]), "+f"(d[2]), "+f"(d[3])
        : "r"(a[0]), "r"(a[1]), "r"(a[2]), "r"(a[3]), "r"(b[0]), "r"(b[1]));
}

// ---------------- pipelined TF32 GEMM with fused A-transforms ----------------
// AMODE 0: A = A1
// AMODE 1: A = a0[gid]*A1 + a1[gid]*A2   (blend in smem)
// AMODE 2: A = elu((A1 - mu[k]) * rstd[k]) (transform in smem)
// smem floats: A1 stages 2x4608 @0, W stages 2x4224 @9216, A2 stages 2x4608 @17664
#define AOFF(buf) ((buf) * 4608)
#define WOFF(buf) (9216 + (buf) * 4224)
#define A2OFF(buf) (17664 + (buf) * 4608)
#define SMEM_G0 ((9216 + 8448) * 4)
#define SMEM_G1 ((9216 + 8448 + 9216) * 4)

template <int AMODE>
__device__ __forceinline__ void stage_issue(uint32_t sb, int buf, const float* __restrict__ A,
                                            const float* __restrict__ A2,
                                            const float* __restrict__ W, int rowBase, int colBase,
                                            int k0, int n, int K, int NC, int tid) {
    uint32_t abase = sb + AOFF(buf) * 4;
    uint32_t wbase = sb + WOFF(buf) * 4;
#pragma unroll
    for (int q = 0; q < 4; q++) {
        int id = tid + q * 256;
        int r = id >> 3, kq = id & 7;
        int grow = rowBase + r;
        const float* src = A + (size_t)grow * K + k0 + kq * 4;
        uint32_t dst = abase + (r * 36 + kq * 4) * 4;
        int sz = grow < n ? 16 : 0;
        asm volatile("cp.async.ca.shared.global [%0], [%1], 16, %2;" ::"r"(dst), "l"(src), "r"(sz)
                     : "memory");
    }
    if (AMODE == 1) {
        uint32_t a2base = sb + A2OFF(buf) * 4;
#pragma unroll
        for (int q = 0; q < 4; q++) {
            int id = tid + q * 256;
            int r = id >> 3, kq = id & 7;
            int grow = rowBase + r;
            const float* src = A2 + (size_t)grow * K + k0 + kq * 4;
            uint32_t dst = a2base + (r * 36 + kq * 4) * 4;
            int sz = grow < n ? 16 : 0;
            asm volatile("cp.async.ca.shared.global [%0], [%1], 16, %2;" ::"r"(dst), "l"(src),
                         "r"(sz)
                         : "memory");
        }
    }
#pragma unroll
    for (int q = 0; q < 4; q++) {
        int id = tid + q * 256;
        int kk = id >> 5, nq = id & 31;
        const float* src = W + (size_t)(k0 + kk) * NC + colBase + nq * 4;
        uint32_t dst = wbase + (kk * 132 + nq * 4) * 4;
        asm volatile("cp.async.ca.shared.global [%0], [%1], 16;" ::"r"(dst), "l"(src) : "memory");
    }
    asm volatile("cp.async.commit_group;" ::: "memory");
}

template <int AMODE, int STAT>
__global__ void __launch_bounds__(256, 2) k_gemm(
    const float* __restrict__ A1, const float* __restrict__ A2,
    const float* __restrict__ acoef, const int* __restrict__ gid,
    const float* __restrict__ W, const float* __restrict__ bias,
    const float* __restrict__ mu, const float* __restrict__ rstd,
    float* __restrict__ C, double* dstat, int n, int K, int NC) {
    extern __shared__ float smf[];
    __shared__ float sstat[256];
    const uint32_t sb = smem_u32(smf);
    const int tid = threadIdx.x;
    const int lane = tid & 31;
    const int wid = tid >> 5;
    const int warp_m = wid >> 2;
    const int warp_n = wid & 3;
    const int rowBase = blockIdx.y * 128;
    const int colBase = blockIdx.x * 128;
    const int g4 = lane >> 2;
    const int t4 = lane & 3;

    if (STAT && tid < 256) sstat[tid] = 0.f;

    float c0 = 0.f, c1 = 0.f;
    if (AMODE == 1) {
        int rr = rowBase + (tid >> 1);
        if (rr < n) {
            int g = gid[rr];
            c0 = acoef[2 * g];
            c1 = acoef[2 * g + 1];
        }
    }

    stage_issue<AMODE>(sb, 0, A1, A2, W, rowBase, colBase, 0, n, K, NC, tid);
    stage_issue<AMODE>(sb, 1, A1, A2, W, rowBase, colBase, 32, n, K, NC, tid);

    float acc[4][4][4];
#pragma unroll
    for (int mi = 0; mi < 4; mi++)
#pragma unroll
        for (int ni = 0; ni < 4; ni++)
#pragma unroll
            for (int r = 0; r < 4; r++) acc[mi][ni][r] = 0.f;

    const int nk = K >> 5;
    for (int i = 0; i < nk; i++) {
        int p = i & 1;
        if (i + 1 < nk)
            asm volatile("cp.async.wait_group 1;" ::: "memory");
        else
            asm volatile("cp.async.wait_group 0;" ::: "memory");
        __syncthreads();
        if (AMODE == 1) {
            float* a = smf + AOFF(p) + (tid >> 1) * 36 + (tid & 1) * 16;
            const float* b2 = smf + A2OFF(p) + (tid >> 1) * 36 + (tid & 1) * 16;
#pragma unroll
            for (int j = 0; j < 16; j++) a[j] = c0 * a[j] + c1 * b2[j];
            __syncthreads();
        } else if (AMODE == 2) {
            int kg = i * 32 + (tid & 1) * 16;
            float* a = smf + AOFF(p) + (tid >> 1) * 36 + (tid & 1) * 16;
#pragma unroll
            for (int j = 0; j < 16; j++) a[j] = eluf((a[j] - mu[kg + j]) * rstd[kg + j]);
            __syncthreads();
        }
        const float* Af = smf + AOFF(p);
        const float* Wf = smf + WOFF(p);
#pragma unroll
        for (int ks = 0; ks < 4; ks++) {
            int kk = ks * 8;
            uint32_t a[4][4];
#pragma unroll
            for (int mi = 0; mi < 4; mi++) {
                int r = warp_m * 64 + mi * 16 + g4;
                a[mi][0] = f2tf(Af[r * 36 + kk + t4]);
                a[mi][1] = f2tf(Af[(r + 8) * 36 + kk + t4]);
                a[mi][2] = f2tf(Af[r * 36 + kk + t4 + 4]);
                a[mi][3] = f2tf(Af[(r + 8) * 36 + kk + t4 + 4]);
            }
            uint32_t b[4][2];
#pragma unroll
            for (int ni = 0; ni < 4; ni++) {
                int c = warp_n * 32 + ni * 8 + g4;
                b[ni][0] = f2tf(Wf[(kk + t4) * 132 + c]);
                b[ni][1] = f2tf(Wf[(kk + t4 + 4) * 132 + c]);
            }
#pragma unroll
            for (int mi = 0; mi < 4; mi++)
#pragma unroll
                for (int ni = 0; ni < 4; ni++) mma8(acc[mi][ni], a[mi], b[ni]);
        }
        __syncthreads();
        if (i + 2 < nk)
            stage_issue<AMODE>(sb, p, A1, A2, W, rowBase, colBase, (i + 2) * 32, n, K, NC, tid);
    }

    float cs[8], cq[8];
#pragma unroll
    for (int i = 0; i < 8; i++) { cs[i] = 0.f; cq[i] = 0.f; }

#pragma unroll
    for (int mi = 0; mi < 4; mi++) {
        int r0 = rowBase + warp_m * 64 + mi * 16 + g4;
        int r1 = r0 + 8;
#pragma unroll
        for (int ni = 0; ni < 4; ni++) {
            int c = colBase + warp_n * 32 + ni * 8 + t4 * 2;
            float b0 = bias[c], b1 = bias[c + 1];
            if (r0 < n) {
                float v0 = acc[mi][ni][0] + b0, v1 = acc[mi][ni][1] + b1;
                C[(size_t)r0 * NC + c] = v0;
                C[(size_t)r0 * NC + c + 1] = v1;
                if (STAT) {
                    cs[ni * 2] += v0; cq[ni * 2] += v0 * v0;
                    cs[ni * 2 + 1] += v1; cq[ni * 2 + 1] += v1 * v1;
                }
            }
            if (r1 < n) {
                float v2 = acc[mi][ni][2] + b0, v3 = acc[mi][ni][3] + b1;
                C[(size_t)r1 * NC + c] = v2;
                C[(size_t)r1 * NC + c + 1] = v3;
                if (STAT) {
                    cs[ni * 2] += v2; cq[ni * 2] += v2 * v2;
                    cs[ni * 2 + 1] += v3; cq[ni * 2 + 1] += v3 * v3;
                }
            }
        }
    }
    if (STAT) {
#pragma unroll
        for (int i = 0; i < 8; i++) {
            float s = cs[i], q = cq[i];
            s += __shfl_down_sync(0xffffffffu, s, 16);
            q += __shfl_down_sync(0xffffffffu, q, 16);
            s += __shfl_down_sync(0xffffffffu, s, 8);
            q += __shfl_down_sync(0xffffffffu, q, 8);
            s += __shfl_down_sync(0xffffffffu, s, 4);
            q += __shfl_down_sync(0xffffffffu, q, 4);
            if (g4 == 0) {
                int c = warp_n * 32 + (i >> 1) * 8 + t4 * 2 + (i & 1);
                atomicAdd(&sstat[c], s);
                atomicAdd(&sstat[128 + c], q);
            }
        }
        __syncthreads();
        if (tid < 128) {
            atomicAdd(&dstat[colBase + tid], (double)sstat[tid]);
            atomicAdd(&dstat[256 + colBase + tid], (double)sstat[128 + tid]);
        }
    }
}

// ---------------- fills ----------------
__global__ void k_zero0(float* glq, float* gsumq, float* accq, float* accda, float* pe, float* de,
                        int* degda, int* degq, double* dstat) {
    int i = blockIdx.x * blockDim.x + threadIdx.x;
    if (i < NDA) degda[i] = 0;
    if (i < NQ) degq[i] = 0;
    if (i < BB * HD) glq[i] = 0.f;
    if (i < BB) gsumq[i] = 0.f;
    if (i < BB * 4) { accq[i] = 0.f; accda[i] = 0.f; }
    if (i < HH) { pe[i] = 0.f; de[i] = 0.f; }
    if (i < 512) dstat[i] = 0.0;
}

// ---------------- fused gate kernels ----------------
__global__ void __launch_bounds__(1024) k_gapq(const float* __restrict__ M,
                                               const float* __restrict__ w,
                                               const float* __restrict__ b,
                                               const int* __restrict__ gid, float* ebuf,
                                               float* gsum, int n) {
    __shared__ int sgid[32];
    __shared__ float se[32];
    int wid = threadIdx.x >> 5, lane = threadIdx.x & 31;
    int node = blockIdx.x * 32 + wid;
    if (node < n) {
        float4 a = ((const float4*)(M + (size_t)node * HD))[lane];
        float4 wv = ((const float4*)w)[lane];
        float s = a.x * wv.x + a.y * wv.y + a.z * wv.z + a.w * wv.w;
#pragma unroll
        for (int o = 16; o; o >>= 1) s += __shfl_down_sync(0xffffffffu, s, o);
        if (lane == 0) {
            float e = expf(s + b[0]);
            ebuf[node] = e;
            sgid[wid] = gid[node];
            se[wid] = e;
        }
    } else if (lane == 0) sgid[wid] = -1;
    __syncthreads();
    if (threadIdx.x == 0) {
        int cur = -2;
        float a = 0.f;
        for (int i = 0; i < 32; i++) {
            int g = sgid[i];
            if (g < 0) continue;
            if (g != cur) { if (cur >= 0) atomicAdd(&gsum[cur], a); cur = g; a = 0.f; }
            a += se[i];
        }
        if (cur >= 0) atomicAdd(&gsum[cur], a);
    }
}

__global__ void k_gap_pool(const float* __restrict__ M, const int* __restrict__ gid,
                           const float* __restrict__ e, const float* __restrict__ gsum,
                           float* pool, int n) {
    int w = (blockIdx.x * blockDim.x + threadIdx.x) >> 5;
    int lane = threadIdx.x & 31;
    if (w >= n) return;
    int b = gid[w];
    float wt = e[w] / gsum[b];
    const float* row = M + (size_t)w * HD;
#pragma unroll
    for (int j = lane; j < HD; j += 32) atomicAdd(&pool[b * HD + j], wt * row[j]);
}

__global__ void __launch_bounds__(1024) k_gapdots(
    const float* __restrict__ M1, const float* __restrict__ M2, const float* __restrict__ w1,
    const float* __restrict__ b1, const float* __restrict__ w2, const float* __restrict__ b2,
    const float* __restrict__ qc, const int* __restrict__ gid, float* acc, int n) {
    __shared__ int sgid[32];
    __shared__ float sv[32][4];
    int wid = threadIdx.x >> 5, lane = threadIdx.x & 31;
    int node = blockIdx.x * 32 + wid;
    if (node < n) {
        float4 a = ((const float4*)(M1 + (size_t)node * HD))[lane];
        float4 bb = ((const float4*)(M2 + (size_t)node * HD))[lane];
        float4 w1v = ((const float4*)w1)[lane];
        float4 w2v = ((const float4*)w2)[lane];
        float4 qv = ((const float4*)qc)[lane];
        float s1 = a.x * w1v.x + a.y * w1v.y + a.z * w1v.z + a.w * w1v.w;
        float q1 = a.x * qv.x + a.y * qv.y + a.z * qv.z + a.w * qv.w;
        float s2 = bb.x * w2v.x + bb.y * w2v.y + bb.z * w2v.z + bb.w * w2v.w;
        float q2 = bb.x * qv.x + bb.y * qv.y + bb.z * qv.z + bb.w * qv.w;
#pragma unroll
        for (int o = 16; o; o >>= 1) {
            s1 += __shfl_down_sync(0xffffffffu, s1, o);
            q1 += __shfl_down_sync(0xffffffffu, q1, o);
            s2 += __shfl_down_sync(0xffffffffu, s2, o);
            q2 += __shfl_down_sync(0xffffffffu, q2, o);
        }
        if (lane == 0) {
            float e1 = expf(s1 + b1[0]), e2 = expf(s2 + b2[0]);
            sgid[wid] = gid[node];
            sv[wid][0] = e1; sv[wid][1] = e1 * q1; sv[wid][2] = e2; sv[wid][3] = e2 * q2;
        }
    } else if (lane == 0) sgid[wid] = -1;
    __syncthreads();
    if (threadIdx.x < 4) {
        int comp = threadIdx.x;
        int cur = -2;
        float a = 0.f;
        for (int i = 0; i < 32; i++) {
            int g = sgid[i];
            if (g < 0) continue;
            if (g != cur) { if (cur >= 0) atomicAdd(&acc[cur * 4 + comp], a); cur = g; a = 0.f; }
            a += sv[i][comp];
        }
        if (cur >= 0) atomicAdd(&acc[cur * 4 + comp], a);
    }
}

// both graphs' att_comb softmax in one launch (threads 0-63: q, 64-127: da)
__global__ void k_comb2x(const float* __restrict__ accq, float* aabq,
                         const float* __restrict__ accda, float* aabda) {
    int t = threadIdx.x;
    const float* acc = t < BB ? accq : accda;
    float* aab = t < BB ? aabq : aabda;
    int b = t & (BB - 1);
    float d1 = acc[b * 4 + 1] / acc[b * 4 + 0];
    float d2 = acc[b * 4 + 3] / acc[b * 4 + 2];
    float mm = fmaxf(d1, d2);
    float e1 = expf(d1 - mm), e2 = expf(d2 - mm);
    float ss = e1 + e2;
    aab[2 * b] = e1 / ss;
    aab[2 * b + 1] = e2 / ss;
}

__global__ void k_eler(const float* __restrict__ feat, const float* __restrict__ Q,
                       const int* __restrict__ gid, float* el, float* er, int n) {
    int idx = blockIdx.x * blockDim.x + threadIdx.x;
    if (idx >= n * HH) return;
    int i = idx >> 3, h = idx & 7;
    const float* f = feat + (size_t)i * HD + h * 16;
    const float* q = Q + (size_t)gid[i] * HD2 + h * 32;
    float sl = 0.f, sr = 0.f;
#pragma unroll
    for (int c = 0; c < 16; c++) {
        float fv = f[c];
        sl = fmaf(fv, q[c], sl);
        sr = fmaf(fv, q[16 + c], sr);
    }
    el[idx] = sl;
    er[idx] = sr;
}

// ---------------- CSR build ----------------
__global__ void k_hist(const int* __restrict__ dst, int* deg, int E) {
    int e = blockIdx.x * blockDim.x + threadIdx.x;
    if (e < E) atomicAdd(&deg[dst[e]], 1);
}
__global__ void k_scan1(const int* __restrict__ deg, int* out, int* bsum, int n) {
    __shared__ int sh[512];
    int base = blockIdx.x * 512, t = threadIdx.x;
    int v0 = (base + t < n) ? deg[base + t] : 0;
    int v1 = (base + 256 + t < n) ? deg[base + 256 + t] : 0;
    sh[t] = v0; sh[t + 256] = v1;
    __syncthreads();
    for (int off = 1; off < 512; off <<= 1) {
        int i0 = t, i1 = t + 256;
        int n0 = sh[i0] + ((i0 >= off) ? sh[i0 - off] : 0);
        int n1 = sh[i1] + ((i1 >= off) ? sh[i1 - off] : 0);
        __syncthreads();
        sh[i0] = n0; sh[i1] = n1;
        __syncthreads();
    }
    if (base + t < n) out[base + t] = sh[t] - v0;
    if (base + 256 + t < n) out[base + 256 + t] = sh[t + 256] - v1;
    if (t == 0) bsum[blockIdx.x] = sh[511];
}
__global__ void k_scan2(int* bsum, int nb) {
    __shared__ int sh[256];
    int t = threadIdx.x;
    int v = (t < nb) ? bsum[t] : 0;
    sh[t] = v;
    __syncthreads();
    for (int off = 1; off < 256; off <<= 1) {
        int x = sh[t] + ((t >= off) ? sh[t - off] : 0);
        __syncthreads();
        sh[t] = x;
        __syncthreads();
    }
    if (t < nb) bsum[t] = sh[t] - v;
}
__global__ void k_scan3(int* coff, int* cursor, const int* __restrict__ bsum, int n) {
    int i = blockIdx.x * blockDim.x + threadIdx.x;
    if (i < n) {
        int v = coff[i] + bsum[i >> 9];
        coff[i] = v;
        cursor[i] = v;
    }
}
__global__ void k_scatter(const int* __restrict__ dst, int* cursor, int* eid, int E) {
    int e = blockIdx.x * blockDim.x + threadIdx.x;
    if (e < E) {
        int p = atomicAdd(&cursor[dst[e]], 1);
        eid[p] = e;
    }
}

// ---------------- single-pass edge softmax + aggregation ----------------
__global__ void k_node_agg(const int* __restrict__ src, const int* __restrict__ eid,
                           const int* __restrict__ coff, const int* __restrict__ deg,
                           const float* __restrict__ el, const float* __restrict__ er,
                           const float* __restrict__ ft, float* agg, float* s, int n) {
    int w = (blockIdx.x * blockDim.x + threadIdx.x) >> 5;
    int lane = threadIdx.x & 31;
    if (w >= n) return;
    int h = lane >> 2;
    int off = coff[w], d = deg[w];
    float erv = er[w * HH + h];
    float wsum = 0.f;
    float4 acc = make_float4(0.f, 0.f, 0.f, 0.f);
#pragma unroll 2
    for (int j = 0; j < d; j++) {
        int sn = src[eid[off + j]];
        float v = el[sn * HH + h] + erv;
        v = v > 0.f ? v : NEG_SLOPE * v;
        float wt = expf(v);
        wsum += wt;
        float4 fv = *(const float4*)(ft + (size_t)sn * HD + lane * 4);
        acc.x = fmaf(wt, fv.x, acc.x);
        acc.y = fmaf(wt, fv.y, acc.y);
        acc.z = fmaf(wt, fv.z, acc.z);
        acc.w = fmaf(wt, fv.w, acc.w);
    }
    float inv = wsum > 0.f ? 1.f / wsum : 0.f;
    acc.x *= inv; acc.y *= inv; acc.z *= inv; acc.w *= inv;
    *(float4*)(agg + (size_t)w * HD + lane * 4) = acc;
    if ((lane & 3) == 0) s[w * HH + h] = wsum;
}

// ---------------- batchnorm finalize (self-zeroing) / apply ----------------
__global__ void k_bnfin(double* st, int n, float* mu, float* rstd) {
    int c = threadIdx.x;
    double m = st[c] / n;
    double v = st[256 + c] / n - m * m;
    if (v < 0.0) v = 0.0;
    mu[c] = (float)m;
    rstd[c] = (float)(1.0 / sqrt(v + 1e-5));
    st[c] = 0.0;
    st[256 + c] = 0.0;
}
__global__ void k_bnelu(const float* __restrict__ Y, const float* __restrict__ mu,
                        const float* __restrict__ rstd, float* out, long long total, int C) {
    long long i = (long long)blockIdx.x * blockDim.x + threadIdx.x;
    if (i < total) {
        int c = (int)(i % C);
        out[i] = eluf((Y[i] - mu[c]) * rstd[c]);
    }
}
__global__ void k_final(const float* __restrict__ hlast, const float* __restrict__ Y,
                        const float* __restrict__ mu, const float* __restrict__ rstd, float* out,
                        long long total) {
    long long i = (long long)blockIdx.x * blockDim.x + threadIdx.x;
    if (i < total) {
        int c = (int)(i & (HD - 1));
        out[i] = hlast[i] + eluf((Y[i] - mu[c]) * rstd[c]);
    }
}

// ---------------- loss ----------------
__global__ void k_pesum(const int* __restrict__ ids, int nids, const int* __restrict__ src,
                        const int* __restrict__ dst, const float* __restrict__ el,
                        const float* __restrict__ er, const float* __restrict__ s, float* out8) {
    float acc[HH];
#pragma unroll
    for (int h = 0; h < HH; h++) acc[h] = 0.f;
    for (int i = blockIdx.x * blockDim.x + threadIdx.x; i < nids; i += gridDim.x * blockDim.x) {
        int e = ids[i];
        int se = src[e] * HH, de = dst[e] * HH;
#pragma unroll
        for (int h = 0; h < HH; h++) {
            float v = el[se + h] + er[de + h];
            v = v > 0.f ? v : NEG_SLOPE * v;
            acc[h] += expf(v) / s[de + h];
        }
    }
#pragma unroll
    for (int h = 0; h < HH; h++)
#pragma unroll
        for (int o = 16; o; o >>= 1) acc[h] += __shfl_down_sync(0xffffffffu, acc[h], o);
    if ((threadIdx.x & 31) == 0)
#pragma unroll
        for (int h = 0; h < HH; h++) atomicAdd(&out8[h], acc[h]);
}
__global__ void k_loss(const float* pe, const float* de, const int* lenp, float* out) {
    float sum = 0.f;
#pragma unroll
    for (int h = 0; h < HH; h++) sum += pe[h] - de[h];
    out[0] = -sum / (8.0f * (float)lenp[0]);
}

// ---------------- host ----------------
static inline int cdiv(long long a, long long b) { return (int)((a + b - 1) / b); }

extern "C" void kernel_launch(void* const* d_in, const int* in_sizes, int n_in, void* d_out,
                              int out_size) {
    const float* h_da_last = (const float*)d_in[0];
    const float* h_q_last  = (const float*)d_in[1];
    const float* h_da_0    = (const float*)d_in[2];
    const float* h_q_0     = (const float*)d_in[3];
    const float* W_L       = (const float*)d_in[4];
    const float* b_L       = (const float*)d_in[5];
    const float* gateq_W   = (const float*)d_in[6];
    const float* gateq_b   = (const float*)d_in[7];
    const float* gate1_W   = (const float*)d_in[8];
    const float* gate1_b   = (const float*)d_in[9];
    const float* gate2_W   = (const float*)d_in[10];
    const float* gate2_b   = (const float*)d_in[11];
    const float* Q_comb    = (const float*)d_in[12];
    const float* Qf_W1     = (const float*)d_in[13];
    const float* Qf_b1     = (const float*)d_in[14];
    const float* Qf_W2     = (const float*)d_in[15];
    const float* Qf_b2     = (const float*)d_in[16];
    const float* end_W1    = (const float*)d_in[17];
    const float* end_b1    = (const float*)d_in[18];
    const float* end_W2    = (const float*)d_in[19];
    const float* end_b2    = (const float*)d_in[20];
    const int* src_da = (const int*)d_in[21];
    const int* dst_da = (const int*)d_in[22];
    const int* src_q  = (const int*)d_in[23];
    const int* dst_q  = (const int*)d_in[24];
    const int* gid_da = (const int*)d_in[25];
    const int* gid_q  = (const int*)d_in[26];
    const int* PEid   = (const int*)d_in[27];
    const int* DEid   = (const int*)d_in[28];
    const int* lenp   = (const int*)d_in[29];
    int nPE = in_sizes[27], nDE = in_sizes[28];

    float* out = (float*)d_out;
    float* out_da = out;
    float* out_q = out + (long long)NDA * HD;
    float* out_loss = out + (long long)NDA * HD + (long long)NQ * HD;

    float *feat, *featq, *ft, *agg, *y1, *y2, *el, *er, *ss, *eb;
    float *glq, *t1, *t2, *Qb, *gsumq, *accq, *accda, *aabq, *aabda, *mu, *rstd, *pe, *de;
    double* dstat;
    int *deg, *coff, *cursor, *eid, *bsum, *degq, *coffq, *cursorq, *eidq, *bsumq;
    cudaGetSymbolAddress((void**)&feat, g_feat);
    cudaGetSymbolAddress((void**)&featq, g_featq);
    cudaGetSymbolAddress((void**)&ft, g_ft);
    cudaGetSymbolAddress((void**)&agg, g_agg);
    cudaGetSymbolAddress((void**)&y1, g_y1);
    cudaGetSymbolAddress((void**)&y2, g_y2);
    cudaGetSymbolAddress((void**)&el, g_el);
    cudaGetSymbolAddress((void**)&er, g_er);
    cudaGetSymbolAddress((void**)&ss, g_s);
    cudaGetSymbolAddress((void**)&eb, g_eb);
    cudaGetSymbolAddress((void**)&glq, g_glq);
    cudaGetSymbolAddress((void**)&t1, g_t1);
    cudaGetSymbolAddress((void**)&t2, g_t2);
    cudaGetSymbolAddress((void**)&Qb, g_Q);
    cudaGetSymbolAddress((void**)&gsumq, g_gsumq);
    cudaGetSymbolAddress((void**)&accq, g_accq);
    cudaGetSymbolAddress((void**)&accda, g_accda);
    cudaGetSymbolAddress((void**)&aabq, g_aabq);
    cudaGetSymbolAddress((void**)&aabda, g_aabda);
    cudaGetSymbolAddress((void**)&mu, g_mu);
    cudaGetSymbolAddress((void**)&rstd, g_rstd);
    cudaGetSymbolAddress((void**)&pe, g_pe);
    cudaGetSymbolAddress((void**)&de, g_de);
    cudaGetSymbolAddress((void**)&dstat, g_dstat);
    cudaGetSymbolAddress((void**)&deg, g_deg);
    cudaGetSymbolAddress((void**)&coff, g_coff);
    cudaGetSymbolAddress((void**)&cursor, g_cursor);
    cudaGetSymbolAddress((void**)&eid, g_eid);
    cudaGetSymbolAddress((void**)&bsum, g_bsum);
    cudaGetSymbolAddress((void**)&degq, g_degq);
    cudaGetSymbolAddress((void**)&coffq, g_coffq);
    cudaGetSymbolAddress((void**)&cursorq, g_cursorq);
    cudaGetSymbolAddress((void**)&eidq, g_eidq);
    cudaGetSymbolAddress((void**)&bsumq, g_bsumq);

    cudaFuncSetAttribute(k_gemm<0, 0>, cudaFuncAttributeMaxDynamicSharedMemorySize, SMEM_G0);
    cudaFuncSetAttribute(k_gemm<0, 1>, cudaFuncAttributeMaxDynamicSharedMemorySize, SMEM_G0);
    cudaFuncSetAttribute(k_gemm<1, 0>, cudaFuncAttributeMaxDynamicSharedMemorySize, SMEM_G1);
    cudaFuncSetAttribute(k_gemm<2, 1>, cudaFuncAttributeMaxDynamicSharedMemorySize, SMEM_G1);

    // 1-5: independent prep (launch #6 = da feat GEMM for ncu -s 5 -c 1)
    k_zero0<<<cdiv(NDA, 256), 256>>>(glq, gsumq, accq, accda, pe, de, deg, degq, dstat);
    k_gapq<<<cdiv(NQ, 32), 1024>>>(h_q_last, gateq_W, gateq_b, gid_q, eb, gsumq, NQ);
    k_gap_pool<<<cdiv((long long)NQ * 32, 256), 256>>>(h_q_last, gid_q, eb, gsumq, glq, NQ);
    k_gapdots<<<cdiv(NDA, 32), 1024>>>(h_da_0, h_da_last, gate1_W, gate1_b, gate2_W, gate2_b,
                                       Q_comb, gid_da, accda, NDA);
    k_hist<<<cdiv(EDA, 256), 256>>>(dst_da, deg, EDA);
    k_gemm<0, 0><<<dim3(1, cdiv(NDA, 128)), 256, SMEM_G0>>>(h_da_last, nullptr, nullptr, nullptr,
                                                            W_L, b_L, nullptr, nullptr, feat,
                                                            nullptr, NDA, 128, 128);
    k_gemm<0, 0><<<dim3(1, cdiv(NQ, 128)), 256, SMEM_G0>>>(h_q_last, nullptr, nullptr, nullptr,
                                                           W_L, b_L, nullptr, nullptr, featq,
                                                           nullptr, NQ, 128, 128);
    k_gapdots<<<cdiv(NQ, 32), 1024>>>(h_q_0, h_q_last, gate1_W, gate1_b, gate2_W, gate2_b, Q_comb,
                                      gid_q, accq, NQ);
    k_scan1<<<cdiv(NDA, 512), 256>>>(deg, coff, bsum, NDA);
    k_scan2<<<1, 256>>>(bsum, cdiv(NDA, 512));
    k_scan3<<<cdiv(NDA, 256), 256>>>(coff, cursor, bsum, NDA);
    k_scatter<<<cdiv(EDA, 256), 256>>>(dst_da, cursor, eid, EDA);
    k_hist<<<cdiv(EQ, 256), 256>>>(dst_q, degq, EQ);
    k_scan1<<<cdiv(NQ, 512), 256>>>(degq, coffq, bsumq, NQ);
    k_scan2<<<1, 256>>>(bsumq, cdiv(NQ, 512));
    k_scan3<<<cdiv(NQ, 256), 256>>>(coffq, cursorq, bsumq, NQ);
    k_scatter<<<cdiv(EQ, 256), 256>>>(dst_q, cursorq, eidq, EQ);
    k_comb2x<<<1, 128>>>(accq, aabq, accda, aabda);

    // Qf FNN -> Qb
    k_gemm<0, 1><<<dim3(2, 1), 256, SMEM_G0>>>(glq, nullptr, nullptr, nullptr, Qf_W1, Qf_b1,
                                               nullptr, nullptr, t1, dstat, BB, 128, 256);
    k_bnfin<<<1, 256>>>(dstat, BB, mu, rstd);
    k_gemm<2, 1><<<dim3(2, 1), 256, SMEM_G1>>>(t1, nullptr, nullptr, nullptr, Qf_W2, Qf_b2, mu,
                                               rstd, t2, dstat, BB, 256, 256);
    k_bnfin<<<1, 256>>>(dstat, BB, mu, rstd);
    k_bnelu<<<cdiv(BB * 256, 256), 256>>>(t2, mu, rstd, Qb, (long long)BB * 256, 256);

    // ---- q branch ----
    k_gemm<1, 0><<<dim3(1, cdiv(NQ, 128)), 256, SMEM_G1>>>(h_q_0, h_q_last, aabq, gid_q, W_L, b_L,
                                                           nullptr, nullptr, ft, nullptr, NQ, 128,
                                                           128);
    k_eler<<<cdiv((long long)NQ * HH, 256), 256>>>(featq, Qb, gid_q, el, er, NQ);
    k_node_agg<<<cdiv((long long)NQ * 32, 256), 256>>>(src_q, eidq, coffq, degq, el, er, ft, agg,
                                                       ss, NQ);
    k_gemm<0, 1><<<dim3(2, cdiv(NQ, 128)), 256, SMEM_G0>>>(agg, nullptr, nullptr, nullptr, end_W1,
                                                           end_b1, nullptr, nullptr, y1, dstat,
                                                           NQ, 128, 256);
    k_bnfin<<<1, 256>>>(dstat, NQ, mu, rstd);
    k_gemm<2, 1><<<dim3(1, cdiv(NQ, 128)), 256, SMEM_G1>>>(y1, nullptr, nullptr, nullptr, end_W2,
                                                           end_b2, mu, rstd, y2, dstat, NQ, 256,
                                                           128);
    k_bnfin<<<1, 128>>>(dstat, NQ, mu, rstd);
    k_final<<<cdiv((long long)NQ * HD, 256), 256>>>(h_q_last, y2, mu, rstd, out_q,
                                                    (long long)NQ * HD);

    // ---- da branch ----
    k_gemm<1, 0><<<dim3(1, cdiv(NDA, 128)), 256, SMEM_G1>>>(h_da_0, h_da_last, aabda, gid_da, W_L,
                                                            b_L, nullptr, nullptr, ft, nullptr,
                                                            NDA, 128, 128);
    k_eler<<<cdiv((long long)NDA * HH, 256), 256>>>(feat, Qb, gid_da, el, er, NDA);
    k_node_agg<<<cdiv((long long)NDA * 32, 256), 256>>>(src_da, eid, coff, deg, el, er, ft, agg,
                                                        ss, NDA);
    k_gemm<0, 1><<<dim3(2, cdiv(NDA, 128)), 256, SMEM_G0>>>(agg, nullptr, nullptr, nullptr,
                                                            end_W1, end_b1, nullptr, nullptr, y1,
                                                            dstat, NDA, 128, 256);
    k_bnfin<<<1, 256>>>(dstat, NDA, mu, rstd);
    k_gemm<2, 1><<<dim3(1, cdiv(NDA, 128)), 256, SMEM_G1>>>(y1, nullptr, nullptr, nullptr, end_W2,
                                                            end_b2, mu, rstd, y2, dstat, NDA, 256,
                                                            128);
    k_bnfin<<<1, 128>>>(dstat, NDA, mu, rstd);
    k_final<<<cdiv((long long)NDA * HD, 256), 256>>>(h_da_last, y2, mu, rstd, out_da,
                                                     (long long)NDA * HD);

    // ---- loss ----
    k_pesum<<<256, 256>>>(PEid, nPE, src_da, dst_da, el, er, ss, pe);
    k_pesum<<<256, 256>>>(DEid, nDE, src_da, dst_da, el, er, ss, de);
    k_loss<<<1, 1>>>(pe, de, lenp, out_loss);
}

// round 9
// speedup vs baseline: 3.3843x; 1.1129x over previous
#include <cuda_runtime.h>
#include <math.h>
#include <stdint.h>

#define NDA 100000
#define NQ  20000
#define EDA 1000000
#define EQ  200000
#define BB  64
#define HH  8
#define HD  128
#define HD2 256
#define NEG_SLOPE 2.0f

// ---------------- scratch ----------------
__device__ float g_feat[(size_t)NDA * HD];
__device__ float g_featq[(size_t)NQ * HD];
__device__ float g_ft[(size_t)NDA * HD];
__device__ float g_ftq[(size_t)NQ * HD];
__device__ float g_agg[(size_t)NDA * HD];
__device__ float g_aggq[(size_t)NQ * HD];
__device__ float g_y1[(size_t)NDA * HD2];
__device__ float g_y1q[(size_t)NQ * HD2];
__device__ float g_y2[(size_t)NDA * HD];
__device__ float g_y2q[(size_t)NQ * HD];
__device__ float g_el[NDA * HH];
__device__ float g_er[NDA * HH];
__device__ float g_s[NDA * HH];
__device__ float g_elq[NQ * HH];
__device__ float g_erq[NQ * HH];
__device__ float g_sq2[NQ * HH];
__device__ float g_eb[NQ];
__device__ int   g_deg[NDA];
__device__ int   g_coff[NDA];
__device__ int   g_cursor[NDA];
__device__ int   g_srcs[EDA];
__device__ int   g_bsum[256];
__device__ int   g_degq[NQ];
__device__ int   g_coffq[NQ];
__device__ int   g_cursorq[NQ];
__device__ int   g_srcsq[EQ];
__device__ int   g_bsumq[256];
__device__ float g_glq[BB * HD];
__device__ float g_t1[BB * HD2];
__device__ float g_t2[BB * HD2];
__device__ float g_Q[BB * HD2];
__device__ float g_gsumq[BB];
__device__ float g_accq[BB * 4];
__device__ float g_accda[BB * 4];
__device__ float g_aabq[BB * 2];
__device__ float g_aabda[BB * 2];
__device__ double g_dstat[1024];
__device__ float g_mu[512];
__device__ float g_rstd[512];
__device__ float g_pe[HH];
__device__ float g_de[HH];

__device__ __forceinline__ float eluf(float x) { return x > 0.f ? x : expm1f(x); }

__device__ __forceinline__ uint32_t smem_u32(const void* p) {
    uint32_t a;
    asm("{ .reg .u64 t; cvta.to.shared.u64 t, %1; cvt.u32.u64 %0, t; }" : "=r"(a) : "l"(p));
    return a;
}
__device__ __forceinline__ uint32_t f2tf(float x) {
    uint32_t r;
    asm("cvt.rna.tf32.f32 %0, %1;" : "=r"(r) : "f"(x));
    return r;
}
__device__ __forceinline__ void mma8(float* d, const uint32_t* a, const uint32_t* b) {
    asm volatile(
        "mma.sync.aligned.m16n8k8.row.col.f32.tf32.tf32.f32 "
        "{%0,%1,%2,%3}, {%4,%5,%6,%7}, {%8,%9}, {%0,%1,%2,%3};\n"
        : "+f"(d[0]), "+f"(d[1]), "+f"(d[2]), "+f"(d[3])
        : "r"(a[0]), "r"(a[1]), "r"(a[2]), "r"(a[3]), "r"(b[0]), "r"(b[1]));
}

// ---------------- pipelined TF32 GEMM, two-branch batched ----------------
#define AOFF(buf) ((buf) * 4608)
#define WOFF(buf) (9216 + (buf) * 4224)
#define A2OFF(buf) (17664 + (buf) * 4608)
#define SMEM_G0 ((9216 + 8448) * 4)
#define SMEM_G1 ((9216 + 8448 + 9216) * 4)

template <int AMODE>
__device__ __forceinline__ void stage_issue(uint32_t sb, int buf, const float* __restrict__ A,
                                            const float* __restrict__ A2,
                                            const float* __restrict__ W, int rowBase, int colBase,
                                            int k0, int n, int K, int NC, int tid) {
    uint32_t abase = sb + AOFF(buf) * 4;
    uint32_t wbase = sb + WOFF(buf) * 4;
#pragma unroll
    for (int q = 0; q < 4; q++) {
        int id = tid + q * 256;
        int r = id >> 3, kq = id & 7;
        int grow = rowBase + r;
        const float* src = A + (size_t)grow * K + k0 + kq * 4;
        uint32_t dst = abase + (r * 36 + kq * 4) * 4;
        int sz = grow < n ? 16 : 0;
        asm volatile("cp.async.ca.shared.global [%0], [%1], 16, %2;" ::"r"(dst), "l"(src), "r"(sz)
                     : "memory");
    }
    if (AMODE == 1) {
        uint32_t a2base = sb + A2OFF(buf) * 4;
#pragma unroll
        for (int q = 0; q < 4; q++) {
            int id = tid + q * 256;
            int r = id >> 3, kq = id & 7;
            int grow = rowBase + r;
            const float* src = A2 + (size_t)grow * K + k0 + kq * 4;
            uint32_t dst = a2base + (r * 36 + kq * 4) * 4;
            int sz = grow < n ? 16 : 0;
            asm volatile("cp.async.ca.shared.global [%0], [%1], 16, %2;" ::"r"(dst), "l"(src),
                         "r"(sz)
                         : "memory");
        }
    }
#pragma unroll
    for (int q = 0; q < 4; q++) {
        int id = tid + q * 256;
        int kk = id >> 5, nq = id & 31;
        const float* src = W + (size_t)(k0 + kk) * NC + colBase + nq * 4;
        uint32_t dst = wbase + (kk * 132 + nq * 4) * 4;
        asm volatile("cp.async.ca.shared.global [%0], [%1], 16;" ::"r"(dst), "l"(src) : "memory");
    }
    asm volatile("cp.async.commit_group;" ::: "memory");
}

template <int AMODE, int STAT>
__global__ void __launch_bounds__(256, 2) k_gemm(
    const float* __restrict__ A1a, const float* __restrict__ A2a,
    const float* __restrict__ aca, const int* __restrict__ gia,
    const float* __restrict__ A1b, const float* __restrict__ A2b,
    const float* __restrict__ acb, const int* __restrict__ gib,
    const float* __restrict__ W, const float* __restrict__ bias,
    const float* __restrict__ mu0, const float* __restrict__ rstd0,
    const float* __restrict__ mu1, const float* __restrict__ rstd1,
    float* Ca, float* Cb, double* ds0, double* ds1,
    int na, int nb, int yb, int K, int NC) {
    extern __shared__ float smf[];
    __shared__ float sstat[256];
    const uint32_t sb = smem_u32(smf);
    const int tid = threadIdx.x;
    const int lane = tid & 31;
    const int wid = tid >> 5;
    const int warp_m = wid >> 2;
    const int warp_n = wid & 3;

    int by = blockIdx.y;
    const float *A1, *A2, *acoef, *mu, *rstd;
    const int* gid;
    float* C;
    double* dstat;
    int n;
    if (by < yb) {
        A1 = A1a; A2 = A2a; acoef = aca; gid = gia; C = Ca; dstat = ds0; n = na;
        mu = mu0; rstd = rstd0;
    } else {
        by -= yb;
        A1 = A1b; A2 = A2b; acoef = acb; gid = gib; C = Cb; dstat = ds1; n = nb;
        mu = mu1; rstd = rstd1;
    }
    const int rowBase = by * 128;
    const int colBase = blockIdx.x * 128;
    const int g4 = lane >> 2;
    const int t4 = lane & 3;

    if (STAT && tid < 256) sstat[tid] = 0.f;

    float c0 = 0.f, c1 = 0.f;
    if (AMODE == 1) {
        int rr = rowBase + (tid >> 1);
        if (rr < n) {
            int g = gid[rr];
            c0 = acoef[2 * g];
            c1 = acoef[2 * g + 1];
        }
    }

    stage_issue<AMODE>(sb, 0, A1, A2, W, rowBase, colBase, 0, n, K, NC, tid);
    stage_issue<AMODE>(sb, 1, A1, A2, W, rowBase, colBase, 32, n, K, NC, tid);

    float acc[4][4][4];
#pragma unroll
    for (int mi = 0; mi < 4; mi++)
#pragma unroll
        for (int ni = 0; ni < 4; ni++)
#pragma unroll
            for (int r = 0; r < 4; r++) acc[mi][ni][r] = 0.f;

    const int nk = K >> 5;
    for (int i = 0; i < nk; i++) {
        int p = i & 1;
        if (i + 1 < nk)
            asm volatile("cp.async.wait_group 1;" ::: "memory");
        else
            asm volatile("cp.async.wait_group 0;" ::: "memory");
        __syncthreads();
        if (AMODE == 1) {
            float* a = smf + AOFF(p) + (tid >> 1) * 36 + (tid & 1) * 16;
            const float* b2 = smf + A2OFF(p) + (tid >> 1) * 36 + (tid & 1) * 16;
#pragma unroll
            for (int j = 0; j < 16; j++) a[j] = c0 * a[j] + c1 * b2[j];
            __syncthreads();
        } else if (AMODE == 2) {
            int kg = i * 32 + (tid & 1) * 16;
            float* a = smf + AOFF(p) + (tid >> 1) * 36 + (tid & 1) * 16;
#pragma unroll
            for (int j = 0; j < 16; j++) a[j] = eluf((a[j] - mu[kg + j]) * rstd[kg + j]);
            __syncthreads();
        }
        const float* Af = smf + AOFF(p);
        const float* Wf = smf + WOFF(p);
#pragma unroll
        for (int ks = 0; ks < 4; ks++) {
            int kk = ks * 8;
            uint32_t a[4][4];
#pragma unroll
            for (int mi = 0; mi < 4; mi++) {
                int r = warp_m * 64 + mi * 16 + g4;
                a[mi][0] = f2tf(Af[r * 36 + kk + t4]);
                a[mi][1] = f2tf(Af[(r + 8) * 36 + kk + t4]);
                a[mi][2] = f2tf(Af[r * 36 + kk + t4 + 4]);
                a[mi][3] = f2tf(Af[(r + 8) * 36 + kk + t4 + 4]);
            }
            uint32_t b[4][2];
#pragma unroll
            for (int ni = 0; ni < 4; ni++) {
                int c = warp_n * 32 + ni * 8 + g4;
                b[ni][0] = f2tf(Wf[(kk + t4) * 132 + c]);
                b[ni][1] = f2tf(Wf[(kk + t4 + 4) * 132 + c]);
            }
#pragma unroll
            for (int mi = 0; mi < 4; mi++)
#pragma unroll
                for (int ni = 0; ni < 4; ni++) mma8(acc[mi][ni], a[mi], b[ni]);
        }
        __syncthreads();
        if (i + 2 < nk)
            stage_issue<AMODE>(sb, p, A1, A2, W, rowBase, colBase, (i + 2) * 32, n, K, NC, tid);
    }

    float cs[8], cq[8];
#pragma unroll
    for (int i = 0; i < 8; i++) { cs[i] = 0.f; cq[i] = 0.f; }

#pragma unroll
    for (int mi = 0; mi < 4; mi++) {
        int r0 = rowBase + warp_m * 64 + mi * 16 + g4;
        int r1 = r0 + 8;
#pragma unroll
        for (int ni = 0; ni < 4; ni++) {
            int c = colBase + warp_n * 32 + ni * 8 + t4 * 2;
            float b0 = bias[c], b1 = bias[c + 1];
            if (r0 < n) {
                float v0 = acc[mi][ni][0] + b0, v1 = acc[mi][ni][1] + b1;
                C[(size_t)r0 * NC + c] = v0;
                C[(size_t)r0 * NC + c + 1] = v1;
                if (STAT) {
                    cs[ni * 2] += v0; cq[ni * 2] += v0 * v0;
                    cs[ni * 2 + 1] += v1; cq[ni * 2 + 1] += v1 * v1;
                }
            }
            if (r1 < n) {
                float v2 = acc[mi][ni][2] + b0, v3 = acc[mi][ni][3] + b1;
                C[(size_t)r1 * NC + c] = v2;
                C[(size_t)r1 * NC + c + 1] = v3;
                if (STAT) {
                    cs[ni * 2] += v2; cq[ni * 2] += v2 * v2;
                    cs[ni * 2 + 1] += v3; cq[ni * 2 + 1] += v3 * v3;
                }
            }
        }
    }
    if (STAT) {
#pragma unroll
        for (int i = 0; i < 8; i++) {
            float s = cs[i], q = cq[i];
            s += __shfl_down_sync(0xffffffffu, s, 16);
            q += __shfl_down_sync(0xffffffffu, q, 16);
            s += __shfl_down_sync(0xffffffffu, s, 8);
            q += __shfl_down_sync(0xffffffffu, q, 8);
            s += __shfl_down_sync(0xffffffffu, s, 4);
            q += __shfl_down_sync(0xffffffffu, q, 4);
            if (g4 == 0) {
                int c = warp_n * 32 + (i >> 1) * 8 + t4 * 2 + (i & 1);
                atomicAdd(&sstat[c], s);
                atomicAdd(&sstat[128 + c], q);
            }
        }
        __syncthreads();
        if (tid < 128) {
            atomicAdd(&dstat[colBase + tid], (double)sstat[tid]);
            atomicAdd(&dstat[256 + colBase + tid], (double)sstat[128 + tid]);
        }
    }
}

// ---------------- fills ----------------
__global__ void k_zero0(float* glq, float* gsumq, float* accq, float* accda, float* pe, float* de,
                        int* dga, int* dgb, double* dstat) {
    int i = blockIdx.x * blockDim.x + threadIdx.x;
    if (i < NDA) dga[i] = 0;
    if (i < NQ) dgb[i] = 0;
    if (i < BB * HD) glq[i] = 0.f;
    if (i < BB) gsumq[i] = 0.f;
    if (i < BB * 4) { accq[i] = 0.f; accda[i] = 0.f; }
    if (i < HH) { pe[i] = 0.f; de[i] = 0.f; }
    if (i < 1024) dstat[i] = 0.0;
}

// ---------------- gate kernels ----------------
__global__ void __launch_bounds__(1024) k_gapq(const float* __restrict__ M,
                                               const float* __restrict__ w,
                                               const float* __restrict__ b,
                                               const int* __restrict__ gid, float* ebuf,
                                               float* gsum, int n) {
    __shared__ int sgid[32];
    __shared__ float se[32];
    int wid = threadIdx.x >> 5, lane = threadIdx.x & 31;
    int node = blockIdx.x * 32 + wid;
    if (node < n) {
        float4 a = ((const float4*)(M + (size_t)node * HD))[lane];
        float4 wv = ((const float4*)w)[lane];
        float s = a.x * wv.x + a.y * wv.y + a.z * wv.z + a.w * wv.w;
#pragma unroll
        for (int o = 16; o; o >>= 1) s += __shfl_down_sync(0xffffffffu, s, o);
        if (lane == 0) {
            float e = expf(s + b[0]);
            ebuf[node] = e;
            sgid[wid] = gid[node];
            se[wid] = e;
        }
    } else if (lane == 0) sgid[wid] = -1;
    __syncthreads();
    if (threadIdx.x == 0) {
        int cur = -2;
        float a = 0.f;
        for (int i = 0; i < 32; i++) {
            int g = sgid[i];
            if (g < 0) continue;
            if (g != cur) { if (cur >= 0) atomicAdd(&gsum[cur], a); cur = g; a = 0.f; }
            a += se[i];
        }
        if (cur >= 0) atomicAdd(&gsum[cur], a);
    }
}

__global__ void k_gap_pool(const float* __restrict__ M, const int* __restrict__ gid,
                           const float* __restrict__ e, const float* __restrict__ gsum,
                           float* pool, int n) {
    int w = (blockIdx.x * blockDim.x + threadIdx.x) >> 5;
    int lane = threadIdx.x & 31;
    if (w >= n) return;
    int b = gid[w];
    float wt = e[w] / gsum[b];
    const float* row = M + (size_t)w * HD;
#pragma unroll
    for (int j = lane; j < HD; j += 32) atomicAdd(&pool[b * HD + j], wt * row[j]);
}

// batched gate dots: blocks [0,ybreak) da, rest q (both node counts divide by 32)
__global__ void __launch_bounds__(1024) k_gapdots_b(
    const float* __restrict__ h0a, const float* __restrict__ hla, const int* __restrict__ gia,
    float* acca,
    const float* __restrict__ h0b, const float* __restrict__ hlb, const int* __restrict__ gib,
    float* accb,
    const float* __restrict__ w1, const float* __restrict__ b1, const float* __restrict__ w2,
    const float* __restrict__ b2, const float* __restrict__ qc, int ybreak) {
    __shared__ int sgid[32];
    __shared__ float sv[32][4];
    const float *M1, *M2;
    const int* gid;
    float* acc;
    int nodeBase;
    if ((int)blockIdx.x < ybreak) {
        M1 = h0a; M2 = hla; gid = gia; acc = acca; nodeBase = blockIdx.x * 32;
    } else {
        M1 = h0b; M2 = hlb; gid = gib; acc = accb; nodeBase = (blockIdx.x - ybreak) * 32;
    }
    int wid = threadIdx.x >> 5, lane = threadIdx.x & 31;
    int node = nodeBase + wid;
    {
        float4 a = ((const float4*)(M1 + (size_t)node * HD))[lane];
        float4 bb = ((const float4*)(M2 + (size_t)node * HD))[lane];
        float4 w1v = ((const float4*)w1)[lane];
        float4 w2v = ((const float4*)w2)[lane];
        float4 qv = ((const float4*)qc)[lane];
        float s1 = a.x * w1v.x + a.y * w1v.y + a.z * w1v.z + a.w * w1v.w;
        float q1 = a.x * qv.x + a.y * qv.y + a.z * qv.z + a.w * qv.w;
        float s2 = bb.x * w2v.x + bb.y * w2v.y + bb.z * w2v.z + bb.w * w2v.w;
        float q2 = bb.x * qv.x + bb.y * qv.y + bb.z * qv.z + bb.w * qv.w;
#pragma unroll
        for (int o = 16; o; o >>= 1) {
            s1 += __shfl_down_sync(0xffffffffu, s1, o);
            q1 += __shfl_down_sync(0xffffffffu, q1, o);
            s2 += __shfl_down_sync(0xffffffffu, s2, o);
            q2 += __shfl_down_sync(0xffffffffu, q2, o);
        }
        if (lane == 0) {
            float e1 = expf(s1 + b1[0]), e2 = expf(s2 + b2[0]);
            sgid[wid] = gid[node];
            sv[wid][0] = e1; sv[wid][1] = e1 * q1; sv[wid][2] = e2; sv[wid][3] = e2 * q2;
        }
    }
    __syncthreads();
    if (threadIdx.x < 4) {
        int comp = threadIdx.x;
        int cur = -2;
        float a = 0.f;
        for (int i = 0; i < 32; i++) {
            int g = sgid[i];
            if (g != cur) { if (cur >= 0) atomicAdd(&acc[cur * 4 + comp], a); cur = g; a = 0.f; }
            a += sv[i][comp];
        }
        if (cur >= 0) atomicAdd(&acc[cur * 4 + comp], a);
    }
}

__global__ void k_comb2x(const float* __restrict__ accq, float* aabq,
                         const float* __restrict__ accda, float* aabda) {
    int t = threadIdx.x;
    const float* acc = t < BB ? accq : accda;
    float* aab = t < BB ? aabq : aabda;
    int b = t & (BB - 1);
    float d1 = acc[b * 4 + 1] / acc[b * 4 + 0];
    float d2 = acc[b * 4 + 3] / acc[b * 4 + 2];
    float mm = fmaxf(d1, d2);
    float e1 = expf(d1 - mm), e2 = expf(d2 - mm);
    float ss = e1 + e2;
    aab[2 * b] = e1 / ss;
    aab[2 * b + 1] = e2 / ss;
}

// batched eler
__global__ void k_eler_b(const float* __restrict__ feata, const int* __restrict__ gia, float* ela,
                         float* era, const float* __restrict__ featb,
                         const int* __restrict__ gib, float* elb, float* erb,
                         const float* __restrict__ Q, int na, int nb) {
    int idx = blockIdx.x * blockDim.x + threadIdx.x;
    const float* feat;
    const int* gid;
    float *el, *er;
    if (idx < na * HH) {
        feat = feata; gid = gia; el = ela; er = era;
    } else {
        idx -= na * HH;
        if (idx >= nb * HH) return;
        feat = featb; gid = gib; el = elb; er = erb;
    }
    int i = idx >> 3, h = idx & 7;
    const float* f = feat + (size_t)i * HD + h * 16;
    const float* q = Q + (size_t)gid[i] * HD2 + h * 32;
    float sl = 0.f, sr = 0.f;
#pragma unroll
    for (int c = 0; c < 16; c++) {
        float fv = f[c];
        sl = fmaf(fv, q[c], sl);
        sr = fmaf(fv, q[16 + c], sr);
    }
    el[idx] = sl;
    er[idx] = sr;
}

// ---------------- CSR build (batched) ----------------
__global__ void k_hist_b(const int* __restrict__ dsta, int* dga, const int* __restrict__ dstb,
                         int* dgb, int Ea, int Eb) {
    int e = blockIdx.x * blockDim.x + threadIdx.x;
    if (e < Ea) {
        atomicAdd(&dga[dsta[e]], 1);
    } else {
        e -= Ea;
        if (e < Eb) atomicAdd(&dgb[dstb[e]], 1);
    }
}
__global__ void k_scan1_b(const int* __restrict__ dga, int* coffa, int* bsuma,
                          const int* __restrict__ dgb, int* coffb, int* bsumb, int na, int nb,
                          int nba) {
    __shared__ int sh[512];
    const int* dg;
    int *outp, *bsum;
    int n, bid;
    if ((int)blockIdx.x < nba) { dg = dga; outp = coffa; bsum = bsuma; n = na; bid = blockIdx.x; }
    else { dg = dgb; outp = coffb; bsum = bsumb; n = nb; bid = blockIdx.x - nba; }
    int base = bid * 512, t = threadIdx.x;
    int v0 = (base + t < n) ? dg[base + t] : 0;
    int v1 = (base + 256 + t < n) ? dg[base + 256 + t] : 0;
    sh[t] = v0; sh[t + 256] = v1;
    __syncthreads();
    for (int off = 1; off < 512; off <<= 1) {
        int i0 = t, i1 = t + 256;
        int n0 = sh[i0] + ((i0 >= off) ? sh[i0 - off] : 0);
        int n1 = sh[i1] + ((i1 >= off) ? sh[i1 - off] : 0);
        __syncthreads();
        sh[i0] = n0; sh[i1] = n1;
        __syncthreads();
    }
    if (base + t < n) outp[base + t] = sh[t] - v0;
    if (base + 256 + t < n) outp[base + 256 + t] = sh[t + 256] - v1;
    if (t == 0) bsum[bid] = sh[511];
}
__global__ void k_scan2_b(int* bsuma, int nba, int* bsumb, int nbb) {
    __shared__ int sh[256];
    int* bsum = blockIdx.x == 0 ? bsuma : bsumb;
    int nb = blockIdx.x == 0 ? nba : nbb;
    int t = threadIdx.x;
    int v = (t < nb) ? bsum[t] : 0;
    sh[t] = v;
    __syncthreads();
    for (int off = 1; off < 256; off <<= 1) {
        int x = sh[t] + ((t >= off) ? sh[t - off] : 0);
        __syncthreads();
        sh[t] = x;
        __syncthreads();
    }
    if (t < nb) bsum[t] = sh[t] - v;
}
__global__ void k_scan3_b(int* coffa, int* cura, const int* __restrict__ bsuma, int* coffb,
                          int* curb, const int* __restrict__ bsumb, int na, int nb) {
    int i = blockIdx.x * blockDim.x + threadIdx.x;
    if (i < na) {
        int v = coffa[i] + bsuma[i >> 9];
        coffa[i] = v;
        cura[i] = v;
    } else {
        i -= na;
        if (i < nb) {
            int v = coffb[i] + bsumb[i >> 9];
            coffb[i] = v;
            curb[i] = v;
        }
    }
}
__global__ void k_scatter_b(const int* __restrict__ srca, const int* __restrict__ dsta, int* cura,
                            int* srcsa, const int* __restrict__ srcb,
                            const int* __restrict__ dstb, int* curb, int* srcsb, int Ea, int Eb) {
    int e = blockIdx.x * blockDim.x + threadIdx.x;
    if (e < Ea) {
        int p = atomicAdd(&cura[dsta[e]], 1);
        srcsa[p] = srca[e];
    } else {
        e -= Ea;
        if (e < Eb) {
            int p = atomicAdd(&curb[dstb[e]], 1);
            srcsb[p] = srcb[e];
        }
    }
}

// ---------------- batched single-pass edge softmax + aggregation ----------------
__global__ void k_node_agg_b(const int* __restrict__ srcsa, const int* __restrict__ coffa,
                             const int* __restrict__ dga, const float* __restrict__ ela,
                             const float* __restrict__ era, const float* __restrict__ fta,
                             float* agga, float* sa, const int* __restrict__ srcsb,
                             const int* __restrict__ coffb, const int* __restrict__ dgb,
                             const float* __restrict__ elb, const float* __restrict__ erb,
                             const float* __restrict__ ftb, float* aggb, float* sb2, int na,
                             int nb) {
    int w = (blockIdx.x * blockDim.x + threadIdx.x) >> 5;
    int lane = threadIdx.x & 31;
    const int *srcs, *coff, *dg;
    const float *el, *er, *ft;
    float *agg, *s;
    if (w < na) {
        srcs = srcsa; coff = coffa; dg = dga; el = ela; er = era; ft = fta; agg = agga; s = sa;
    } else {
        w -= na;
        if (w >= nb) return;
        srcs = srcsb; coff = coffb; dg = dgb; el = elb; er = erb; ft = ftb; agg = aggb; s = sb2;
    }
    int h = lane >> 2;
    int off = coff[w], d = dg[w];
    float erv = er[w * HH + h];
    float wsum = 0.f;
    float4 acc = make_float4(0.f, 0.f, 0.f, 0.f);
#pragma unroll 2
    for (int j = 0; j < d; j++) {
        int sn = srcs[off + j];
        float v = el[sn * HH + h] + erv;
        v = v > 0.f ? v : NEG_SLOPE * v;
        float wt = expf(v);
        wsum += wt;
        float4 fv = *(const float4*)(ft + (size_t)sn * HD + lane * 4);
        acc.x = fmaf(wt, fv.x, acc.x);
        acc.y = fmaf(wt, fv.y, acc.y);
        acc.z = fmaf(wt, fv.z, acc.z);
        acc.w = fmaf(wt, fv.w, acc.w);
    }
    float inv = wsum > 0.f ? 1.f / wsum : 0.f;
    acc.x *= inv; acc.y *= inv; acc.z *= inv; acc.w *= inv;
    *(float4*)(agg + (size_t)w * HD + lane * 4) = acc;
    if ((lane & 3) == 0) s[w * HH + h] = wsum;
}

// ---------------- bn finalize (two branches, self-zeroing) ----------------
__global__ void k_bnfin2(double* st0, int n0, float* mu0, float* rstd0, double* st1, int n1,
                         float* mu1, float* rstd1, int C) {
    int t = threadIdx.x;
    double* st;
    float *mu, *rstd;
    int n, c;
    if (t < C) { st = st0; mu = mu0; rstd = rstd0; n = n0; c = t; }
    else { st = st1; mu = mu1; rstd = rstd1; n = n1; c = t - C; }
    double m = st[c] / n;
    double v = st[256 + c] / n - m * m;
    if (v < 0.0) v = 0.0;
    mu[c] = (float)m;
    rstd[c] = (float)(1.0 / sqrt(v + 1e-5));
    st[c] = 0.0;
    st[256 + c] = 0.0;
}
__global__ void k_bnelu(const float* __restrict__ Y, const float* __restrict__ mu,
                        const float* __restrict__ rstd, float* outp, long long total, int C) {
    long long i = (long long)blockIdx.x * blockDim.x + threadIdx.x;
    if (i < total) {
        int c = (int)(i % C);
        outp[i] = eluf((Y[i] - mu[c]) * rstd[c]);
    }
}
__global__ void k_final_b(const float* __restrict__ hla, const float* __restrict__ y2a,
                          const float* __restrict__ mu0, const float* __restrict__ rstd0,
                          float* outa, const float* __restrict__ hlb,
                          const float* __restrict__ y2b, const float* __restrict__ mu1,
                          const float* __restrict__ rstd1, float* outb, long long ta,
                          long long tb) {
    long long i = (long long)blockIdx.x * blockDim.x + threadIdx.x;
    const float *hl, *Y, *mu, *rstd;
    float* outp;
    if (i < ta) { hl = hla; Y = y2a; mu = mu0; rstd = rstd0; outp = outa; }
    else {
        i -= ta;
        if (i >= tb) return;
        hl = hlb; Y = y2b; mu = mu1; rstd = rstd1; outp = outb;
    }
    int c = (int)(i & (HD - 1));
    outp[i] = hl[i] + eluf((Y[i] - mu[c]) * rstd[c]);
}

// ---------------- loss ----------------
__global__ void k_pesum_b(const int* __restrict__ peid, int npe, float* peout,
                          const int* __restrict__ deid, int nde, float* deout,
                          const int* __restrict__ src, const int* __restrict__ dst,
                          const float* __restrict__ el, const float* __restrict__ er,
                          const float* __restrict__ s) {
    const int* ids;
    float* out8;
    int nids, bid;
    int half = gridDim.x / 2;
    if ((int)blockIdx.x < half) { ids = peid; out8 = peout; nids = npe; bid = blockIdx.x; }
    else { ids = deid; out8 = deout; nids = nde; bid = blockIdx.x - half; }
    float acc[HH];
#pragma unroll
    for (int h = 0; h < HH; h++) acc[h] = 0.f;
    for (int i = bid * blockDim.x + threadIdx.x; i < nids; i += half * blockDim.x) {
        int e = ids[i];
        int se = src[e] * HH, de = dst[e] * HH;
#pragma unroll
        for (int h = 0; h < HH; h++) {
            float v = el[se + h] + er[de + h];
            v = v > 0.f ? v : NEG_SLOPE * v;
            acc[h] += expf(v) / s[de + h];
        }
    }
#pragma unroll
    for (int h = 0; h < HH; h++)
#pragma unroll
        for (int o = 16; o; o >>= 1) acc[h] += __shfl_down_sync(0xffffffffu, acc[h], o);
    if ((threadIdx.x & 31) == 0)
#pragma unroll
        for (int h = 0; h < HH; h++) atomicAdd(&out8[h], acc[h]);
}
__global__ void k_loss(const float* pe, const float* de, const int* lenp, float* outp) {
    float sum = 0.f;
#pragma unroll
    for (int h = 0; h < HH; h++) sum += pe[h] - de[h];
    outp[0] = -sum / (8.0f * (float)lenp[0]);
}

// ---------------- host ----------------
static inline int cdiv(long long a, long long b) { return (int)((a + b - 1) / b); }

extern "C" void kernel_launch(void* const* d_in, const int* in_sizes, int n_in, void* d_out,
                              int out_size) {
    const float* h_da_last = (const float*)d_in[0];
    const float* h_q_last  = (const float*)d_in[1];
    const float* h_da_0    = (const float*)d_in[2];
    const float* h_q_0     = (const float*)d_in[3];
    const float* W_L       = (const float*)d_in[4];
    const float* b_L       = (const float*)d_in[5];
    const float* gateq_W   = (const float*)d_in[6];
    const float* gateq_b   = (const float*)d_in[7];
    const float* gate1_W   = (const float*)d_in[8];
    const float* gate1_b   = (const float*)d_in[9];
    const float* gate2_W   = (const float*)d_in[10];
    const float* gate2_b   = (const float*)d_in[11];
    const float* Q_comb    = (const float*)d_in[12];
    const float* Qf_W1     = (const float*)d_in[13];
    const float* Qf_b1     = (const float*)d_in[14];
    const float* Qf_W2     = (const float*)d_in[15];
    const float* Qf_b2     = (const float*)d_in[16];
    const float* end_W1    = (const float*)d_in[17];
    const float* end_b1    = (const float*)d_in[18];
    const float* end_W2    = (const float*)d_in[19];
    const float* end_b2    = (const float*)d_in[20];
    const int* src_da = (const int*)d_in[21];
    const int* dst_da = (const int*)d_in[22];
    const int* src_q  = (const int*)d_in[23];
    const int* dst_q  = (const int*)d_in[24];
    const int* gid_da = (const int*)d_in[25];
    const int* gid_q  = (const int*)d_in[26];
    const int* PEid   = (const int*)d_in[27];
    const int* DEid   = (const int*)d_in[28];
    const int* lenp   = (const int*)d_in[29];
    int nPE = in_sizes[27], nDE = in_sizes[28];

    float* outp = (float*)d_out;
    float* out_da = outp;
    float* out_q = outp + (long long)NDA * HD;
    float* out_loss = outp + (long long)NDA * HD + (long long)NQ * HD;

    float *feat, *featq, *ft, *ftq, *agg, *aggq, *y1, *y1q, *y2, *y2q;
    float *el, *er, *ss, *elq, *erq, *sq2, *eb;
    float *glq, *t1, *t2, *Qb, *gsumq, *accq, *accda, *aabq, *aabda, *mu, *rstd, *pe, *de;
    double* dstat;
    int *dg, *coff, *cursor, *srcs, *bsum, *dgq, *coffq, *cursorq, *srcsq, *bsumq;
    cudaGetSymbolAddress((void**)&feat, g_feat);
    cudaGetSymbolAddress((void**)&featq, g_featq);
    cudaGetSymbolAddress((void**)&ft, g_ft);
    cudaGetSymbolAddress((void**)&ftq, g_ftq);
    cudaGetSymbolAddress((void**)&agg, g_agg);
    cudaGetSymbolAddress((void**)&aggq, g_aggq);
    cudaGetSymbolAddress((void**)&y1, g_y1);
    cudaGetSymbolAddress((void**)&y1q, g_y1q);
    cudaGetSymbolAddress((void**)&y2, g_y2);
    cudaGetSymbolAddress((void**)&y2q, g_y2q);
    cudaGetSymbolAddress((void**)&el, g_el);
    cudaGetSymbolAddress((void**)&er, g_er);
    cudaGetSymbolAddress((void**)&ss, g_s);
    cudaGetSymbolAddress((void**)&elq, g_elq);
    cudaGetSymbolAddress((void**)&erq, g_erq);
    cudaGetSymbolAddress((void**)&sq2, g_sq2);
    cudaGetSymbolAddress((void**)&eb, g_eb);
    cudaGetSymbolAddress((void**)&glq, g_glq);
    cudaGetSymbolAddress((void**)&t1, g_t1);
    cudaGetSymbolAddress((void**)&t2, g_t2);
    cudaGetSymbolAddress((void**)&Qb, g_Q);
    cudaGetSymbolAddress((void**)&gsumq, g_gsumq);
    cudaGetSymbolAddress((void**)&accq, g_accq);
    cudaGetSymbolAddress((void**)&accda, g_accda);
    cudaGetSymbolAddress((void**)&aabq, g_aabq);
    cudaGetSymbolAddress((void**)&aabda, g_aabda);
    cudaGetSymbolAddress((void**)&mu, g_mu);
    cudaGetSymbolAddress((void**)&rstd, g_rstd);
    cudaGetSymbolAddress((void**)&pe, g_pe);
    cudaGetSymbolAddress((void**)&de, g_de);
    cudaGetSymbolAddress((void**)&dstat, g_dstat);
    cudaGetSymbolAddress((void**)&dg, g_deg);
    cudaGetSymbolAddress((void**)&coff, g_coff);
    cudaGetSymbolAddress((void**)&cursor, g_cursor);
    cudaGetSymbolAddress((void**)&srcs, g_srcs);
    cudaGetSymbolAddress((void**)&bsum, g_bsum);
    cudaGetSymbolAddress((void**)&dgq, g_degq);
    cudaGetSymbolAddress((void**)&coffq, g_coffq);
    cudaGetSymbolAddress((void**)&cursorq, g_cursorq);
    cudaGetSymbolAddress((void**)&srcsq, g_srcsq);
    cudaGetSymbolAddress((void**)&bsumq, g_bsumq);

    double* dstat1 = dstat + 512;
    float* mu1 = mu + 256;
    float* rstd1 = rstd + 256;

    cudaFuncSetAttribute(k_gemm<0, 0>, cudaFuncAttributeMaxDynamicSharedMemorySize, SMEM_G0);
    cudaFuncSetAttribute(k_gemm<0, 1>, cudaFuncAttributeMaxDynamicSharedMemorySize, SMEM_G0);
    cudaFuncSetAttribute(k_gemm<1, 0>, cudaFuncAttributeMaxDynamicSharedMemorySize, SMEM_G1);
    cudaFuncSetAttribute(k_gemm<2, 1>, cudaFuncAttributeMaxDynamicSharedMemorySize, SMEM_G1);

    const int YDA = cdiv(NDA, 128), YQ = cdiv(NQ, 128);

    // 1-5: prep (launch #6 = batched feat GEMM for ncu -s 5 -c 1)
    k_zero0<<<cdiv(NDA, 256), 256>>>(glq, gsumq, accq, accda, pe, de, dg, dgq, dstat);
    k_gapq<<<cdiv(NQ, 32), 1024>>>(h_q_last, gateq_W, gateq_b, gid_q, eb, gsumq, NQ);
    k_gap_pool<<<cdiv((long long)NQ * 32, 256), 256>>>(h_q_last, gid_q, eb, gsumq, glq, NQ);
    k_gapdots_b<<<NDA / 32 + NQ / 32, 1024>>>(h_da_0, h_da_last, gid_da, accda, h_q_0, h_q_last,
                                              gid_q, accq, gate1_W, gate1_b, gate2_W, gate2_b,
                                              Q_comb, NDA / 32);
    k_hist_b<<<cdiv(EDA + EQ, 256), 256>>>(dst_da, dg, dst_q, dgq, EDA, EQ);
    k_gemm<0, 0><<<dim3(1, YDA + YQ), 256, SMEM_G0>>>(
        h_da_last, nullptr, nullptr, nullptr, h_q_last, nullptr, nullptr, nullptr, W_L, b_L,
        nullptr, nullptr, nullptr, nullptr, feat, featq, nullptr, nullptr, NDA, NQ, YDA, 128, 128);
    // CSR
    int NBA = cdiv(NDA, 512), NBB = cdiv(NQ, 512);
    k_scan1_b<<<NBA + NBB, 256>>>(dg, coff, bsum, dgq, coffq, bsumq, NDA, NQ, NBA);
    k_scan2_b<<<2, 256>>>(bsum, NBA, bsumq, NBB);
    k_scan3_b<<<cdiv(NDA + NQ, 256), 256>>>(coff, cursor, bsum, coffq, cursorq, bsumq, NDA, NQ);
    k_scatter_b<<<cdiv(EDA + EQ, 256), 256>>>(src_da, dst_da, cursor, srcs, src_q, dst_q, cursorq,
                                              srcsq, EDA, EQ);
    k_comb2x<<<1, 128>>>(accq, aabq, accda, aabda);

    // Qf FNN -> Qb (single-branch: yb covers all blocks)
    k_gemm<0, 1><<<dim3(2, 1), 256, SMEM_G0>>>(glq, nullptr, nullptr, nullptr, nullptr, nullptr,
                                               nullptr, nullptr, Qf_W1, Qf_b1, nullptr, nullptr,
                                               nullptr, nullptr, t1, nullptr, dstat, nullptr, BB,
                                               0, 1, 128, 256);
    k_bnfin2<<<1, 512>>>(dstat, BB, mu, rstd, dstat1, 1, mu1, rstd1, 256);
    k_gemm<2, 1><<<dim3(2, 1), 256, SMEM_G1>>>(t1, nullptr, nullptr, nullptr, nullptr, nullptr,
                                               nullptr, nullptr, Qf_W2, Qf_b2, mu, rstd, nullptr,
                                               nullptr, t2, nullptr, dstat, nullptr, BB, 0, 1,
                                               256, 256);
    k_bnfin2<<<1, 512>>>(dstat, BB, mu, rstd, dstat1, 1, mu1, rstd1, 256);
    k_bnelu<<<cdiv(BB * 256, 256), 256>>>(t2, mu, rstd, Qb, (long long)BB * 256, 256);

    // batched ft GEMM (AMODE1)
    k_gemm<1, 0><<<dim3(1, YDA + YQ), 256, SMEM_G1>>>(
        h_da_0, h_da_last, aabda, gid_da, h_q_0, h_q_last, aabq, gid_q, W_L, b_L, nullptr,
        nullptr, nullptr, nullptr, ft, ftq, nullptr, nullptr, NDA, NQ, YDA, 128, 128);
    // batched eler
    k_eler_b<<<cdiv((long long)(NDA + NQ) * HH, 256), 256>>>(feat, gid_da, el, er, featq, gid_q,
                                                             elq, erq, Qb, NDA, NQ);
    // batched node agg
    k_node_agg_b<<<cdiv((long long)(NDA + NQ) * 32, 256), 256>>>(
        srcs, coff, dg, el, er, ft, agg, ss, srcsq, coffq, dgq, elq, erq, ftq, aggq, sq2, NDA, NQ);
    // batched end_W1 GEMM + stats
    k_gemm<0, 1><<<dim3(2, YDA + YQ), 256, SMEM_G0>>>(
        agg, nullptr, nullptr, nullptr, aggq, nullptr, nullptr, nullptr, end_W1, end_b1, nullptr,
        nullptr, nullptr, nullptr, y1, y1q, dstat, dstat1, NDA, NQ, YDA, 128, 256);
    k_bnfin2<<<1, 512>>>(dstat, NDA, mu, rstd, dstat1, NQ, mu1, rstd1, 256);
    // batched end_W2 GEMM (AMODE2) + stats
    k_gemm<2, 1><<<dim3(1, YDA + YQ), 256, SMEM_G1>>>(
        y1, nullptr, nullptr, nullptr, y1q, nullptr, nullptr, nullptr, end_W2, end_b2, mu, rstd,
        mu1, rstd1, y2, y2q, dstat, dstat1, NDA, NQ, YDA, 256, 128);
    k_bnfin2<<<1, 256>>>(dstat, NDA, mu, rstd, dstat1, NQ, mu1, rstd1, 128);
    // batched final
    k_final_b<<<cdiv((long long)(NDA + NQ) * HD, 256), 256>>>(
        h_da_last, y2, mu, rstd, out_da, h_q_last, y2q, mu1, rstd1, out_q, (long long)NDA * HD,
        (long long)NQ * HD);

    // loss (da branch edge stats)
    k_pesum_b<<<256, 256>>>(PEid, nPE, pe, DEid, nDE, de, src_da, dst_da, el, er, ss);
    k_loss<<<1, 1>>>(pe, de, lenp, out_loss);
}

// round 10
// speedup vs baseline: 3.6947x; 1.0917x over previous
#include <cuda_runtime.h>
#include <math.h>
#include <stdint.h>

#define NDA 100000
#define NQ  20000
#define EDA 1000000
#define EQ  200000
#define BB  64
#define HH  8
#define HD  128
#define HD2 256
#define NEG_SLOPE 2.0f

// ---------------- scratch ----------------
__device__ float g_feat[(size_t)NDA * HD];
__device__ float g_featq[(size_t)NQ * HD];
__device__ float g_ft[(size_t)NDA * HD];
__device__ float g_ftq[(size_t)NQ * HD];
__device__ float g_agg[(size_t)NDA * HD];
__device__ float g_aggq[(size_t)NQ * HD];
__device__ float g_y1[(size_t)NDA * HD2];
__device__ float g_y1q[(size_t)NQ * HD2];
__device__ float g_y2[(size_t)NDA * HD];
__device__ float g_y2q[(size_t)NQ * HD];
__device__ float g_el[NDA * HH];
__device__ float g_er[NDA * HH];
__device__ float g_s[NDA * HH];
__device__ float g_elq[NQ * HH];
__device__ float g_erq[NQ * HH];
__device__ float g_sq2[NQ * HH];
__device__ float g_eb[NQ];
__device__ int   g_deg[NDA];
__device__ int   g_coff[NDA];
__device__ int   g_cursor[NDA];
__device__ int   g_srcs[EDA];
__device__ int   g_bsum[256];
__device__ int   g_degq[NQ];
__device__ int   g_coffq[NQ];
__device__ int   g_cursorq[NQ];
__device__ int   g_srcsq[EQ];
__device__ int   g_bsumq[256];
__device__ float g_glq[BB * HD];
__device__ float g_t1[BB * HD2];
__device__ float g_t2[BB * HD2];
__device__ float g_Q[BB * HD2];
__device__ float g_gsumq[BB];
__device__ float g_accq[BB * 4];
__device__ float g_accda[BB * 4];
__device__ float g_aabq[BB * 2];
__device__ float g_aabda[BB * 2];
__device__ double g_dstat[1024];
__device__ float g_mu[512];
__device__ float g_rstd[512];
__device__ float g_pe[HH];
__device__ float g_de[HH];

__device__ __forceinline__ float eluf(float x) { return x > 0.f ? x : expm1f(x); }

__device__ __forceinline__ uint32_t smem_u32(const void* p) {
    uint32_t a;
    asm("{ .reg .u64 t; cvta.to.shared.u64 t, %1; cvt.u32.u64 %0, t; }" : "=r"(a) : "l"(p));
    return a;
}
__device__ __forceinline__ uint32_t f2tf(float x) {
    uint32_t r;
    asm("cvt.rna.tf32.f32 %0, %1;" : "=r"(r) : "f"(x));
    return r;
}
__device__ __forceinline__ void mma8(float* d, const uint32_t* a, const uint32_t* b) {
    asm volatile(
        "mma.sync.aligned.m16n8k8.row.col.f32.tf32.tf32.f32 "
        "{%0,%1,%2,%3}, {%4,%5,%6,%7}, {%8,%9}, {%0,%1,%2,%3};\n"
        : "+f"(d[0]), "+f"(d[1]), "+f"(d[2]), "+f"(d[3])
        : "r"(a[0]), "r"(a[1]), "r"(a[2]), "r"(a[3]), "r"(b[0]), "r"(b[1]));
}

#define AOFF(buf) ((buf) * 4608)
#define WOFF(buf) (9216 + (buf) * 4224)
#define A2OFF(buf) (17664 + (buf) * 4608)
#define SMEM_G0 ((9216 + 8448) * 4)
#define SMEM_G1 ((9216 + 8448 + 9216) * 4)

__device__ __forceinline__ void stage_issue_r(uint32_t sb, int buf, const float* __restrict__ A,
                                              const float* __restrict__ A2, bool blend,
                                              const float* __restrict__ W, int rowBase,
                                              int colBase, int k0, int n, int K, int NC,
                                              int tid) {
    uint32_t abase = sb + AOFF(buf) * 4;
    uint32_t wbase = sb + WOFF(buf) * 4;
#pragma unroll
    for (int q = 0; q < 4; q++) {
        int id = tid + q * 256;
        int r = id >> 3, kq = id & 7;
        int grow = rowBase + r;
        const float* src = A + (size_t)grow * K + k0 + kq * 4;
        uint32_t dst = abase + (r * 36 + kq * 4) * 4;
        int sz = grow < n ? 16 : 0;
        asm volatile("cp.async.ca.shared.global [%0], [%1], 16, %2;" ::"r"(dst), "l"(src), "r"(sz)
                     : "memory");
    }
    if (blend) {
        uint32_t a2base = sb + A2OFF(buf) * 4;
#pragma unroll
        for (int q = 0; q < 4; q++) {
            int id = tid + q * 256;
            int r = id >> 3, kq = id & 7;
            int grow = rowBase + r;
            const float* src = A2 + (size_t)grow * K + k0 + kq * 4;
            uint32_t dst = a2base + (r * 36 + kq * 4) * 4;
            int sz = grow < n ? 16 : 0;
            asm volatile("cp.async.ca.shared.global [%0], [%1], 16, %2;" ::"r"(dst), "l"(src),
                         "r"(sz)
                         : "memory");
        }
    }
#pragma unroll
    for (int q = 0; q < 4; q++) {
        int id = tid + q * 256;
        int kk = id >> 5, nq = id & 31;
        const float* src = W + (size_t)(k0 + kk) * NC + colBase + nq * 4;
        uint32_t dst = wbase + (kk * 132 + nq * 4) * 4;
        asm volatile("cp.async.ca.shared.global [%0], [%1], 16;" ::"r"(dst), "l"(src) : "memory");
    }
    asm volatile("cp.async.commit_group;" ::: "memory");
}

// ---------------- mega W_L GEMM: 4 sub-problems + fused el/er for feat ----------------
// sub 0: feat da (AMODE0 + eler) ; 1: feat q (AMODE0 + eler)
// sub 2: ft da (blend) ; 3: ft q (blend).  K=NC=128, grid.x=1.
__global__ void __launch_bounds__(256, 2) k_gemmW(
    const float* __restrict__ hdl, const float* __restrict__ hql,
    const float* __restrict__ hd0, const float* __restrict__ hq0,
    const float* __restrict__ aabda, const float* __restrict__ aabq,
    const int* __restrict__ gid_da, const int* __restrict__ gid_q,
    const float* __restrict__ W, const float* __restrict__ bias,
    const float* __restrict__ Qb,
    float* feat, float* featq, float* ft, float* ftq,
    float* el, float* er, float* elq, float* erq, int YDA, int YQ) {
    extern __shared__ float smf[];
    const uint32_t sb = smem_u32(smf);
    const int tid = threadIdx.x;
    const int lane = tid & 31;
    const int wid = tid >> 5;
    const int warp_m = wid >> 2;
    const int warp_n = wid & 3;

    int by = blockIdx.y;
    const float *A1, *A2, *acoef;
    const int* gid;
    float *C, *elo, *ero;
    int n;
    bool blend;
    if (by < YDA) {
        A1 = hdl; A2 = nullptr; acoef = nullptr; gid = gid_da; C = feat; elo = el; ero = er;
        n = NDA; blend = false;
    } else if (by < YDA + YQ) {
        by -= YDA;
        A1 = hql; A2 = nullptr; acoef = nullptr; gid = gid_q; C = featq; elo = elq; ero = erq;
        n = NQ; blend = false;
    } else if (by < 2 * YDA + YQ) {
        by -= YDA + YQ;
        A1 = hd0; A2 = hdl; acoef = aabda; gid = gid_da; C = ft; elo = nullptr; ero = nullptr;
        n = NDA; blend = true;
    } else {
        by -= 2 * YDA + YQ;
        A1 = hq0; A2 = hql; acoef = aabq; gid = gid_q; C = ftq; elo = nullptr; ero = nullptr;
        n = NQ; blend = true;
    }
    const int rowBase = by * 128;
    const int g4 = lane >> 2;
    const int t4 = lane & 3;

    float c0 = 0.f, c1 = 0.f;
    if (blend) {
        int rr = rowBase + (tid >> 1);
        if (rr < n) {
            int g = gid[rr];
            c0 = acoef[2 * g];
            c1 = acoef[2 * g + 1];
        }
    }

    stage_issue_r(sb, 0, A1, A2, blend, W, rowBase, 0, 0, n, 128, 128, tid);
    stage_issue_r(sb, 1, A1, A2, blend, W, rowBase, 0, 32, n, 128, 128, tid);

    float acc[4][4][4];
#pragma unroll
    for (int mi = 0; mi < 4; mi++)
#pragma unroll
        for (int ni = 0; ni < 4; ni++)
#pragma unroll
            for (int r = 0; r < 4; r++) acc[mi][ni][r] = 0.f;

    const int nk = 4;
    for (int i = 0; i < nk; i++) {
        int p = i & 1;
        if (i + 1 < nk)
            asm volatile("cp.async.wait_group 1;" ::: "memory");
        else
            asm volatile("cp.async.wait_group 0;" ::: "memory");
        __syncthreads();
        if (blend) {
            float* a = smf + AOFF(p) + (tid >> 1) * 36 + (tid & 1) * 16;
            const float* b2 = smf + A2OFF(p) + (tid >> 1) * 36 + (tid & 1) * 16;
#pragma unroll
            for (int j = 0; j < 16; j++) a[j] = c0 * a[j] + c1 * b2[j];
            __syncthreads();
        }
        const float* Af = smf + AOFF(p);
        const float* Wf = smf + WOFF(p);
#pragma unroll
        for (int ks = 0; ks < 4; ks++) {
            int kk = ks * 8;
            uint32_t a[4][4];
#pragma unroll
            for (int mi = 0; mi < 4; mi++) {
                int r = warp_m * 64 + mi * 16 + g4;
                a[mi][0] = f2tf(Af[r * 36 + kk + t4]);
                a[mi][1] = f2tf(Af[(r + 8) * 36 + kk + t4]);
                a[mi][2] = f2tf(Af[r * 36 + kk + t4 + 4]);
                a[mi][3] = f2tf(Af[(r + 8) * 36 + kk + t4 + 4]);
            }
            uint32_t b[4][2];
#pragma unroll
            for (int ni = 0; ni < 4; ni++) {
                int c = warp_n * 32 + ni * 8 + g4;
                b[ni][0] = f2tf(Wf[(kk + t4) * 132 + c]);
                b[ni][1] = f2tf(Wf[(kk + t4 + 4) * 132 + c]);
            }
#pragma unroll
            for (int mi = 0; mi < 4; mi++)
#pragma unroll
                for (int ni = 0; ni < 4; ni++) mma8(acc[mi][ni], a[mi], b[ni]);
        }
        __syncthreads();
        if (i + 2 < nk)
            stage_issue_r(sb, p, A1, A2, blend, W, rowBase, 0, (i + 2) * 32, n, 128, 128, tid);
    }

    // epilogue: write C; feat sub-problems also stash the tile in smem for el/er
    float* sC = smf;  // 128 x 132, reuses stage buffers (all consumed)
#pragma unroll
    for (int mi = 0; mi < 4; mi++) {
        int lr0 = warp_m * 64 + mi * 16 + g4;
        int lr1 = lr0 + 8;
        int r0 = rowBase + lr0, r1 = rowBase + lr1;
#pragma unroll
        for (int ni = 0; ni < 4; ni++) {
            int c = warp_n * 32 + ni * 8 + t4 * 2;
            float b0 = bias[c], b1 = bias[c + 1];
            float v0 = acc[mi][ni][0] + b0, v1 = acc[mi][ni][1] + b1;
            float v2 = acc[mi][ni][2] + b0, v3 = acc[mi][ni][3] + b1;
            if (r0 < n) {
                C[(size_t)r0 * HD + c] = v0;
                C[(size_t)r0 * HD + c + 1] = v1;
            }
            if (r1 < n) {
                C[(size_t)r1 * HD + c] = v2;
                C[(size_t)r1 * HD + c + 1] = v3;
            }
            if (elo) {
                sC[lr0 * 132 + c] = v0;
                sC[lr0 * 132 + c + 1] = v1;
                sC[lr1 * 132 + c] = v2;
                sC[lr1 * 132 + c + 1] = v3;
            }
        }
    }
    if (elo) {
        __syncthreads();
        int il = tid >> 1;             // local row 0..127
        int hbase = (tid & 1) * 4;     // heads 0-3 or 4-7
        int grow = rowBase + il;
        if (grow < n) {
            int gg = gid[grow];
            const float* f = sC + il * 132;
#pragma unroll
            for (int hh = 0; hh < 4; hh++) {
                int h = hbase + hh;
                const float* q = Qb + (size_t)gg * HD2 + h * 32;
                float sl = 0.f, sr = 0.f;
#pragma unroll
                for (int c = 0; c < 16; c++) {
                    float fv = f[h * 16 + c];
                    sl = fmaf(fv, q[c], sl);
                    sr = fmaf(fv, q[16 + c], sr);
                }
                elo[grow * HH + h] = sl;
                ero[grow * HH + h] = sr;
            }
        }
    }
}

// ---------------- two-problem GEMM (Qf + end layers) ----------------
template <int AMODE, int STAT>
__global__ void __launch_bounds__(256, 2) k_gemm(
    const float* __restrict__ A1a, const float* __restrict__ A1b,
    const float* __restrict__ W, const float* __restrict__ bias,
    const float* __restrict__ mu0, const float* __restrict__ rstd0,
    const float* __restrict__ mu1, const float* __restrict__ rstd1,
    float* Ca, float* Cb, double* ds0, double* ds1,
    int na, int nb, int yb, int K, int NC) {
    extern __shared__ float smf[];
    __shared__ float sstat[256];
    const uint32_t sb = smem_u32(smf);
    const int tid = threadIdx.x;
    const int lane = tid & 31;
    const int wid = tid >> 5;
    const int warp_m = wid >> 2;
    const int warp_n = wid & 3;

    int by = blockIdx.y;
    const float *A1, *mu, *rstd;
    float* C;
    double* dstat;
    int n;
    if (by < yb) {
        A1 = A1a; C = Ca; dstat = ds0; n = na; mu = mu0; rstd = rstd0;
    } else {
        by -= yb;
        A1 = A1b; C = Cb; dstat = ds1; n = nb; mu = mu1; rstd = rstd1;
    }
    const int rowBase = by * 128;
    const int colBase = blockIdx.x * 128;
    const int g4 = lane >> 2;
    const int t4 = lane & 3;

    if (STAT && tid < 256) sstat[tid] = 0.f;

    stage_issue_r(sb, 0, A1, nullptr, false, W, rowBase, colBase, 0, n, K, NC, tid);
    stage_issue_r(sb, 1, A1, nullptr, false, W, rowBase, colBase, 32, n, K, NC, tid);

    float acc[4][4][4];
#pragma unroll
    for (int mi = 0; mi < 4; mi++)
#pragma unroll
        for (int ni = 0; ni < 4; ni++)
#pragma unroll
            for (int r = 0; r < 4; r++) acc[mi][ni][r] = 0.f;

    const int nk = K >> 5;
    for (int i = 0; i < nk; i++) {
        int p = i & 1;
        if (i + 1 < nk)
            asm volatile("cp.async.wait_group 1;" ::: "memory");
        else
            asm volatile("cp.async.wait_group 0;" ::: "memory");
        __syncthreads();
        if (AMODE == 2) {
            int kg = i * 32 + (tid & 1) * 16;
            float* a = smf + AOFF(p) + (tid >> 1) * 36 + (tid & 1) * 16;
#pragma unroll
            for (int j = 0; j < 16; j++) a[j] = eluf((a[j] - mu[kg + j]) * rstd[kg + j]);
            __syncthreads();
        }
        const float* Af = smf + AOFF(p);
        const float* Wf = smf + WOFF(p);
#pragma unroll
        for (int ks = 0; ks < 4; ks++) {
            int kk = ks * 8;
            uint32_t a[4][4];
#pragma unroll
            for (int mi = 0; mi < 4; mi++) {
                int r = warp_m * 64 + mi * 16 + g4;
                a[mi][0] = f2tf(Af[r * 36 + kk + t4]);
                a[mi][1] = f2tf(Af[(r + 8) * 36 + kk + t4]);
                a[mi][2] = f2tf(Af[r * 36 + kk + t4 + 4]);
                a[mi][3] = f2tf(Af[(r + 8) * 36 + kk + t4 + 4]);
            }
            uint32_t b[4][2];
#pragma unroll
            for (int ni = 0; ni < 4; ni++) {
                int c = warp_n * 32 + ni * 8 + g4;
                b[ni][0] = f2tf(Wf[(kk + t4) * 132 + c]);
                b[ni][1] = f2tf(Wf[(kk + t4 + 4) * 132 + c]);
            }
#pragma unroll
            for (int mi = 0; mi < 4; mi++)
#pragma unroll
                for (int ni = 0; ni < 4; ni++) mma8(acc[mi][ni], a[mi], b[ni]);
        }
        __syncthreads();
        if (i + 2 < nk)
            stage_issue_r(sb, p, A1, nullptr, false, W, rowBase, colBase, (i + 2) * 32, n, K, NC,
                          tid);
    }

    float cs[8], cq[8];
#pragma unroll
    for (int i = 0; i < 8; i++) { cs[i] = 0.f; cq[i] = 0.f; }

#pragma unroll
    for (int mi = 0; mi < 4; mi++) {
        int r0 = rowBase + warp_m * 64 + mi * 16 + g4;
        int r1 = r0 + 8;
#pragma unroll
        for (int ni = 0; ni < 4; ni++) {
            int c = colBase + warp_n * 32 + ni * 8 + t4 * 2;
            float b0 = bias[c], b1 = bias[c + 1];
            if (r0 < n) {
                float v0 = acc[mi][ni][0] + b0, v1 = acc[mi][ni][1] + b1;
                C[(size_t)r0 * NC + c] = v0;
                C[(size_t)r0 * NC + c + 1] = v1;
                if (STAT) {
                    cs[ni * 2] += v0; cq[ni * 2] += v0 * v0;
                    cs[ni * 2 + 1] += v1; cq[ni * 2 + 1] += v1 * v1;
                }
            }
            if (r1 < n) {
                float v2 = acc[mi][ni][2] + b0, v3 = acc[mi][ni][3] + b1;
                C[(size_t)r1 * NC + c] = v2;
                C[(size_t)r1 * NC + c + 1] = v3;
                if (STAT) {
                    cs[ni * 2] += v2; cq[ni * 2] += v2 * v2;
                    cs[ni * 2 + 1] += v3; cq[ni * 2 + 1] += v3 * v3;
                }
            }
        }
    }
    if (STAT) {
#pragma unroll
        for (int i = 0; i < 8; i++) {
            float s = cs[i], q = cq[i];
            s += __shfl_down_sync(0xffffffffu, s, 16);
            q += __shfl_down_sync(0xffffffffu, q, 16);
            s += __shfl_down_sync(0xffffffffu, s, 8);
            q += __shfl_down_sync(0xffffffffu, q, 8);
            s += __shfl_down_sync(0xffffffffu, s, 4);
            q += __shfl_down_sync(0xffffffffu, q, 4);
            if (g4 == 0) {
                int c = warp_n * 32 + (i >> 1) * 8 + t4 * 2 + (i & 1);
                atomicAdd(&sstat[c], s);
                atomicAdd(&sstat[128 + c], q);
            }
        }
        __syncthreads();
        if (tid < 128) {
            atomicAdd(&dstat[colBase + tid], (double)sstat[tid]);
            atomicAdd(&dstat[256 + colBase + tid], (double)sstat[128 + tid]);
        }
    }
}

// ---------------- fills ----------------
__global__ void k_zero0(float* glq, float* gsumq, float* accq, float* accda, float* pe, float* de,
                        int* dga, int* dgb, double* dstat) {
    int i = blockIdx.x * blockDim.x + threadIdx.x;
    if (i < NDA) dga[i] = 0;
    if (i < NQ) dgb[i] = 0;
    if (i < BB * HD) glq[i] = 0.f;
    if (i < BB) gsumq[i] = 0.f;
    if (i < BB * 4) { accq[i] = 0.f; accda[i] = 0.f; }
    if (i < HH) { pe[i] = 0.f; de[i] = 0.f; }
    if (i < 1024) dstat[i] = 0.0;
}

// ---------------- gate kernels ----------------
__global__ void __launch_bounds__(1024) k_gapq(const float* __restrict__ M,
                                               const float* __restrict__ w,
                                               const float* __restrict__ b,
                                               const int* __restrict__ gid, float* ebuf,
                                               float* gsum, int n) {
    __shared__ int sgid[32];
    __shared__ float se[32];
    int wid = threadIdx.x >> 5, lane = threadIdx.x & 31;
    int node = blockIdx.x * 32 + wid;
    if (node < n) {
        float4 a = ((const float4*)(M + (size_t)node * HD))[lane];
        float4 wv = ((const float4*)w)[lane];
        float s = a.x * wv.x + a.y * wv.y + a.z * wv.z + a.w * wv.w;
#pragma unroll
        for (int o = 16; o; o >>= 1) s += __shfl_down_sync(0xffffffffu, s, o);
        if (lane == 0) {
            float e = expf(s + b[0]);
            ebuf[node] = e;
            sgid[wid] = gid[node];
            se[wid] = e;
        }
    } else if (lane == 0) sgid[wid] = -1;
    __syncthreads();
    if (threadIdx.x == 0) {
        int cur = -2;
        float a = 0.f;
        for (int i = 0; i < 32; i++) {
            int g = sgid[i];
            if (g < 0) continue;
            if (g != cur) { if (cur >= 0) atomicAdd(&gsum[cur], a); cur = g; a = 0.f; }
            a += se[i];
        }
        if (cur >= 0) atomicAdd(&gsum[cur], a);
    }
}

__global__ void k_gap_pool(const float* __restrict__ M, const int* __restrict__ gid,
                           const float* __restrict__ e, const float* __restrict__ gsum,
                           float* pool, int n) {
    int w = (blockIdx.x * blockDim.x + threadIdx.x) >> 5;
    int lane = threadIdx.x & 31;
    if (w >= n) return;
    int b = gid[w];
    float wt = e[w] / gsum[b];
    const float* row = M + (size_t)w * HD;
#pragma unroll
    for (int j = lane; j < HD; j += 32) atomicAdd(&pool[b * HD + j], wt * row[j]);
}

__global__ void __launch_bounds__(1024) k_gapdots_b(
    const float* __restrict__ h0a, const float* __restrict__ hla, const int* __restrict__ gia,
    float* acca,
    const float* __restrict__ h0b, const float* __restrict__ hlb, const int* __restrict__ gib,
    float* accb,
    const float* __restrict__ w1, const float* __restrict__ b1, const float* __restrict__ w2,
    const float* __restrict__ b2, const float* __restrict__ qc, int ybreak) {
    __shared__ int sgid[32];
    __shared__ float sv[32][4];
    const float *M1, *M2;
    const int* gid;
    float* acc;
    int nodeBase;
    if ((int)blockIdx.x < ybreak) {
        M1 = h0a; M2 = hla; gid = gia; acc = acca; nodeBase = blockIdx.x * 32;
    } else {
        M1 = h0b; M2 = hlb; gid = gib; acc = accb; nodeBase = (blockIdx.x - ybreak) * 32;
    }
    int wid = threadIdx.x >> 5, lane = threadIdx.x & 31;
    int node = nodeBase + wid;
    {
        float4 a = ((const float4*)(M1 + (size_t)node * HD))[lane];
        float4 bb = ((const float4*)(M2 + (size_t)node * HD))[lane];
        float4 w1v = ((const float4*)w1)[lane];
        float4 w2v = ((const float4*)w2)[lane];
        float4 qv = ((const float4*)qc)[lane];
        float s1 = a.x * w1v.x + a.y * w1v.y + a.z * w1v.z + a.w * w1v.w;
        float q1 = a.x * qv.x + a.y * qv.y + a.z * qv.z + a.w * qv.w;
        float s2 = bb.x * w2v.x + bb.y * w2v.y + bb.z * w2v.z + bb.w * w2v.w;
        float q2 = bb.x * qv.x + bb.y * qv.y + bb.z * qv.z + bb.w * qv.w;
#pragma unroll
        for (int o = 16; o; o >>= 1) {
            s1 += __shfl_down_sync(0xffffffffu, s1, o);
            q1 += __shfl_down_sync(0xffffffffu, q1, o);
            s2 += __shfl_down_sync(0xffffffffu, s2, o);
            q2 += __shfl_down_sync(0xffffffffu, q2, o);
        }
        if (lane == 0) {
            float e1 = expf(s1 + b1[0]), e2 = expf(s2 + b2[0]);
            sgid[wid] = gid[node];
            sv[wid][0] = e1; sv[wid][1] = e1 * q1; sv[wid][2] = e2; sv[wid][3] = e2 * q2;
        }
    }
    __syncthreads();
    if (threadIdx.x < 4) {
        int comp = threadIdx.x;
        int cur = -2;
        float a = 0.f;
        for (int i = 0; i < 32; i++) {
            int g = sgid[i];
            if (g != cur) { if (cur >= 0) atomicAdd(&acc[cur * 4 + comp], a); cur = g; a = 0.f; }
            a += sv[i][comp];
        }
        if (cur >= 0) atomicAdd(&acc[cur * 4 + comp], a);
    }
}

__global__ void k_comb2x(const float* __restrict__ accq, float* aabq,
                         const float* __restrict__ accda, float* aabda) {
    int t = threadIdx.x;
    const float* acc = t < BB ? accq : accda;
    float* aab = t < BB ? aabq : aabda;
    int b = t & (BB - 1);
    float d1 = acc[b * 4 + 1] / acc[b * 4 + 0];
    float d2 = acc[b * 4 + 3] / acc[b * 4 + 2];
    float mm = fmaxf(d1, d2);
    float e1 = expf(d1 - mm), e2 = expf(d2 - mm);
    float ss = e1 + e2;
    aab[2 * b] = e1 / ss;
    aab[2 * b + 1] = e2 / ss;
}

// ---------------- CSR build (batched) ----------------
__global__ void k_hist_b(const int* __restrict__ dsta, int* dga, const int* __restrict__ dstb,
                         int* dgb, int Ea, int Eb) {
    int e = blockIdx.x * blockDim.x + threadIdx.x;
    if (e < Ea) {
        atomicAdd(&dga[dsta[e]], 1);
    } else {
        e -= Ea;
        if (e < Eb) atomicAdd(&dgb[dstb[e]], 1);
    }
}
__global__ void k_scan1_b(const int* __restrict__ dga, int* coffa, int* bsuma,
                          const int* __restrict__ dgb, int* coffb, int* bsumb, int na, int nb,
                          int nba) {
    __shared__ int sh[512];
    const int* dg;
    int *outp, *bsum;
    int n, bid;
    if ((int)blockIdx.x < nba) { dg = dga; outp = coffa; bsum = bsuma; n = na; bid = blockIdx.x; }
    else { dg = dgb; outp = coffb; bsum = bsumb; n = nb; bid = blockIdx.x - nba; }
    int base = bid * 512, t = threadIdx.x;
    int v0 = (base + t < n) ? dg[base + t] : 0;
    int v1 = (base + 256 + t < n) ? dg[base + 256 + t] : 0;
    sh[t] = v0; sh[t + 256] = v1;
    __syncthreads();
    for (int off = 1; off < 512; off <<= 1) {
        int i0 = t, i1 = t + 256;
        int n0 = sh[i0] + ((i0 >= off) ? sh[i0 - off] : 0);
        int n1 = sh[i1] + ((i1 >= off) ? sh[i1 - off] : 0);
        __syncthreads();
        sh[i0] = n0; sh[i1] = n1;
        __syncthreads();
    }
    if (base + t < n) outp[base + t] = sh[t] - v0;
    if (base + 256 + t < n) outp[base + 256 + t] = sh[t + 256] - v1;
    if (t == 0) bsum[bid] = sh[511];
}
__global__ void k_scan2_b(int* bsuma, int nba, int* bsumb, int nbb) {
    __shared__ int sh[256];
    int* bsum = blockIdx.x == 0 ? bsuma : bsumb;
    int nb = blockIdx.x == 0 ? nba : nbb;
    int t = threadIdx.x;
    int v = (t < nb) ? bsum[t] : 0;
    sh[t] = v;
    __syncthreads();
    for (int off = 1; off < 256; off <<= 1) {
        int x = sh[t] + ((t >= off) ? sh[t - off] : 0);
        __syncthreads();
        sh[t] = x;
        __syncthreads();
    }
    if (t < nb) bsum[t] = sh[t] - v;
}
__global__ void k_scan3_b(int* coffa, int* cura, const int* __restrict__ bsuma, int* coffb,
                          int* curb, const int* __restrict__ bsumb, int na, int nb) {
    int i = blockIdx.x * blockDim.x + threadIdx.x;
    if (i < na) {
        int v = coffa[i] + bsuma[i >> 9];
        coffa[i] = v;
        cura[i] = v;
    } else {
        i -= na;
        if (i < nb) {
            int v = coffb[i] + bsumb[i >> 9];
            coffb[i] = v;
            curb[i] = v;
        }
    }
}
__global__ void k_scatter_b(const int* __restrict__ srca, const int* __restrict__ dsta, int* cura,
                            int* srcsa, const int* __restrict__ srcb,
                            const int* __restrict__ dstb, int* curb, int* srcsb, int Ea, int Eb) {
    int e = blockIdx.x * blockDim.x + threadIdx.x;
    if (e < Ea) {
        int p = atomicAdd(&cura[dsta[e]], 1);
        srcsa[p] = srca[e];
    } else {
        e -= Ea;
        if (e < Eb) {
            int p = atomicAdd(&curb[dstb[e]], 1);
            srcsb[p] = srcb[e];
        }
    }
}

// ---------------- batched single-pass edge softmax + aggregation ----------------
__global__ void k_node_agg_b(const int* __restrict__ srcsa, const int* __restrict__ coffa,
                             const int* __restrict__ dga, const float* __restrict__ ela,
                             const float* __restrict__ era, const float* __restrict__ fta,
                             float* agga, float* sa, const int* __restrict__ srcsb,
                             const int* __restrict__ coffb, const int* __restrict__ dgb,
                             const float* __restrict__ elb, const float* __restrict__ erb,
                             const float* __restrict__ ftb, float* aggb, float* sb2, int na,
                             int nb) {
    int w = (blockIdx.x * blockDim.x + threadIdx.x) >> 5;
    int lane = threadIdx.x & 31;
    const int *srcs, *coff, *dg;
    const float *el, *er, *ft;
    float *agg, *s;
    if (w < na) {
        srcs = srcsa; coff = coffa; dg = dga; el = ela; er = era; ft = fta; agg = agga; s = sa;
    } else {
        w -= na;
        if (w >= nb) return;
        srcs = srcsb; coff = coffb; dg = dgb; el = elb; er = erb; ft = ftb; agg = aggb; s = sb2;
    }
    int h = lane >> 2;
    int off = coff[w], d = dg[w];
    float erv = er[w * HH + h];
    float wsum = 0.f;
    float4 acc = make_float4(0.f, 0.f, 0.f, 0.f);
#pragma unroll 2
    for (int j = 0; j < d; j++) {
        int sn = srcs[off + j];
        float v = el[sn * HH + h] + erv;
        v = v > 0.f ? v : NEG_SLOPE * v;
        float wt = expf(v);
        wsum += wt;
        float4 fv = *(const float4*)(ft + (size_t)sn * HD + lane * 4);
        acc.x = fmaf(wt, fv.x, acc.x);
        acc.y = fmaf(wt, fv.y, acc.y);
        acc.z = fmaf(wt, fv.z, acc.z);
        acc.w = fmaf(wt, fv.w, acc.w);
    }
    float inv = wsum > 0.f ? 1.f / wsum : 0.f;
    acc.x *= inv; acc.y *= inv; acc.z *= inv; acc.w *= inv;
    *(float4*)(agg + (size_t)w * HD + lane * 4) = acc;
    if ((lane & 3) == 0) s[w * HH + h] = wsum;
}

// ---------------- bn finalize (self-zeroing) / apply ----------------
__global__ void k_bnfin2(double* st0, int n0, float* mu0, float* rstd0, double* st1, int n1,
                         float* mu1, float* rstd1, int C) {
    int t = threadIdx.x;
    double* st;
    float *mu, *rstd;
    int n, c;
    if (t < C) { st = st0; mu = mu0; rstd = rstd0; n = n0; c = t; }
    else { st = st1; mu = mu1; rstd = rstd1; n = n1; c = t - C; }
    double m = st[c] / n;
    double v = st[256 + c] / n - m * m;
    if (v < 0.0) v = 0.0;
    mu[c] = (float)m;
    rstd[c] = (float)(1.0 / sqrt(v + 1e-5));
    st[c] = 0.0;
    st[256 + c] = 0.0;
}
__global__ void k_bnelu(const float* __restrict__ Y, const float* __restrict__ mu,
                        const float* __restrict__ rstd, float* outp, long long total, int C) {
    long long i = (long long)blockIdx.x * blockDim.x + threadIdx.x;
    if (i < total) {
        int c = (int)(i % C);
        outp[i] = eluf((Y[i] - mu[c]) * rstd[c]);
    }
}
__global__ void k_final_b(const float* __restrict__ hla, const float* __restrict__ y2a,
                          const float* __restrict__ mu0, const float* __restrict__ rstd0,
                          float* outa, const float* __restrict__ hlb,
                          const float* __restrict__ y2b, const float* __restrict__ mu1,
                          const float* __restrict__ rstd1, float* outb, long long ta,
                          long long tb) {
    long long i = (long long)blockIdx.x * blockDim.x + threadIdx.x;
    const float *hl, *Y, *mu, *rstd;
    float* outp;
    if (i < ta) { hl = hla; Y = y2a; mu = mu0; rstd = rstd0; outp = outa; }
    else {
        i -= ta;
        if (i >= tb) return;
        hl = hlb; Y = y2b; mu = mu1; rstd = rstd1; outp = outb;
    }
    int c = (int)(i & (HD - 1));
    outp[i] = hl[i] + eluf((Y[i] - mu[c]) * rstd[c]);
}

// ---------------- loss ----------------
__global__ void k_pesum_b(const int* __restrict__ peid, int npe, float* peout,
                          const int* __restrict__ deid, int nde, float* deout,
                          const int* __restrict__ src, const int* __restrict__ dst,
                          const float* __restrict__ el, const float* __restrict__ er,
                          const float* __restrict__ s) {
    const int* ids;
    float* out8;
    int nids, bid;
    int half = gridDim.x / 2;
    if ((int)blockIdx.x < half) { ids = peid; out8 = peout; nids = npe; bid = blockIdx.x; }
    else { ids = deid; out8 = deout; nids = nde; bid = blockIdx.x - half; }
    float acc[HH];
#pragma unroll
    for (int h = 0; h < HH; h++) acc[h] = 0.f;
    for (int i = bid * blockDim.x + threadIdx.x; i < nids; i += half * blockDim.x) {
        int e = ids[i];
        int se = src[e] * HH, de = dst[e] * HH;
#pragma unroll
        for (int h = 0; h < HH; h++) {
            float v = el[se + h] + er[de + h];
            v = v > 0.f ? v : NEG_SLOPE * v;
            acc[h] += expf(v) / s[de + h];
        }
    }
#pragma unroll
    for (int h = 0; h < HH; h++)
#pragma unroll
        for (int o = 16; o; o >>= 1) acc[h] += __shfl_down_sync(0xffffffffu, acc[h], o);
    if ((threadIdx.x & 31) == 0)
#pragma unroll
        for (int h = 0; h < HH; h++) atomicAdd(&out8[h], acc[h]);
}
__global__ void k_loss(const float* pe, const float* de, const int* lenp, float* outp) {
    float sum = 0.f;
#pragma unroll
    for (int h = 0; h < HH; h++) sum += pe[h] - de[h];
    outp[0] = -sum / (8.0f * (float)lenp[0]);
}

// ---------------- host ----------------
static inline int cdiv(long long a, long long b) { return (int)((a + b - 1) / b); }

extern "C" void kernel_launch(void* const* d_in, const int* in_sizes, int n_in, void* d_out,
                              int out_size) {
    const float* h_da_last = (const float*)d_in[0];
    const float* h_q_last  = (const float*)d_in[1];
    const float* h_da_0    = (const float*)d_in[2];
    const float* h_q_0     = (const float*)d_in[3];
    const float* W_L       = (const float*)d_in[4];
    const float* b_L       = (const float*)d_in[5];
    const float* gateq_W   = (const float*)d_in[6];
    const float* gateq_b   = (const float*)d_in[7];
    const float* gate1_W   = (const float*)d_in[8];
    const float* gate1_b   = (const float*)d_in[9];
    const float* gate2_W   = (const float*)d_in[10];
    const float* gate2_b   = (const float*)d_in[11];
    const float* Q_comb    = (const float*)d_in[12];
    const float* Qf_W1     = (const float*)d_in[13];
    const float* Qf_b1     = (const float*)d_in[14];
    const float* Qf_W2     = (const float*)d_in[15];
    const float* Qf_b2     = (const float*)d_in[16];
    const float* end_W1    = (const float*)d_in[17];
    const float* end_b1    = (const float*)d_in[18];
    const float* end_W2    = (const float*)d_in[19];
    const float* end_b2    = (const float*)d_in[20];
    const int* src_da = (const int*)d_in[21];
    const int* dst_da = (const int*)d_in[22];
    const int* src_q  = (const int*)d_in[23];
    const int* dst_q  = (const int*)d_in[24];
    const int* gid_da = (const int*)d_in[25];
    const int* gid_q  = (const int*)d_in[26];
    const int* PEid   = (const int*)d_in[27];
    const int* DEid   = (const int*)d_in[28];
    const int* lenp   = (const int*)d_in[29];
    int nPE = in_sizes[27], nDE = in_sizes[28];

    float* outp = (float*)d_out;
    float* out_da = outp;
    float* out_q = outp + (long long)NDA * HD;
    float* out_loss = outp + (long long)NDA * HD + (long long)NQ * HD;

    float *feat, *featq, *ft, *ftq, *agg, *aggq, *y1, *y1q, *y2, *y2q;
    float *el, *er, *ss, *elq, *erq, *sq2, *eb;
    float *glq, *t1, *t2, *Qb, *gsumq, *accq, *accda, *aabq, *aabda, *mu, *rstd, *pe, *de;
    double* dstat;
    int *dg, *coff, *cursor, *srcs, *bsum, *dgq, *coffq, *cursorq, *srcsq, *bsumq;
    cudaGetSymbolAddress((void**)&feat, g_feat);
    cudaGetSymbolAddress((void**)&featq, g_featq);
    cudaGetSymbolAddress((void**)&ft, g_ft);
    cudaGetSymbolAddress((void**)&ftq, g_ftq);
    cudaGetSymbolAddress((void**)&agg, g_agg);
    cudaGetSymbolAddress((void**)&aggq, g_aggq);
    cudaGetSymbolAddress((void**)&y1, g_y1);
    cudaGetSymbolAddress((void**)&y1q, g_y1q);
    cudaGetSymbolAddress((void**)&y2, g_y2);
    cudaGetSymbolAddress((void**)&y2q, g_y2q);
    cudaGetSymbolAddress((void**)&el, g_el);
    cudaGetSymbolAddress((void**)&er, g_er);
    cudaGetSymbolAddress((void**)&ss, g_s);
    cudaGetSymbolAddress((void**)&elq, g_elq);
    cudaGetSymbolAddress((void**)&erq, g_erq);
    cudaGetSymbolAddress((void**)&sq2, g_sq2);
    cudaGetSymbolAddress((void**)&eb, g_eb);
    cudaGetSymbolAddress((void**)&glq, g_glq);
    cudaGetSymbolAddress((void**)&t1, g_t1);
    cudaGetSymbolAddress((void**)&t2, g_t2);
    cudaGetSymbolAddress((void**)&Qb, g_Q);
    cudaGetSymbolAddress((void**)&gsumq, g_gsumq);
    cudaGetSymbolAddress((void**)&accq, g_accq);
    cudaGetSymbolAddress((void**)&accda, g_accda);
    cudaGetSymbolAddress((void**)&aabq, g_aabq);
    cudaGetSymbolAddress((void**)&aabda, g_aabda);
    cudaGetSymbolAddress((void**)&mu, g_mu);
    cudaGetSymbolAddress((void**)&rstd, g_rstd);
    cudaGetSymbolAddress((void**)&pe, g_pe);
    cudaGetSymbolAddress((void**)&de, g_de);
    cudaGetSymbolAddress((void**)&dstat, g_dstat);
    cudaGetSymbolAddress((void**)&dg, g_deg);
    cudaGetSymbolAddress((void**)&coff, g_coff);
    cudaGetSymbolAddress((void**)&cursor, g_cursor);
    cudaGetSymbolAddress((void**)&srcs, g_srcs);
    cudaGetSymbolAddress((void**)&bsum, g_bsum);
    cudaGetSymbolAddress((void**)&dgq, g_degq);
    cudaGetSymbolAddress((void**)&coffq, g_coffq);
    cudaGetSymbolAddress((void**)&cursorq, g_cursorq);
    cudaGetSymbolAddress((void**)&srcsq, g_srcsq);
    cudaGetSymbolAddress((void**)&bsumq, g_bsumq);

    double* dstat1 = dstat + 512;
    float* mu1 = mu + 256;
    float* rstd1 = rstd + 256;

    cudaFuncSetAttribute(k_gemmW, cudaFuncAttributeMaxDynamicSharedMemorySize, SMEM_G1);
    cudaFuncSetAttribute(k_gemm<0, 1>, cudaFuncAttributeMaxDynamicSharedMemorySize, SMEM_G0);
    cudaFuncSetAttribute(k_gemm<2, 1>, cudaFuncAttributeMaxDynamicSharedMemorySize, SMEM_G0);

    const int YDA = cdiv(NDA, 128), YQ = cdiv(NQ, 128);

    // prep
    k_zero0<<<cdiv(NDA, 256), 256>>>(glq, gsumq, accq, accda, pe, de, dg, dgq, dstat);
    k_gapq<<<cdiv(NQ, 32), 1024>>>(h_q_last, gateq_W, gateq_b, gid_q, eb, gsumq, NQ);
    k_gap_pool<<<cdiv((long long)NQ * 32, 256), 256>>>(h_q_last, gid_q, eb, gsumq, glq, NQ);
    k_gapdots_b<<<NDA / 32 + NQ / 32, 1024>>>(h_da_0, h_da_last, gid_da, accda, h_q_0, h_q_last,
                                              gid_q, accq, gate1_W, gate1_b, gate2_W, gate2_b,
                                              Q_comb, NDA / 32);
    k_hist_b<<<cdiv(EDA + EQ, 256), 256>>>(dst_da, dg, dst_q, dgq, EDA, EQ);
    // Qf FNN -> Qb
    k_gemm<0, 1><<<dim3(2, 1), 256, SMEM_G0>>>(glq, nullptr, Qf_W1, Qf_b1, nullptr, nullptr,
                                               nullptr, nullptr, t1, nullptr, dstat, nullptr, BB,
                                               0, 1, 128, 256);
    k_bnfin2<<<1, 512>>>(dstat, BB, mu, rstd, dstat1, 1, mu1, rstd1, 256);
    k_gemm<2, 1><<<dim3(2, 1), 256, SMEM_G0>>>(t1, nullptr, Qf_W2, Qf_b2, mu, rstd, nullptr,
                                               nullptr, t2, nullptr, dstat, nullptr, BB, 0, 1,
                                               256, 256);
    k_bnfin2<<<1, 512>>>(dstat, BB, mu, rstd, dstat1, 1, mu1, rstd1, 256);
    k_bnelu<<<cdiv(BB * 256, 256), 256>>>(t2, mu, rstd, Qb, (long long)BB * 256, 256);
    k_comb2x<<<1, 128>>>(accq, aabq, accda, aabda);
    // CSR
    int NBA = cdiv(NDA, 512), NBB = cdiv(NQ, 512);
    k_scan1_b<<<NBA + NBB, 256>>>(dg, coff, bsum, dgq, coffq, bsumq, NDA, NQ, NBA);
    k_scan2_b<<<2, 256>>>(bsum, NBA, bsumq, NBB);
    k_scan3_b<<<cdiv(NDA + NQ, 256), 256>>>(coff, cursor, bsum, coffq, cursorq, bsumq, NDA, NQ);
    k_scatter_b<<<cdiv(EDA + EQ, 256), 256>>>(src_da, dst_da, cursor, srcs, src_q, dst_q, cursorq,
                                              srcsq, EDA, EQ);

    // mega W_L GEMM: feat(da,q) + ft(da,q), fused el/er for feat
    k_gemmW<<<dim3(1, 2 * (YDA + YQ)), 256, SMEM_G1>>>(
        h_da_last, h_q_last, h_da_0, h_q_0, aabda, aabq, gid_da, gid_q, W_L, b_L, Qb, feat, featq,
        ft, ftq, el, er, elq, erq, YDA, YQ);

    // batched node agg
    k_node_agg_b<<<cdiv((long long)(NDA + NQ) * 32, 256), 256>>>(
        srcs, coff, dg, el, er, ft, agg, ss, srcsq, coffq, dgq, elq, erq, ftq, aggq, sq2, NDA, NQ);
    // end FNN
    k_gemm<0, 1><<<dim3(2, YDA + YQ), 256, SMEM_G0>>>(agg, aggq, end_W1, end_b1, nullptr, nullptr,
                                                      nullptr, nullptr, y1, y1q, dstat, dstat1,
                                                      NDA, NQ, YDA, 128, 256);
    k_bnfin2<<<1, 512>>>(dstat, NDA, mu, rstd, dstat1, NQ, mu1, rstd1, 256);
    k_gemm<2, 1><<<dim3(1, YDA + YQ), 256, SMEM_G0>>>(y1, y1q, end_W2, end_b2, mu, rstd, mu1,
                                                      rstd1, y2, y2q, dstat, dstat1, NDA, NQ, YDA,
                                                      256, 128);
    k_bnfin2<<<1, 256>>>(dstat, NDA, mu, rstd, dstat1, NQ, mu1, rstd1, 128);
    k_final_b<<<cdiv((long long)(NDA + NQ) * HD, 256), 256>>>(
        h_da_last, y2, mu, rstd, out_da, h_q_last, y2q, mu1, rstd1, out_q, (long long)NDA * HD,
        (long long)NQ * HD);

    // loss
    k_pesum_b<<<256, 256>>>(PEid, nPE, pe, DEid, nDE, de, src_da, dst_da, el, er, ss);
    k_loss<<<1, 1>>>(pe, de, lenp, out_loss);
}

// round 11
// speedup vs baseline: 3.7022x; 1.0020x over previous
#include <cuda_runtime.h>
#include <math.h>
#include <stdint.h>

#define NDA 100000
#define NQ  20000
#define EDA 1000000
#define EQ  200000
#define BB  64
#define HH  8
#define HD  128
#define HD2 256
#define NEG_SLOPE 2.0f

// ---------------- scratch ----------------
__device__ float g_feat[(size_t)NDA * HD];
__device__ float g_featq[(size_t)NQ * HD];
__device__ float g_ft[(size_t)NDA * HD];
__device__ float g_ftq[(size_t)NQ * HD];
__device__ float g_agg[(size_t)NDA * HD];
__device__ float g_aggq[(size_t)NQ * HD];
__device__ float g_y1[(size_t)NDA * HD2];
__device__ float g_y1q[(size_t)NQ * HD2];
__device__ float g_y2[(size_t)NDA * HD];
__device__ float g_y2q[(size_t)NQ * HD];
__device__ float g_el[NDA * HH];
__device__ float g_er[NDA * HH];
__device__ float g_s[NDA * HH];
__device__ float g_elq[NQ * HH];
__device__ float g_erq[NQ * HH];
__device__ float g_sq2[NQ * HH];
__device__ float g_eb[NQ];
__device__ int   g_deg[NDA];
__device__ int   g_coff[NDA];
__device__ int   g_cursor[NDA];
__device__ int   g_srcs[EDA];
__device__ int   g_bsum[256];
__device__ int   g_degq[NQ];
__device__ int   g_coffq[NQ];
__device__ int   g_cursorq[NQ];
__device__ int   g_srcsq[EQ];
__device__ int   g_bsumq[256];
__device__ float g_glq[BB * HD];
__device__ float g_t1[BB * HD2];
__device__ float g_t2[BB * HD2];
__device__ float g_Q[BB * HD2];
__device__ float g_gsumq[BB];
__device__ float g_accq[BB * 4];
__device__ float g_accda[BB * 4];
__device__ float g_aabq[BB * 2];
__device__ float g_aabda[BB * 2];
__device__ double g_dstat[1024];
__device__ float g_mu[512];
__device__ float g_rstd[512];
__device__ float g_pe[HH];
__device__ float g_de[HH];

__device__ __forceinline__ float eluf(float x) { return x > 0.f ? x : expm1f(x); }

__device__ __forceinline__ uint32_t smem_u32(const void* p) {
    uint32_t a;
    asm("{ .reg .u64 t; cvta.to.shared.u64 t, %1; cvt.u32.u64 %0, t; }" : "=r"(a) : "l"(p));
    return a;
}
__device__ __forceinline__ uint32_t f2tf(float x) {
    uint32_t r;
    asm("cvt.rna.tf32.f32 %0, %1;" : "=r"(r) : "f"(x));
    return r;
}
__device__ __forceinline__ void mma8(float* d, const uint32_t* a, const uint32_t* b) {
    asm volatile(
        "mma.sync.aligned.m16n8k8.row.col.f32.tf32.tf32.f32 "
        "{%0,%1,%2,%3}, {%4,%5,%6,%7}, {%8,%9}, {%0,%1,%2,%3};\n"
        : "+f"(d[0]), "+f"(d[1]), "+f"(d[2]), "+f"(d[3])
        : "r"(a[0]), "r"(a[1]), "r"(a[2]), "r"(a[3]), "r"(b[0]), "r"(b[1]));
}

#define AOFF(buf) ((buf) * 4608)
#define WOFF(buf) (9216 + (buf) * 4224)
#define A2OFF(buf) (17664 + (buf) * 4608)
#define SMEM_G0 ((9216 + 8448) * 4)
#define SMEM_G1 ((9216 + 8448 + 9216) * 4)

__device__ __forceinline__ void stage_issue_r(uint32_t sb, int buf, const float* __restrict__ A,
                                              const float* __restrict__ A2, bool blend,
                                              const float* __restrict__ W, int rowBase,
                                              int colBase, int k0, int n, int K, int NC,
                                              int tid) {
    uint32_t abase = sb + AOFF(buf) * 4;
    uint32_t wbase = sb + WOFF(buf) * 4;
#pragma unroll
    for (int q = 0; q < 4; q++) {
        int id = tid + q * 256;
        int r = id >> 3, kq = id & 7;
        int grow = rowBase + r;
        const float* src = A + (size_t)grow * K + k0 + kq * 4;
        uint32_t dst = abase + (r * 36 + kq * 4) * 4;
        int sz = grow < n ? 16 : 0;
        asm volatile("cp.async.ca.shared.global [%0], [%1], 16, %2;" ::"r"(dst), "l"(src), "r"(sz)
                     : "memory");
    }
    if (blend) {
        uint32_t a2base = sb + A2OFF(buf) * 4;
#pragma unroll
        for (int q = 0; q < 4; q++) {
            int id = tid + q * 256;
            int r = id >> 3, kq = id & 7;
            int grow = rowBase + r;
            const float* src = A2 + (size_t)grow * K + k0 + kq * 4;
            uint32_t dst = a2base + (r * 36 + kq * 4) * 4;
            int sz = grow < n ? 16 : 0;
            asm volatile("cp.async.ca.shared.global [%0], [%1], 16, %2;" ::"r"(dst), "l"(src),
                         "r"(sz)
                         : "memory");
        }
    }
#pragma unroll
    for (int q = 0; q < 4; q++) {
        int id = tid + q * 256;
        int kk = id >> 5, nq = id & 31;
        const float* src = W + (size_t)(k0 + kk) * NC + colBase + nq * 4;
        uint32_t dst = wbase + (kk * 132 + nq * 4) * 4;
        asm volatile("cp.async.ca.shared.global [%0], [%1], 16;" ::"r"(dst), "l"(src) : "memory");
    }
    asm volatile("cp.async.commit_group;" ::: "memory");
}

// ---------------- mega W_L GEMM: 4 sub-problems + fused el/er for feat ----------------
__global__ void __launch_bounds__(256, 2) k_gemmW(
    const float* __restrict__ hdl, const float* __restrict__ hql,
    const float* __restrict__ hd0, const float* __restrict__ hq0,
    const float* __restrict__ aabda, const float* __restrict__ aabq,
    const int* __restrict__ gid_da, const int* __restrict__ gid_q,
    const float* __restrict__ W, const float* __restrict__ bias,
    const float* __restrict__ Qb,
    float* feat, float* featq, float* ft, float* ftq,
    float* el, float* er, float* elq, float* erq, int YDA, int YQ) {
    extern __shared__ float smf[];
    const uint32_t sb = smem_u32(smf);
    const int tid = threadIdx.x;
    const int lane = tid & 31;
    const int wid = tid >> 5;
    const int warp_m = wid >> 2;
    const int warp_n = wid & 3;

    int by = blockIdx.y;
    const float *A1, *A2, *acoef;
    const int* gid;
    float *C, *elo, *ero;
    int n;
    bool blend;
    if (by < YDA) {
        A1 = hdl; A2 = nullptr; acoef = nullptr; gid = gid_da; C = feat; elo = el; ero = er;
        n = NDA; blend = false;
    } else if (by < YDA + YQ) {
        by -= YDA;
        A1 = hql; A2 = nullptr; acoef = nullptr; gid = gid_q; C = featq; elo = elq; ero = erq;
        n = NQ; blend = false;
    } else if (by < 2 * YDA + YQ) {
        by -= YDA + YQ;
        A1 = hd0; A2 = hdl; acoef = aabda; gid = gid_da; C = ft; elo = nullptr; ero = nullptr;
        n = NDA; blend = true;
    } else {
        by -= 2 * YDA + YQ;
        A1 = hq0; A2 = hql; acoef = aabq; gid = gid_q; C = ftq; elo = nullptr; ero = nullptr;
        n = NQ; blend = true;
    }
    const int rowBase = by * 128;
    const int g4 = lane >> 2;
    const int t4 = lane & 3;

    float c0 = 0.f, c1 = 0.f;
    if (blend) {
        int rr = rowBase + (tid >> 1);
        if (rr < n) {
            int g = gid[rr];
            c0 = acoef[2 * g];
            c1 = acoef[2 * g + 1];
        }
    }

    stage_issue_r(sb, 0, A1, A2, blend, W, rowBase, 0, 0, n, 128, 128, tid);
    stage_issue_r(sb, 1, A1, A2, blend, W, rowBase, 0, 32, n, 128, 128, tid);

    float acc[4][4][4];
#pragma unroll
    for (int mi = 0; mi < 4; mi++)
#pragma unroll
        for (int ni = 0; ni < 4; ni++)
#pragma unroll
            for (int r = 0; r < 4; r++) acc[mi][ni][r] = 0.f;

    const int nk = 4;
    for (int i = 0; i < nk; i++) {
        int p = i & 1;
        if (i + 1 < nk)
            asm volatile("cp.async.wait_group 1;" ::: "memory");
        else
            asm volatile("cp.async.wait_group 0;" ::: "memory");
        __syncthreads();
        if (blend) {
            float* a = smf + AOFF(p) + (tid >> 1) * 36 + (tid & 1) * 16;
            const float* b2 = smf + A2OFF(p) + (tid >> 1) * 36 + (tid & 1) * 16;
#pragma unroll
            for (int j = 0; j < 16; j++) a[j] = c0 * a[j] + c1 * b2[j];
            __syncthreads();
        }
        const float* Af = smf + AOFF(p);
        const float* Wf = smf + WOFF(p);
#pragma unroll
        for (int ks = 0; ks < 4; ks++) {
            int kk = ks * 8;
            uint32_t a[4][4];
#pragma unroll
            for (int mi = 0; mi < 4; mi++) {
                int r = warp_m * 64 + mi * 16 + g4;
                a[mi][0] = f2tf(Af[r * 36 + kk + t4]);
                a[mi][1] = f2tf(Af[(r + 8) * 36 + kk + t4]);
                a[mi][2] = f2tf(Af[r * 36 + kk + t4 + 4]);
                a[mi][3] = f2tf(Af[(r + 8) * 36 + kk + t4 + 4]);
            }
            uint32_t b[4][2];
#pragma unroll
            for (int ni = 0; ni < 4; ni++) {
                int c = warp_n * 32 + ni * 8 + g4;
                b[ni][0] = f2tf(Wf[(kk + t4) * 132 + c]);
                b[ni][1] = f2tf(Wf[(kk + t4 + 4) * 132 + c]);
            }
#pragma unroll
            for (int mi = 0; mi < 4; mi++)
#pragma unroll
                for (int ni = 0; ni < 4; ni++) mma8(acc[mi][ni], a[mi], b[ni]);
        }
        __syncthreads();
        if (i + 2 < nk)
            stage_issue_r(sb, p, A1, A2, blend, W, rowBase, 0, (i + 2) * 32, n, 128, 128, tid);
    }

    float* sC = smf;
#pragma unroll
    for (int mi = 0; mi < 4; mi++) {
        int lr0 = warp_m * 64 + mi * 16 + g4;
        int lr1 = lr0 + 8;
        int r0 = rowBase + lr0, r1 = rowBase + lr1;
#pragma unroll
        for (int ni = 0; ni < 4; ni++) {
            int c = warp_n * 32 + ni * 8 + t4 * 2;
            float b0 = bias[c], b1 = bias[c + 1];
            float v0 = acc[mi][ni][0] + b0, v1 = acc[mi][ni][1] + b1;
            float v2 = acc[mi][ni][2] + b0, v3 = acc[mi][ni][3] + b1;
            if (r0 < n) {
                C[(size_t)r0 * HD + c] = v0;
                C[(size_t)r0 * HD + c + 1] = v1;
            }
            if (r1 < n) {
                C[(size_t)r1 * HD + c] = v2;
                C[(size_t)r1 * HD + c + 1] = v3;
            }
            if (elo) {
                sC[lr0 * 132 + c] = v0;
                sC[lr0 * 132 + c + 1] = v1;
                sC[lr1 * 132 + c] = v2;
                sC[lr1 * 132 + c + 1] = v3;
            }
        }
    }
    if (elo) {
        __syncthreads();
        int il = tid >> 1;
        int hbase = (tid & 1) * 4;
        int grow = rowBase + il;
        if (grow < n) {
            int gg = gid[grow];
            const float* f = sC + il * 132;
#pragma unroll
            for (int hh = 0; hh < 4; hh++) {
                int h = hbase + hh;
                const float* q = Qb + (size_t)gg * HD2 + h * 32;
                float sl = 0.f, sr = 0.f;
#pragma unroll
                for (int c = 0; c < 16; c++) {
                    float fv = f[h * 16 + c];
                    sl = fmaf(fv, q[c], sl);
                    sr = fmaf(fv, q[16 + c], sr);
                }
                elo[grow * HH + h] = sl;
                ero[grow * HH + h] = sr;
            }
        }
    }
}

// ---------------- two-problem GEMM (Qf + end layers) ----------------
template <int AMODE, int STAT>
__global__ void __launch_bounds__(256, 2) k_gemm(
    const float* __restrict__ A1a, const float* __restrict__ A1b,
    const float* __restrict__ W, const float* __restrict__ bias,
    const float* __restrict__ mu0, const float* __restrict__ rstd0,
    const float* __restrict__ mu1, const float* __restrict__ rstd1,
    float* Ca, float* Cb, double* ds0, double* ds1,
    int na, int nb, int yb, int K, int NC) {
    extern __shared__ float smf[];
    __shared__ float sstat[256];
    const uint32_t sb = smem_u32(smf);
    const int tid = threadIdx.x;
    const int lane = tid & 31;
    const int wid = tid >> 5;
    const int warp_m = wid >> 2;
    const int warp_n = wid & 3;

    int by = blockIdx.y;
    const float *A1, *mu, *rstd;
    float* C;
    double* dstat;
    int n;
    if (by < yb) {
        A1 = A1a; C = Ca; dstat = ds0; n = na; mu = mu0; rstd = rstd0;
    } else {
        by -= yb;
        A1 = A1b; C = Cb; dstat = ds1; n = nb; mu = mu1; rstd = rstd1;
    }
    const int rowBase = by * 128;
    const int colBase = blockIdx.x * 128;
    const int g4 = lane >> 2;
    const int t4 = lane & 3;

    if (STAT && tid < 256) sstat[tid] = 0.f;

    stage_issue_r(sb, 0, A1, nullptr, false, W, rowBase, colBase, 0, n, K, NC, tid);
    stage_issue_r(sb, 1, A1, nullptr, false, W, rowBase, colBase, 32, n, K, NC, tid);

    float acc[4][4][4];
#pragma unroll
    for (int mi = 0; mi < 4; mi++)
#pragma unroll
        for (int ni = 0; ni < 4; ni++)
#pragma unroll
            for (int r = 0; r < 4; r++) acc[mi][ni][r] = 0.f;

    const int nk = K >> 5;
    for (int i = 0; i < nk; i++) {
        int p = i & 1;
        if (i + 1 < nk)
            asm volatile("cp.async.wait_group 1;" ::: "memory");
        else
            asm volatile("cp.async.wait_group 0;" ::: "memory");
        __syncthreads();
        if (AMODE == 2) {
            int kg = i * 32 + (tid & 1) * 16;
            float* a = smf + AOFF(p) + (tid >> 1) * 36 + (tid & 1) * 16;
#pragma unroll
            for (int j = 0; j < 16; j++) a[j] = eluf((a[j] - mu[kg + j]) * rstd[kg + j]);
            __syncthreads();
        }
        const float* Af = smf + AOFF(p);
        const float* Wf = smf + WOFF(p);
#pragma unroll
        for (int ks = 0; ks < 4; ks++) {
            int kk = ks * 8;
            uint32_t a[4][4];
#pragma unroll
            for (int mi = 0; mi < 4; mi++) {
                int r = warp_m * 64 + mi * 16 + g4;
                a[mi][0] = f2tf(Af[r * 36 + kk + t4]);
                a[mi][1] = f2tf(Af[(r + 8) * 36 + kk + t4]);
                a[mi][2] = f2tf(Af[r * 36 + kk + t4 + 4]);
                a[mi][3] = f2tf(Af[(r + 8) * 36 + kk + t4 + 4]);
            }
            uint32_t b[4][2];
#pragma unroll
            for (int ni = 0; ni < 4; ni++) {
                int c = warp_n * 32 + ni * 8 + g4;
                b[ni][0] = f2tf(Wf[(kk + t4) * 132 + c]);
                b[ni][1] = f2tf(Wf[(kk + t4 + 4) * 132 + c]);
            }
#pragma unroll
            for (int mi = 0; mi < 4; mi++)
#pragma unroll
                for (int ni = 0; ni < 4; ni++) mma8(acc[mi][ni], a[mi], b[ni]);
        }
        __syncthreads();
        if (i + 2 < nk)
            stage_issue_r(sb, p, A1, nullptr, false, W, rowBase, colBase, (i + 2) * 32, n, K, NC,
                          tid);
    }

    float cs[8], cq[8];
#pragma unroll
    for (int i = 0; i < 8; i++) { cs[i] = 0.f; cq[i] = 0.f; }

#pragma unroll
    for (int mi = 0; mi < 4; mi++) {
        int r0 = rowBase + warp_m * 64 + mi * 16 + g4;
        int r1 = r0 + 8;
#pragma unroll
        for (int ni = 0; ni < 4; ni++) {
            int c = colBase + warp_n * 32 + ni * 8 + t4 * 2;
            float b0 = bias[c], b1 = bias[c + 1];
            if (r0 < n) {
                float v0 = acc[mi][ni][0] + b0, v1 = acc[mi][ni][1] + b1;
                C[(size_t)r0 * NC + c] = v0;
                C[(size_t)r0 * NC + c + 1] = v1;
                if (STAT) {
                    cs[ni * 2] += v0; cq[ni * 2] += v0 * v0;
                    cs[ni * 2 + 1] += v1; cq[ni * 2 + 1] += v1 * v1;
                }
            }
            if (r1 < n) {
                float v2 = acc[mi][ni][2] + b0, v3 = acc[mi][ni][3] + b1;
                C[(size_t)r1 * NC + c] = v2;
                C[(size_t)r1 * NC + c + 1] = v3;
                if (STAT) {
                    cs[ni * 2] += v2; cq[ni * 2] += v2 * v2;
                    cs[ni * 2 + 1] += v3; cq[ni * 2 + 1] += v3 * v3;
                }
            }
        }
    }
    if (STAT) {
#pragma unroll
        for (int i = 0; i < 8; i++) {
            float s = cs[i], q = cq[i];
            s += __shfl_down_sync(0xffffffffu, s, 16);
            q += __shfl_down_sync(0xffffffffu, q, 16);
            s += __shfl_down_sync(0xffffffffu, s, 8);
            q += __shfl_down_sync(0xffffffffu, q, 8);
            s += __shfl_down_sync(0xffffffffu, s, 4);
            q += __shfl_down_sync(0xffffffffu, q, 4);
            if (g4 == 0) {
                int c = warp_n * 32 + (i >> 1) * 8 + t4 * 2 + (i & 1);
                atomicAdd(&sstat[c], s);
                atomicAdd(&sstat[128 + c], q);
            }
        }
        __syncthreads();
        if (tid < 128) {
            atomicAdd(&dstat[colBase + tid], (double)sstat[tid]);
            atomicAdd(&dstat[256 + colBase + tid], (double)sstat[128 + tid]);
        }
    }
}

// ---------------- fills ----------------
__global__ void k_zero0(float* glq, float* gsumq, float* accq, float* accda, float* pe, float* de,
                        int* dga, int* dgb, double* dstat) {
    int i = blockIdx.x * blockDim.x + threadIdx.x;
    if (i < NDA) dga[i] = 0;
    if (i < NQ) dgb[i] = 0;
    if (i < BB * HD) glq[i] = 0.f;
    if (i < BB) gsumq[i] = 0.f;
    if (i < BB * 4) { accq[i] = 0.f; accda[i] = 0.f; }
    if (i < HH) { pe[i] = 0.f; de[i] = 0.f; }
    if (i < 1024) dstat[i] = 0.0;
}

// ---------------- gate kernels ----------------
__global__ void k_gap_pool(const float* __restrict__ M, const int* __restrict__ gid,
                           const float* __restrict__ e, const float* __restrict__ gsum,
                           float* pool, int n) {
    int w = (blockIdx.x * blockDim.x + threadIdx.x) >> 5;
    int lane = threadIdx.x & 31;
    if (w >= n) return;
    int b = gid[w];
    float wt = e[w] / gsum[b];
    const float* row = M + (size_t)w * HD;
#pragma unroll
    for (int j = lane; j < HD; j += 32) atomicAdd(&pool[b * HD + j], wt * row[j]);
}

// batched gate dots; q-side also computes gateq gate (ebuf + gsumq)
__global__ void __launch_bounds__(1024) k_gapdots_b(
    const float* __restrict__ h0a, const float* __restrict__ hla, const int* __restrict__ gia,
    float* acca,
    const float* __restrict__ h0b, const float* __restrict__ hlb, const int* __restrict__ gib,
    float* accb,
    const float* __restrict__ w1, const float* __restrict__ b1, const float* __restrict__ w2,
    const float* __restrict__ b2, const float* __restrict__ qc,
    const float* __restrict__ wq, const float* __restrict__ bq, float* ebuf, float* gsumq,
    int ybreak) {
    __shared__ int sgid[32];
    __shared__ float sv[32][5];
    const float *M1, *M2;
    const int* gid;
    float* acc;
    int nodeBase;
    bool isq = (int)blockIdx.x >= ybreak;
    if (!isq) {
        M1 = h0a; M2 = hla; gid = gia; acc = acca; nodeBase = blockIdx.x * 32;
    } else {
        M1 = h0b; M2 = hlb; gid = gib; acc = accb; nodeBase = (blockIdx.x - ybreak) * 32;
    }
    int wid = threadIdx.x >> 5, lane = threadIdx.x & 31;
    int node = nodeBase + wid;
    {
        float4 a = ((const float4*)(M1 + (size_t)node * HD))[lane];
        float4 bb = ((const float4*)(M2 + (size_t)node * HD))[lane];
        float4 w1v = ((const float4*)w1)[lane];
        float4 w2v = ((const float4*)w2)[lane];
        float4 qv = ((const float4*)qc)[lane];
        float s1 = a.x * w1v.x + a.y * w1v.y + a.z * w1v.z + a.w * w1v.w;
        float q1 = a.x * qv.x + a.y * qv.y + a.z * qv.z + a.w * qv.w;
        float s2 = bb.x * w2v.x + bb.y * w2v.y + bb.z * w2v.z + bb.w * w2v.w;
        float q2 = bb.x * qv.x + bb.y * qv.y + bb.z * qv.z + bb.w * qv.w;
        float s3 = 0.f;
        if (isq) {
            float4 wqv = ((const float4*)wq)[lane];
            s3 = bb.x * wqv.x + bb.y * wqv.y + bb.z * wqv.z + bb.w * wqv.w;
        }
#pragma unroll
        for (int o = 16; o; o >>= 1) {
            s1 += __shfl_down_sync(0xffffffffu, s1, o);
            q1 += __shfl_down_sync(0xffffffffu, q1, o);
            s2 += __shfl_down_sync(0xffffffffu, s2, o);
            q2 += __shfl_down_sync(0xffffffffu, q2, o);
            s3 += __shfl_down_sync(0xffffffffu, s3, o);
        }
        if (lane == 0) {
            float e1 = expf(s1 + b1[0]), e2 = expf(s2 + b2[0]);
            sgid[wid] = gid[node];
            sv[wid][0] = e1; sv[wid][1] = e1 * q1; sv[wid][2] = e2; sv[wid][3] = e2 * q2;
            if (isq) {
                float e3 = expf(s3 + bq[0]);
                ebuf[node] = e3;
                sv[wid][4] = e3;
            }
        }
    }
    __syncthreads();
    int ncomp = isq ? 5 : 4;
    if ((int)threadIdx.x < ncomp) {
        int comp = threadIdx.x;
        int cur = -2;
        float a = 0.f;
        for (int i = 0; i < 32; i++) {
            int g = sgid[i];
            if (g != cur) {
                if (cur >= 0) {
                    if (comp < 4) atomicAdd(&acc[cur * 4 + comp], a);
                    else atomicAdd(&gsumq[cur], a);
                }
                cur = g;
                a = 0.f;
            }
            a += sv[i][comp];
        }
        if (cur >= 0) {
            if (comp < 4) atomicAdd(&acc[cur * 4 + comp], a);
            else atomicAdd(&gsumq[cur], a);
        }
    }
}

__global__ void k_comb2x(const float* __restrict__ accq, float* aabq,
                         const float* __restrict__ accda, float* aabda) {
    int t = threadIdx.x;
    const float* acc = t < BB ? accq : accda;
    float* aab = t < BB ? aabq : aabda;
    int b = t & (BB - 1);
    float d1 = acc[b * 4 + 1] / acc[b * 4 + 0];
    float d2 = acc[b * 4 + 3] / acc[b * 4 + 2];
    float mm = fmaxf(d1, d2);
    float e1 = expf(d1 - mm), e2 = expf(d2 - mm);
    float ss = e1 + e2;
    aab[2 * b] = e1 / ss;
    aab[2 * b + 1] = e2 / ss;
}

// ---------------- CSR build (batched) ----------------
__global__ void k_hist_b(const int* __restrict__ dsta, int* dga, const int* __restrict__ dstb,
                         int* dgb, int Ea, int Eb) {
    int e = blockIdx.x * blockDim.x + threadIdx.x;
    if (e < Ea) {
        atomicAdd(&dga[dsta[e]], 1);
    } else {
        e -= Ea;
        if (e < Eb) atomicAdd(&dgb[dstb[e]], 1);
    }
}
__global__ void k_scan1_b(const int* __restrict__ dga, int* coffa, int* bsuma,
                          const int* __restrict__ dgb, int* coffb, int* bsumb, int na, int nb,
                          int nba) {
    __shared__ int sh[512];
    const int* dg;
    int *outp, *bsum;
    int n, bid;
    if ((int)blockIdx.x < nba) { dg = dga; outp = coffa; bsum = bsuma; n = na; bid = blockIdx.x; }
    else { dg = dgb; outp = coffb; bsum = bsumb; n = nb; bid = blockIdx.x - nba; }
    int base = bid * 512, t = threadIdx.x;
    int v0 = (base + t < n) ? dg[base + t] : 0;
    int v1 = (base + 256 + t < n) ? dg[base + 256 + t] : 0;
    sh[t] = v0; sh[t + 256] = v1;
    __syncthreads();
    for (int off = 1; off < 512; off <<= 1) {
        int i0 = t, i1 = t + 256;
        int n0 = sh[i0] + ((i0 >= off) ? sh[i0 - off] : 0);
        int n1 = sh[i1] + ((i1 >= off) ? sh[i1 - off] : 0);
        __syncthreads();
        sh[i0] = n0; sh[i1] = n1;
        __syncthreads();
    }
    if (base + t < n) outp[base + t] = sh[t] - v0;
    if (base + 256 + t < n) outp[base + 256 + t] = sh[t + 256] - v1;
    if (t == 0) bsum[bid] = sh[511];
}
__global__ void k_scan2_b(int* bsuma, int nba, int* bsumb, int nbb) {
    __shared__ int sh[256];
    int* bsum = blockIdx.x == 0 ? bsuma : bsumb;
    int nb = blockIdx.x == 0 ? nba : nbb;
    int t = threadIdx.x;
    int v = (t < nb) ? bsum[t] : 0;
    sh[t] = v;
    __syncthreads();
    for (int off = 1; off < 256; off <<= 1) {
        int x = sh[t] + ((t >= off) ? sh[t - off] : 0);
        __syncthreads();
        sh[t] = x;
        __syncthreads();
    }
    if (t < nb) bsum[t] = sh[t] - v;
}
__global__ void k_scan3_b(int* coffa, int* cura, const int* __restrict__ bsuma, int* coffb,
                          int* curb, const int* __restrict__ bsumb, int na, int nb) {
    int i = blockIdx.x * blockDim.x + threadIdx.x;
    if (i < na) {
        int v = coffa[i] + bsuma[i >> 9];
        coffa[i] = v;
        cura[i] = v;
    } else {
        i -= na;
        if (i < nb) {
            int v = coffb[i] + bsumb[i >> 9];
            coffb[i] = v;
            curb[i] = v;
        }
    }
}
__global__ void k_scatter_b(const int* __restrict__ srca, const int* __restrict__ dsta, int* cura,
                            int* srcsa, const int* __restrict__ srcb,
                            const int* __restrict__ dstb, int* curb, int* srcsb, int Ea, int Eb) {
    int e = blockIdx.x * blockDim.x + threadIdx.x;
    if (e < Ea) {
        int p = atomicAdd(&cura[dsta[e]], 1);
        srcsa[p] = srca[e];
    } else {
        e -= Ea;
        if (e < Eb) {
            int p = atomicAdd(&curb[dstb[e]], 1);
            srcsb[p] = srcb[e];
        }
    }
}

// ---------------- batched single-pass edge softmax + aggregation (pipelined) ----------------
__global__ void k_node_agg_b(const int* __restrict__ srcsa, const int* __restrict__ coffa,
                             const int* __restrict__ dga, const float* __restrict__ ela,
                             const float* __restrict__ era, const float* __restrict__ fta,
                             float* agga, float* sa, const int* __restrict__ srcsb,
                             const int* __restrict__ coffb, const int* __restrict__ dgb,
                             const float* __restrict__ elb, const float* __restrict__ erb,
                             const float* __restrict__ ftb, float* aggb, float* sb2, int na,
                             int nb) {
    int w = (blockIdx.x * blockDim.x + threadIdx.x) >> 5;
    int lane = threadIdx.x & 31;
    const int *srcs, *coff, *dg;
    const float *el, *er, *ft;
    float *agg, *s;
    if (w < na) {
        srcs = srcsa; coff = coffa; dg = dga; el = ela; er = era; ft = fta; agg = agga; s = sa;
    } else {
        w -= na;
        if (w >= nb) return;
        srcs = srcsb; coff = coffb; dg = dgb; el = elb; er = erb; ft = ftb; agg = aggb; s = sb2;
    }
    int h = lane >> 2;
    int off = coff[w], d = dg[w];
    float erv = er[w * HH + h];
    float wsum = 0.f;
    float4 acc = make_float4(0.f, 0.f, 0.f, 0.f);
    int sn_next = (d > 0) ? __ldg(&srcs[off]) : 0;
#pragma unroll 4
    for (int j = 0; j < d; j++) {
        int sn = sn_next;
        if (j + 1 < d) sn_next = __ldg(&srcs[off + j + 1]);
        float elv = __ldg(&el[sn * HH + h]);
        float4 fv = __ldg((const float4*)(ft + (size_t)sn * HD + lane * 4));
        float v = elv + erv;
        v = v > 0.f ? v : NEG_SLOPE * v;
        float wt = expf(v);
        wsum += wt;
        acc.x = fmaf(wt, fv.x, acc.x);
        acc.y = fmaf(wt, fv.y, acc.y);
        acc.z = fmaf(wt, fv.z, acc.z);
        acc.w = fmaf(wt, fv.w, acc.w);
    }
    float inv = wsum > 0.f ? 1.f / wsum : 0.f;
    acc.x *= inv; acc.y *= inv; acc.z *= inv; acc.w *= inv;
    *(float4*)(agg + (size_t)w * HD + lane * 4) = acc;
    if ((lane & 3) == 0) s[w * HH + h] = wsum;
}

// ---------------- bn finalize (self-zeroing) / apply ----------------
__global__ void k_bnfin2(double* st0, int n0, float* mu0, float* rstd0, double* st1, int n1,
                         float* mu1, float* rstd1, int C) {
    int t = threadIdx.x;
    double* st;
    float *mu, *rstd;
    int n, c;
    if (t < C) { st = st0; mu = mu0; rstd = rstd0; n = n0; c = t; }
    else { st = st1; mu = mu1; rstd = rstd1; n = n1; c = t - C; }
    double m = st[c] / n;
    double v = st[256 + c] / n - m * m;
    if (v < 0.0) v = 0.0;
    mu[c] = (float)m;
    rstd[c] = (float)(1.0 / sqrt(v + 1e-5));
    st[c] = 0.0;
    st[256 + c] = 0.0;
}
__global__ void k_bnelu(const float* __restrict__ Y, const float* __restrict__ mu,
                        const float* __restrict__ rstd, float* outp, long long total, int C) {
    long long i = (long long)blockIdx.x * blockDim.x + threadIdx.x;
    if (i < total) {
        int c = (int)(i % C);
        outp[i] = eluf((Y[i] - mu[c]) * rstd[c]);
    }
}
__global__ void k_final_b(const float* __restrict__ hla, const float* __restrict__ y2a,
                          const float* __restrict__ mu0, const float* __restrict__ rstd0,
                          float* outa, const float* __restrict__ hlb,
                          const float* __restrict__ y2b, const float* __restrict__ mu1,
                          const float* __restrict__ rstd1, float* outb, long long ta,
                          long long tb) {
    long long i = (long long)blockIdx.x * blockDim.x + threadIdx.x;
    const float *hl, *Y, *mu, *rstd;
    float* outp;
    if (i < ta) { hl = hla; Y = y2a; mu = mu0; rstd = rstd0; outp = outa; }
    else {
        i -= ta;
        if (i >= tb) return;
        hl = hlb; Y = y2b; mu = mu1; rstd = rstd1; outp = outb;
    }
    int c = (int)(i & (HD - 1));
    outp[i] = hl[i] + eluf((Y[i] - mu[c]) * rstd[c]);
}

// ---------------- loss ----------------
__global__ void k_pesum_b(const int* __restrict__ peid, int npe, float* peout,
                          const int* __restrict__ deid, int nde, float* deout,
                          const int* __restrict__ src, const int* __restrict__ dst,
                          const float* __restrict__ el, const float* __restrict__ er,
                          const float* __restrict__ s) {
    const int* ids;
    float* out8;
    int nids, bid;
    int half = gridDim.x / 2;
    if ((int)blockIdx.x < half) { ids = peid; out8 = peout; nids = npe; bid = blockIdx.x; }
    else { ids = deid; out8 = deout; nids = nde; bid = blockIdx.x - half; }
    float acc[HH];
#pragma unroll
    for (int h = 0; h < HH; h++) acc[h] = 0.f;
    for (int i = bid * blockDim.x + threadIdx.x; i < nids; i += half * blockDim.x) {
        int e = ids[i];
        int se = src[e] * HH, de = dst[e] * HH;
#pragma unroll
        for (int h = 0; h < HH; h++) {
            float v = el[se + h] + er[de + h];
            v = v > 0.f ? v : NEG_SLOPE * v;
            acc[h] += expf(v) / s[de + h];
        }
    }
#pragma unroll
    for (int h = 0; h < HH; h++)
#pragma unroll
        for (int o = 16; o; o >>= 1) acc[h] += __shfl_down_sync(0xffffffffu, acc[h], o);
    if ((threadIdx.x & 31) == 0)
#pragma unroll
        for (int h = 0; h < HH; h++) atomicAdd(&out8[h], acc[h]);
}
__global__ void k_loss(const float* pe, const float* de, const int* lenp, float* outp) {
    float sum = 0.f;
#pragma unroll
    for (int h = 0; h < HH; h++) sum += pe[h] - de[h];
    outp[0] = -sum / (8.0f * (float)lenp[0]);
}

// ---------------- host ----------------
static inline int cdiv(long long a, long long b) { return (int)((a + b - 1) / b); }

extern "C" void kernel_launch(void* const* d_in, const int* in_sizes, int n_in, void* d_out,
                              int out_size) {
    const float* h_da_last = (const float*)d_in[0];
    const float* h_q_last  = (const float*)d_in[1];
    const float* h_da_0    = (const float*)d_in[2];
    const float* h_q_0     = (const float*)d_in[3];
    const float* W_L       = (const float*)d_in[4];
    const float* b_L       = (const float*)d_in[5];
    const float* gateq_W   = (const float*)d_in[6];
    const float* gateq_b   = (const float*)d_in[7];
    const float* gate1_W   = (const float*)d_in[8];
    const float* gate1_b   = (const float*)d_in[9];
    const float* gate2_W   = (const float*)d_in[10];
    const float* gate2_b   = (const float*)d_in[11];
    const float* Q_comb    = (const float*)d_in[12];
    const float* Qf_W1     = (const float*)d_in[13];
    const float* Qf_b1     = (const float*)d_in[14];
    const float* Qf_W2     = (const float*)d_in[15];
    const float* Qf_b2     = (const float*)d_in[16];
    const float* end_W1    = (const float*)d_in[17];
    const float* end_b1    = (const float*)d_in[18];
    const float* end_W2    = (const float*)d_in[19];
    const float* end_b2    = (const float*)d_in[20];
    const int* src_da = (const int*)d_in[21];
    const int* dst_da = (const int*)d_in[22];
    const int* src_q  = (const int*)d_in[23];
    const int* dst_q  = (const int*)d_in[24];
    const int* gid_da = (const int*)d_in[25];
    const int* gid_q  = (const int*)d_in[26];
    const int* PEid   = (const int*)d_in[27];
    const int* DEid   = (const int*)d_in[28];
    const int* lenp   = (const int*)d_in[29];
    int nPE = in_sizes[27], nDE = in_sizes[28];

    float* outp = (float*)d_out;
    float* out_da = outp;
    float* out_q = outp + (long long)NDA * HD;
    float* out_loss = outp + (long long)NDA * HD + (long long)NQ * HD;

    float *feat, *featq, *ft, *ftq, *agg, *aggq, *y1, *y1q, *y2, *y2q;
    float *el, *er, *ss, *elq, *erq, *sq2, *eb;
    float *glq, *t1, *t2, *Qb, *gsumq, *accq, *accda, *aabq, *aabda, *mu, *rstd, *pe, *de;
    double* dstat;
    int *dg, *coff, *cursor, *srcs, *bsum, *dgq, *coffq, *cursorq, *srcsq, *bsumq;
    cudaGetSymbolAddress((void**)&feat, g_feat);
    cudaGetSymbolAddress((void**)&featq, g_featq);
    cudaGetSymbolAddress((void**)&ft, g_ft);
    cudaGetSymbolAddress((void**)&ftq, g_ftq);
    cudaGetSymbolAddress((void**)&agg, g_agg);
    cudaGetSymbolAddress((void**)&aggq, g_aggq);
    cudaGetSymbolAddress((void**)&y1, g_y1);
    cudaGetSymbolAddress((void**)&y1q, g_y1q);
    cudaGetSymbolAddress((void**)&y2, g_y2);
    cudaGetSymbolAddress((void**)&y2q, g_y2q);
    cudaGetSymbolAddress((void**)&el, g_el);
    cudaGetSymbolAddress((void**)&er, g_er);
    cudaGetSymbolAddress((void**)&ss, g_s);
    cudaGetSymbolAddress((void**)&elq, g_elq);
    cudaGetSymbolAddress((void**)&erq, g_erq);
    cudaGetSymbolAddress((void**)&sq2, g_sq2);
    cudaGetSymbolAddress((void**)&eb, g_eb);
    cudaGetSymbolAddress((void**)&glq, g_glq);
    cudaGetSymbolAddress((void**)&t1, g_t1);
    cudaGetSymbolAddress((void**)&t2, g_t2);
    cudaGetSymbolAddress((void**)&Qb, g_Q);
    cudaGetSymbolAddress((void**)&gsumq, g_gsumq);
    cudaGetSymbolAddress((void**)&accq, g_accq);
    cudaGetSymbolAddress((void**)&accda, g_accda);
    cudaGetSymbolAddress((void**)&aabq, g_aabq);
    cudaGetSymbolAddress((void**)&aabda, g_aabda);
    cudaGetSymbolAddress((void**)&mu, g_mu);
    cudaGetSymbolAddress((void**)&rstd, g_rstd);
    cudaGetSymbolAddress((void**)&pe, g_pe);
    cudaGetSymbolAddress((void**)&de, g_de);
    cudaGetSymbolAddress((void**)&dstat, g_dstat);
    cudaGetSymbolAddress((void**)&dg, g_deg);
    cudaGetSymbolAddress((void**)&coff, g_coff);
    cudaGetSymbolAddress((void**)&cursor, g_cursor);
    cudaGetSymbolAddress((void**)&srcs, g_srcs);
    cudaGetSymbolAddress((void**)&bsum, g_bsum);
    cudaGetSymbolAddress((void**)&dgq, g_degq);
    cudaGetSymbolAddress((void**)&coffq, g_coffq);
    cudaGetSymbolAddress((void**)&cursorq, g_cursorq);
    cudaGetSymbolAddress((void**)&srcsq, g_srcsq);
    cudaGetSymbolAddress((void**)&bsumq, g_bsumq);

    double* dstat1 = dstat + 512;
    float* mu1 = mu + 256;
    float* rstd1 = rstd + 256;

    cudaFuncSetAttribute(k_gemmW, cudaFuncAttributeMaxDynamicSharedMemorySize, SMEM_G1);
    cudaFuncSetAttribute(k_gemm<0, 1>, cudaFuncAttributeMaxDynamicSharedMemorySize, SMEM_G0);
    cudaFuncSetAttribute(k_gemm<2, 1>, cudaFuncAttributeMaxDynamicSharedMemorySize, SMEM_G0);

    const int YDA = cdiv(NDA, 128), YQ = cdiv(NQ, 128);

    // prep
    k_zero0<<<cdiv(NDA, 256), 256>>>(glq, gsumq, accq, accda, pe, de, dg, dgq, dstat);
    k_gapdots_b<<<NDA / 32 + NQ / 32, 1024>>>(h_da_0, h_da_last, gid_da, accda, h_q_0, h_q_last,
                                              gid_q, accq, gate1_W, gate1_b, gate2_W, gate2_b,
                                              Q_comb, gateq_W, gateq_b, eb, gsumq, NDA / 32);
    k_gap_pool<<<cdiv((long long)NQ * 32, 256), 256>>>(h_q_last, gid_q, eb, gsumq, glq, NQ);
    k_hist_b<<<cdiv(EDA + EQ, 256), 256>>>(dst_da, dg, dst_q, dgq, EDA, EQ);
    // Qf FNN -> Qb
    k_gemm<0, 1><<<dim3(2, 1), 256, SMEM_G0>>>(glq, nullptr, Qf_W1, Qf_b1, nullptr, nullptr,
                                               nullptr, nullptr, t1, nullptr, dstat, nullptr, BB,
                                               0, 1, 128, 256);
    k_bnfin2<<<1, 512>>>(dstat, BB, mu, rstd, dstat1, 1, mu1, rstd1, 256);
    k_gemm<2, 1><<<dim3(2, 1), 256, SMEM_G0>>>(t1, nullptr, Qf_W2, Qf_b2, mu, rstd, nullptr,
                                               nullptr, t2, nullptr, dstat, nullptr, BB, 0, 1,
                                               256, 256);
    k_bnfin2<<<1, 512>>>(dstat, BB, mu, rstd, dstat1, 1, mu1, rstd1, 256);
    k_bnelu<<<cdiv(BB * 256, 256), 256>>>(t2, mu, rstd, Qb, (long long)BB * 256, 256);
    k_comb2x<<<1, 128>>>(accq, aabq, accda, aabda);
    // CSR
    int NBA = cdiv(NDA, 512), NBB = cdiv(NQ, 512);
    k_scan1_b<<<NBA + NBB, 256>>>(dg, coff, bsum, dgq, coffq, bsumq, NDA, NQ, NBA);
    k_scan2_b<<<2, 256>>>(bsum, NBA, bsumq, NBB);
    k_scan3_b<<<cdiv(NDA + NQ, 256), 256>>>(coff, cursor, bsum, coffq, cursorq, bsumq, NDA, NQ);
    k_scatter_b<<<cdiv(EDA + EQ, 256), 256>>>(src_da, dst_da, cursor, srcs, src_q, dst_q, cursorq,
                                              srcsq, EDA, EQ);

    // mega W_L GEMM
    k_gemmW<<<dim3(1, 2 * (YDA + YQ)), 256, SMEM_G1>>>(
        h_da_last, h_q_last, h_da_0, h_q_0, aabda, aabq, gid_da, gid_q, W_L, b_L, Qb, feat, featq,
        ft, ftq, el, er, elq, erq, YDA, YQ);

    // batched node agg
    k_node_agg_b<<<cdiv((long long)(NDA + NQ) * 32, 256), 256>>>(
        srcs, coff, dg, el, er, ft, agg, ss, srcsq, coffq, dgq, elq, erq, ftq, aggq, sq2, NDA, NQ);
    // end FNN
    k_gemm<0, 1><<<dim3(2, YDA + YQ), 256, SMEM_G0>>>(agg, aggq, end_W1, end_b1, nullptr, nullptr,
                                                      nullptr, nullptr, y1, y1q, dstat, dstat1,
                                                      NDA, NQ, YDA, 128, 256);
    k_bnfin2<<<1, 512>>>(dstat, NDA, mu, rstd, dstat1, NQ, mu1, rstd1, 256);
    k_gemm<2, 1><<<dim3(1, YDA + YQ), 256, SMEM_G0>>>(y1, y1q, end_W2, end_b2, mu, rstd, mu1,
                                                      rstd1, y2, y2q, dstat, dstat1, NDA, NQ, YDA,
                                                      256, 128);
    k_bnfin2<<<1, 256>>>(dstat, NDA, mu, rstd, dstat1, NQ, mu1, rstd1, 128);
    k_final_b<<<cdiv((long long)(NDA + NQ) * HD, 256), 256>>>(
        h_da_last, y2, mu, rstd, out_da, h_q_last, y2q, mu1, rstd1, out_q, (long long)NDA * HD,
        (long long)NQ * HD);

    // loss
    k_pesum_b<<<128, 256>>>(PEid, nPE, pe, DEid, nDE, de, src_da, dst_da, el, er, ss);
    k_loss<<<1, 1>>>(pe, de, lenp, out_loss);
}